// round 7
// baseline (speedup 1.0000x reference)
#include <cuda_runtime.h>
#include <cuda_bf16.h>
#include <math.h>
#include <stdint.h>

#define DMODEL 2048
#define NHEADS 16
#define DHEAD  128
#define SEQ    2048
#define BATCH  2
#define BHN    (BATCH*NHEADS)   // 32
#define MROWS  (BATCH*SEQ)      // 4096

// log2(e) / sqrt(128)
#define QSCALE (1.4426950408889634f * 0.08838834764831845f)

// ---- GEMM: CTA 128x256, KBLK 64, 8 warps (64x64), 2-stage cp.async ----
#define SROWB  144                    // bytes per smem row (64 bf16 + 8 pad)
#define ATILE  (128 * SROWB)          // 18432
#define BTILE  (256 * SROWB)          // 36864
#define S_AH   0
#define S_AL   (ATILE)
#define S_BH   (2*ATILE)
#define S_BL   (2*ATILE + BTILE)
#define GSTAGE (2*ATILE + 2*BTILE)    // 110592
#define GEMM_SMEM (2*GSTAGE)          // 221184

// ---- HMMA flash config: 128 q x 128 kv, stride 272 B ----
#define FS   272
#define FT   (128 * FS)
#define FQH  0
#define FQL  (FT)
#define FKH  (2*FT)
#define FKL  (3*FT)
#define FVH  (4*FT)
#define FVL  (5*FT)
#define FLASH_SMEM (6*FT)          // 208896 B

// ---------------- scratch (device globals; allocation-free) ----------------
__device__ float  g_q[(size_t)BHN * SEQ * DHEAD];
__device__ float  g_k[(size_t)BHN * SEQ * DHEAD];
__device__ float2 g_rope[SEQ * 64];

__device__ __nv_bfloat16 g_ah[(size_t)MROWS * DMODEL];
__device__ __nv_bfloat16 g_al[(size_t)MROWS * DMODEL];
__device__ __nv_bfloat16 g_wqh[(size_t)DMODEL * DMODEL];
__device__ __nv_bfloat16 g_wql[(size_t)DMODEL * DMODEL];
__device__ __nv_bfloat16 g_wkh[(size_t)DMODEL * DMODEL];
__device__ __nv_bfloat16 g_wkl[(size_t)DMODEL * DMODEL];
__device__ __nv_bfloat16 g_wvh[(size_t)DMODEL * DMODEL];
__device__ __nv_bfloat16 g_wvl[(size_t)DMODEL * DMODEL];
__device__ __nv_bfloat16 g_woh[(size_t)DMODEL * DMODEL];
__device__ __nv_bfloat16 g_wol[(size_t)DMODEL * DMODEL];

__device__ __nv_bfloat16 g_qh[(size_t)BHN * SEQ * DHEAD];
__device__ __nv_bfloat16 g_ql[(size_t)BHN * SEQ * DHEAD];
__device__ __nv_bfloat16 g_kh[(size_t)BHN * SEQ * DHEAD];
__device__ __nv_bfloat16 g_kl[(size_t)BHN * SEQ * DHEAD];
__device__ __nv_bfloat16 g_vh[(size_t)BHN * SEQ * DHEAD];
__device__ __nv_bfloat16 g_vl[(size_t)BHN * SEQ * DHEAD];

// ---------------- helpers ----------------
__device__ __forceinline__ void ldsm4(uint32_t* r, uint32_t addr) {
    asm volatile("ldmatrix.sync.aligned.m8n8.x4.shared.b16 {%0,%1,%2,%3}, [%4];"
                 : "=r"(r[0]), "=r"(r[1]), "=r"(r[2]), "=r"(r[3]) : "r"(addr));
}
__device__ __forceinline__ void ldsm4t(uint32_t* r, uint32_t addr) {
    asm volatile("ldmatrix.sync.aligned.m8n8.x4.trans.shared.b16 {%0,%1,%2,%3}, [%4];"
                 : "=r"(r[0]), "=r"(r[1]), "=r"(r[2]), "=r"(r[3]) : "r"(addr));
}
__device__ __forceinline__ void mma16816(float* d, const uint32_t* a,
                                         uint32_t b0, uint32_t b1) {
    asm volatile(
        "mma.sync.aligned.m16n8k16.row.col.f32.bf16.bf16.f32 "
        "{%0,%1,%2,%3}, {%4,%5,%6,%7}, {%8,%9}, {%0,%1,%2,%3};"
        : "+f"(d[0]), "+f"(d[1]), "+f"(d[2]), "+f"(d[3])
        : "r"(a[0]), "r"(a[1]), "r"(a[2]), "r"(a[3]), "r"(b0), "r"(b1));
}
__device__ __forceinline__ float ex2(float x) {
    float y; asm("ex2.approx.f32 %0, %1;" : "=f"(y) : "f"(x)); return y;
}
__device__ __forceinline__ uint32_t packbf(float lo, float hi) {
    uint32_t r; asm("cvt.rn.bf16x2.f32 %0, %1, %2;" : "=r"(r) : "f"(hi), "f"(lo));
    return r;
}
__device__ __forceinline__ void cpasync16(uint32_t s, const void* g) {
    asm volatile("cp.async.cg.shared.global [%0], [%1], 16;" :: "r"(s), "l"(g));
}

// ---------------------------------------------------------------------------
// RoPE table (fp32 angle, fp64 sin/cos)
// ---------------------------------------------------------------------------
__global__ void rope_table_kernel() {
    int p = blockIdx.x;
    int i = threadIdx.x;  // 0..63
    float freq = (float)pow(10000.0, (double)i / 64.0);
    float ang  = (float)p / freq;
    double s, c;
    sincos((double)ang, &s, &c);
    g_rope[p * 64 + i] = make_float2((float)s, (float)c);
}

// ---------------------------------------------------------------------------
// Rope + bf16 hi/lo split for q (QSCALE folded) and k.
// ---------------------------------------------------------------------------
__global__ void rope_split_kernel() {
    int gid = blockIdx.x * 256 + threadIdx.x;
    int i    = gid & 63;
    int rest = gid >> 6;
    int p    = rest & 2047;
    int bh   = rest >> 11;
    float2 sc = g_rope[p * 64 + i];
    size_t base = ((size_t)bh * SEQ + p) * DHEAD;

    float x0 = g_q[base + i], x1 = g_q[base + 64 + i];
    float q0 = (x0 * sc.y - x1 * sc.x) * QSCALE;
    float q1 = (x1 * sc.y + x0 * sc.x) * QSCALE;
    float y0 = g_k[base + i], y1 = g_k[base + 64 + i];
    float k0 = y0 * sc.y - y1 * sc.x;
    float k1 = y1 * sc.y + y0 * sc.x;

    __nv_bfloat16 h;
    h = __float2bfloat16(q0); g_qh[base + i]      = h; g_ql[base + i]      = __float2bfloat16(q0 - __bfloat162float(h));
    h = __float2bfloat16(q1); g_qh[base + 64 + i] = h; g_ql[base + 64 + i] = __float2bfloat16(q1 - __bfloat162float(h));
    h = __float2bfloat16(k0); g_kh[base + i]      = h; g_kl[base + i]      = __float2bfloat16(k0 - __bfloat162float(h));
    h = __float2bfloat16(k1); g_kh[base + 64 + i] = h; g_kl[base + 64 + i] = __float2bfloat16(k1 - __bfloat162float(h));
}

// ---------------------------------------------------------------------------
// fp32 -> (bf16 hi, bf16 lo) split, elementwise.
// ---------------------------------------------------------------------------
__global__ void split_kernel(const float* __restrict__ x,
                             __nv_bfloat16* __restrict__ hi,
                             __nv_bfloat16* __restrict__ lo) {
    size_t i = ((size_t)blockIdx.x * 256 + threadIdx.x) * 4;
    float4 v = *(const float4*)(x + i);
    float a[4] = {v.x, v.y, v.z, v.w};
    uint32_t ph[2], pl[2];
#pragma unroll
    for (int j = 0; j < 2; ++j) {
        __nv_bfloat16 h0 = __float2bfloat16(a[2*j]);
        __nv_bfloat16 h1 = __float2bfloat16(a[2*j+1]);
        __nv_bfloat16 l0 = __float2bfloat16(a[2*j]   - __bfloat162float(h0));
        __nv_bfloat16 l1 = __float2bfloat16(a[2*j+1] - __bfloat162float(h1));
        ph[j] = (uint32_t)__bfloat16_as_ushort(h0) | ((uint32_t)__bfloat16_as_ushort(h1) << 16);
        pl[j] = (uint32_t)__bfloat16_as_ushort(l0) | ((uint32_t)__bfloat16_as_ushort(l1) << 16);
    }
    *(uint2*)((char*)hi + i * 2) = make_uint2(ph[0], ph[1]);
    *(uint2*)((char*)lo + i * 2) = make_uint2(pl[0], pl[1]);
}

// ---------------------------------------------------------------------------
// Transpose + split: src [H][R][C] fp32 -> dst[h*C + c][r] bf16 (hi, lo).
// ---------------------------------------------------------------------------
__global__ void transpose_split_kernel(const float* __restrict__ src,
                                       __nv_bfloat16* __restrict__ hi,
                                       __nv_bfloat16* __restrict__ lo,
                                       int R, int C) {
    __shared__ float t[32][33];
    int h  = blockIdx.z;
    int r0 = blockIdx.y << 5, c0 = blockIdx.x << 5;
    int tx = threadIdx.x, ty = threadIdx.y;  // 32 x 8
    const float* s = src + (size_t)h * R * C;
#pragma unroll
    for (int j = 0; j < 4; ++j)
        t[ty + 8 * j][tx] = s[(size_t)(r0 + ty + 8 * j) * C + c0 + tx];
    __syncthreads();
#pragma unroll
    for (int j = 0; j < 4; ++j) {
        int c = c0 + ty + 8 * j;
        float v = t[tx][ty + 8 * j];
        __nv_bfloat16 vh = __float2bfloat16(v);
        __nv_bfloat16 vl = __float2bfloat16(v - __bfloat162float(vh));
        size_t o = (size_t)(h * C + c) * R + r0 + tx;
        hi[o] = vh;
        lo[o] = vl;
    }
}

// issue one k-block's cp.async loads into stage `buf`
#define GEMM_ISSUE(it, buf) do {                                               \
    const int _k0 = (it) * 64;                                                 \
    const uint32_t _sd = sb + (uint32_t)(buf) * GSTAGE;                        \
    _Pragma("unroll")                                                          \
    for (int _i = 0; _i < 4; ++_i) {                                           \
        int _slot = tid + _i * 256;                                            \
        int _r = _slot >> 3, _c8 = (_slot & 7) * 8;                            \
        size_t _g = (size_t)(row0 + _r) * DMODEL + _k0 + _c8;                  \
        uint32_t _so = _sd + (uint32_t)(_r * SROWB + _c8 * 2);                 \
        cpasync16(_so + S_AH, Ah + _g);                                        \
        cpasync16(_so + S_AL, Al + _g);                                        \
    }                                                                          \
    _Pragma("unroll")                                                          \
    for (int _i = 0; _i < 8; ++_i) {                                           \
        int _slot = tid + _i * 256;                                            \
        int _r = _slot >> 3, _c8 = (_slot & 7) * 8;                            \
        size_t _g = (size_t)(n0 + _r) * DMODEL + _k0 + _c8;                    \
        uint32_t _so = _sd + (uint32_t)(_r * SROWB + _c8 * 2);                 \
        cpasync16(_so + S_BH, Bh + _g);                                        \
        cpasync16(_so + S_BL, Bl + _g);                                        \
    }                                                                          \
    asm volatile("cp.async.commit_group;" ::: "memory");                       \
} while (0)

// ---------------------------------------------------------------------------
// Pipelined HMMA split GEMM: out = A * B^T + bias.
// CTA 128x256, 8 warps (64x64), KBLK 64, 2-stage cp.async, 1 CTA/SM.
// mode 0: fp32 out -> [b][h][p][e]; mode 1: fp32 row-major;
// mode 2: bf16 hi/lo split -> outh/outl at [b][h][p][e] (V path).
// ---------------------------------------------------------------------------
__global__ __launch_bounds__(256, 1) void gemm_hmma(
    const __nv_bfloat16* __restrict__ Ah,
    const __nv_bfloat16* __restrict__ Al,
    const __nv_bfloat16* __restrict__ Bh,
    const __nv_bfloat16* __restrict__ Bl,
    const float* __restrict__ bias,
    float* __restrict__ out,
    __nv_bfloat16* __restrict__ outh,
    __nv_bfloat16* __restrict__ outl,
    int mode)
{
    extern __shared__ char sm[];
    const uint32_t sb = (uint32_t)__cvta_generic_to_shared(sm);

    const int tid  = threadIdx.x;
    const int wid  = tid >> 5;
    const int lane = tid & 31;
    const int row0 = blockIdx.y * 128;
    const int n0   = blockIdx.x * 256;
    const int m_w  = (wid & 1) * 64;
    const int n_w  = (wid >> 1) * 64;   // 0,64,128,192

    const uint32_t aOff = (uint32_t)(m_w + (lane & 15)) * SROWB + ((lane >> 4) << 4);
    const uint32_t bOff = (uint32_t)(n_w + ((lane >> 4) << 3) + (lane & 7)) * SROWB +
                          (uint32_t)((lane & 8) << 1);

    float acc[4][8][4];
#pragma unroll
    for (int i = 0; i < 4; ++i)
#pragma unroll
        for (int j = 0; j < 8; ++j)
#pragma unroll
            for (int r = 0; r < 4; ++r) acc[i][j][r] = 0.0f;

    GEMM_ISSUE(0, 0);

    for (int it = 0; it < DMODEL / 64; ++it) {
        if (it + 1 < DMODEL / 64) {
            GEMM_ISSUE(it + 1, (it + 1) & 1);
            asm volatile("cp.async.wait_group 1;" ::: "memory");
        } else {
            asm volatile("cp.async.wait_group 0;" ::: "memory");
        }
        __syncthreads();

        const uint32_t st = sb + (uint32_t)(it & 1) * GSTAGE;
        const uint32_t aHi = st + S_AH + aOff;
        const uint32_t aLo = st + S_AL + aOff;
        const uint32_t bHi = st + S_BH + bOff;
        const uint32_t bLo = st + S_BL + bOff;

#pragma unroll
        for (int kk = 0; kk < 4; ++kk) {
            uint32_t Af[4][4], Bf[4][4];
            // pass 1: Ah * Bh
#pragma unroll
            for (int mi = 0; mi < 4; ++mi)
                ldsm4(Af[mi], aHi + mi * (16 * SROWB) + kk * 32);
#pragma unroll
            for (int ni = 0; ni < 4; ++ni)
                ldsm4(Bf[ni], bHi + ni * (16 * SROWB) + kk * 32);
#pragma unroll
            for (int mi = 0; mi < 4; ++mi)
#pragma unroll
                for (int j = 0; j < 8; ++j)
                    mma16816(acc[mi][j], Af[mi], Bf[j >> 1][(j & 1) * 2],
                             Bf[j >> 1][(j & 1) * 2 + 1]);
            // pass 2: Al * Bh (reuse Bf)
            {
                uint32_t Al4[4];
#pragma unroll
                for (int mi = 0; mi < 4; ++mi) {
                    ldsm4(Al4, aLo + mi * (16 * SROWB) + kk * 32);
#pragma unroll
                    for (int j = 0; j < 8; ++j)
                        mma16816(acc[mi][j], Al4, Bf[j >> 1][(j & 1) * 2],
                                 Bf[j >> 1][(j & 1) * 2 + 1]);
                }
            }
            // pass 3: Ah * Bl (reuse Af)
#pragma unroll
            for (int ni = 0; ni < 4; ++ni)
                ldsm4(Bf[ni], bLo + ni * (16 * SROWB) + kk * 32);
#pragma unroll
            for (int mi = 0; mi < 4; ++mi)
#pragma unroll
                for (int j = 0; j < 8; ++j)
                    mma16816(acc[mi][j], Af[mi], Bf[j >> 1][(j & 1) * 2],
                             Bf[j >> 1][(j & 1) * 2 + 1]);
        }
        __syncthreads();
    }

    // Epilogue
    const int g = lane >> 2, t4 = lane & 3;
#pragma unroll
    for (int mi = 0; mi < 4; ++mi) {
        int m = row0 + m_w + mi * 16 + g;
#pragma unroll
        for (int j = 0; j < 8; ++j) {
            int col = n0 + n_w + j * 8 + t4 * 2;
            float b0 = bias[col], b1 = bias[col + 1];
            float2 v0 = make_float2(acc[mi][j][0] + b0, acc[mi][j][1] + b1);
            float2 v1 = make_float2(acc[mi][j][2] + b0, acc[mi][j][3] + b1);
            if (mode == 1) {
                *(float2*)(out + (size_t)m * DMODEL + col)       = v0;
                *(float2*)(out + (size_t)(m + 8) * DMODEL + col) = v1;
            } else {
                int h = col >> 7, e = col & 127;
                int b  = m >> 11, p = m & 2047;
                size_t base = (((size_t)(b * NHEADS + h) * SEQ) << 7) + e;
                size_t i0 = base + ((size_t)p << 7);
                size_t i1 = base + ((size_t)(p + 8) << 7);
                if (mode == 0) {
                    *(float2*)(out + i0) = v0;
                    *(float2*)(out + i1) = v1;
                } else {  // mode 2: bf16 hi/lo split (V path)
                    uint32_t h0 = packbf(v0.x, v0.y);
                    uint32_t l0 = packbf(v0.x - __uint_as_float(h0 << 16),
                                         v0.y - __uint_as_float(h0 & 0xffff0000u));
                    uint32_t h1 = packbf(v1.x, v1.y);
                    uint32_t l1 = packbf(v1.x - __uint_as_float(h1 << 16),
                                         v1.y - __uint_as_float(h1 & 0xffff0000u));
                    *(uint32_t*)(outh + i0) = h0;
                    *(uint32_t*)(outl + i0) = l0;
                    *(uint32_t*)(outh + i1) = h1;
                    *(uint32_t*)(outl + i1) = l1;
                }
            }
        }
    }
}

// ---------------------------------------------------------------------------
// HMMA causal flash attention. CTA = 128 q x 128 kv, 8 warps x 16 rows.
// Epilogue writes z directly as bf16 hi/lo into g_ah/g_al (O-proj input).
// ---------------------------------------------------------------------------
__global__ __launch_bounds__(256, 1) void flash_hmma() {
    extern __shared__ char sm[];
    const uint32_t sb = (uint32_t)__cvta_generic_to_shared(sm);

    const int tid  = threadIdx.x;
    const int wid  = tid >> 5;
    const int lane = tid & 31;
    const int bh   = blockIdx.y;
    const int qt   = gridDim.x - 1 - blockIdx.x;   // heavy tiles first
    const int q0   = qt * 128;

    const __nv_bfloat16* qh = g_qh + (size_t)bh * SEQ * DHEAD;
    const __nv_bfloat16* ql = g_ql + (size_t)bh * SEQ * DHEAD;
    const __nv_bfloat16* kh = g_kh + (size_t)bh * SEQ * DHEAD;
    const __nv_bfloat16* kl = g_kl + (size_t)bh * SEQ * DHEAD;
    const __nv_bfloat16* vh = g_vh + (size_t)bh * SEQ * DHEAD;
    const __nv_bfloat16* vl = g_vl + (size_t)bh * SEQ * DHEAD;

#pragma unroll
    for (int i = 0; i < 8; ++i) {
        int f = tid + i * 256;
        int r = f >> 4, c8 = (f & 15) * 8;
        uint32_t off = (uint32_t)(r * FS + c8 * 2);
        size_t g = (size_t)(q0 + r) * DHEAD + c8;
        *(uint4*)(sm + FQH + off) = *(const uint4*)(qh + g);
        *(uint4*)(sm + FQL + off) = *(const uint4*)(ql + g);
    }

    const uint32_t aOff = (uint32_t)(wid * 16 + (lane & 15)) * FS + ((lane >> 4) << 4);
    const uint32_t aQh = sb + FQH + aOff;
    const uint32_t aQl = sb + FQL + aOff;
    const uint32_t bOff = (uint32_t)(((lane >> 4) << 3) + (lane & 7)) * FS +
                          (uint32_t)((lane & 8) << 1);
    const uint32_t bKh = sb + FKH + bOff;
    const uint32_t bKl = sb + FKL + bOff;
    const uint32_t vOff = (uint32_t)(lane & 15) * FS + ((lane >> 4) << 4);
    const uint32_t bVh = sb + FVH + vOff;
    const uint32_t bVl = sb + FVL + vOff;

    float o[16][4];
#pragma unroll
    for (int j = 0; j < 16; ++j)
#pragma unroll
        for (int r = 0; r < 4; ++r) o[j][r] = 0.0f;
    float m1 = -1e30f, m2 = -1e30f, l1 = 0.0f, l2 = 0.0f;

    for (int t = 0; t <= qt; ++t) {
        const int k0 = t * 128;
        __syncthreads();
#pragma unroll
        for (int i = 0; i < 8; ++i) {
            int f = tid + i * 256;
            int r = f >> 4, c8 = (f & 15) * 8;
            uint32_t off = (uint32_t)(r * FS + c8 * 2);
            size_t g = (size_t)(k0 + r) * DHEAD + c8;
            *(uint4*)(sm + FKH + off) = *(const uint4*)(kh + g);
            *(uint4*)(sm + FKL + off) = *(const uint4*)(kl + g);
            *(uint4*)(sm + FVH + off) = *(const uint4*)(vh + g);
            *(uint4*)(sm + FVL + off) = *(const uint4*)(vl + g);
        }
        __syncthreads();

        float s[16][4];
#pragma unroll
        for (int j = 0; j < 16; ++j)
#pragma unroll
            for (int r = 0; r < 4; ++r) s[j][r] = 0.0f;

#pragma unroll
        for (int kk = 0; kk < 8; ++kk) {
            uint32_t qa[4], qb[4], kb[4];
            ldsm4(qa, aQh + kk * 32);
            ldsm4(qb, aQl + kk * 32);
#pragma unroll
            for (int nn = 0; nn < 8; ++nn) {
                ldsm4(kb, bKh + nn * (16 * FS) + kk * 32);
                mma16816(s[2*nn],   qa, kb[0], kb[1]);
                mma16816(s[2*nn+1], qa, kb[2], kb[3]);
                mma16816(s[2*nn],   qb, kb[0], kb[1]);
                mma16816(s[2*nn+1], qb, kb[2], kb[3]);
                ldsm4(kb, bKl + nn * (16 * FS) + kk * 32);
                mma16816(s[2*nn],   qa, kb[0], kb[1]);
                mma16816(s[2*nn+1], qa, kb[2], kb[3]);
            }
        }

        const int r1 = q0 + wid * 16 + (lane >> 2);
        const int r2 = r1 + 8;
        if (t == qt) {
            const int c0 = k0 + (lane & 3) * 2;
#pragma unroll
            for (int j = 0; j < 16; ++j) {
                int col = c0 + j * 8;
                if (col     > r1) s[j][0] = -1e30f;
                if (col + 1 > r1) s[j][1] = -1e30f;
                if (col     > r2) s[j][2] = -1e30f;
                if (col + 1 > r2) s[j][3] = -1e30f;
            }
        }

        float mx1 = -1e30f, mx2 = -1e30f;
#pragma unroll
        for (int j = 0; j < 16; ++j) {
            mx1 = fmaxf(mx1, fmaxf(s[j][0], s[j][1]));
            mx2 = fmaxf(mx2, fmaxf(s[j][2], s[j][3]));
        }
        mx1 = fmaxf(mx1, __shfl_xor_sync(0xffffffffu, mx1, 1));
        mx1 = fmaxf(mx1, __shfl_xor_sync(0xffffffffu, mx1, 2));
        mx2 = fmaxf(mx2, __shfl_xor_sync(0xffffffffu, mx2, 1));
        mx2 = fmaxf(mx2, __shfl_xor_sync(0xffffffffu, mx2, 2));
        float mn1 = fmaxf(m1, mx1), mn2 = fmaxf(m2, mx2);
        float sc1 = ex2(m1 - mn1), sc2 = ex2(m2 - mn2);
        float rs1 = 0.0f, rs2 = 0.0f;
#pragma unroll
        for (int j = 0; j < 16; ++j) {
            s[j][0] = ex2(s[j][0] - mn1);
            s[j][1] = ex2(s[j][1] - mn1);
            s[j][2] = ex2(s[j][2] - mn2);
            s[j][3] = ex2(s[j][3] - mn2);
            rs1 += s[j][0] + s[j][1];
            rs2 += s[j][2] + s[j][3];
        }
        rs1 += __shfl_xor_sync(0xffffffffu, rs1, 1);
        rs1 += __shfl_xor_sync(0xffffffffu, rs1, 2);
        rs2 += __shfl_xor_sync(0xffffffffu, rs2, 1);
        rs2 += __shfl_xor_sync(0xffffffffu, rs2, 2);
        l1 = l1 * sc1 + rs1;  m1 = mn1;
        l2 = l2 * sc2 + rs2;  m2 = mn2;
#pragma unroll
        for (int j = 0; j < 16; ++j) {
            o[j][0] *= sc1; o[j][1] *= sc1;
            o[j][2] *= sc2; o[j][3] *= sc2;
        }

#pragma unroll
        for (int kk = 0; kk < 8; ++kk) {
            uint32_t ph[4], pl[4], vb[4];
#pragma unroll
            for (int hv = 0; hv < 2; ++hv) {
                const float* sp = s[2*kk + hv];
                uint32_t p0 = packbf(sp[0], sp[1]);
                uint32_t p1 = packbf(sp[2], sp[3]);
                ph[hv*2]   = p0;
                ph[hv*2+1] = p1;
                pl[hv*2]   = packbf(sp[0] - __uint_as_float(p0 << 16),
                                    sp[1] - __uint_as_float(p0 & 0xffff0000u));
                pl[hv*2+1] = packbf(sp[2] - __uint_as_float(p1 << 16),
                                    sp[3] - __uint_as_float(p1 & 0xffff0000u));
            }
            uint32_t pha[4] = {ph[0], ph[1], ph[2], ph[3]};
            uint32_t pla[4] = {pl[0], pl[1], pl[2], pl[3]};
#pragma unroll
            for (int nn = 0; nn < 8; ++nn) {
                ldsm4t(vb, bVh + kk * (16 * FS) + nn * 32);
                mma16816(o[2*nn],   pha, vb[0], vb[1]);
                mma16816(o[2*nn+1], pha, vb[2], vb[3]);
                mma16816(o[2*nn],   pla, vb[0], vb[1]);
                mma16816(o[2*nn+1], pla, vb[2], vb[3]);
                ldsm4t(vb, bVl + kk * (16 * FS) + nn * 32);
                mma16816(o[2*nn],   pha, vb[0], vb[1]);
                mma16816(o[2*nn+1], pha, vb[2], vb[3]);
            }
        }
    }

    // Epilogue: normalize + bf16 hi/lo split straight into g_ah/g_al.
    const int b = bh >> 4, h = bh & 15;
    const int r1 = q0 + wid * 16 + (lane >> 2);
    const float inv1 = 1.0f / l1, inv2 = 1.0f / l2;
    size_t base1 = (size_t)(b * SEQ + r1) * DMODEL + h * DHEAD + (lane & 3) * 2;
    size_t base2 = base1 + (size_t)8 * DMODEL;
#pragma unroll
    for (int j = 0; j < 16; ++j) {
        float a0 = o[j][0] * inv1, a1 = o[j][1] * inv1;
        uint32_t hh = packbf(a0, a1);
        uint32_t ll = packbf(a0 - __uint_as_float(hh << 16),
                             a1 - __uint_as_float(hh & 0xffff0000u));
        *(uint32_t*)&g_ah[base1 + j * 8] = hh;
        *(uint32_t*)&g_al[base1 + j * 8] = ll;
        float a2 = o[j][2] * inv2, a3 = o[j][3] * inv2;
        uint32_t hh2 = packbf(a2, a3);
        uint32_t ll2 = packbf(a2 - __uint_as_float(hh2 << 16),
                              a3 - __uint_as_float(hh2 & 0xffff0000u));
        *(uint32_t*)&g_ah[base2 + j * 8] = hh2;
        *(uint32_t*)&g_al[base2 + j * 8] = ll2;
    }
}

// ---------------------------------------------------------------------------
extern "C" void kernel_launch(void* const* d_in, const int* in_sizes, int n_in,
                              void* d_out, int out_size) {
    (void)in_sizes; (void)n_in; (void)out_size;
    const float* qin = (const float*)d_in[0];
    const float* kin = (const float*)d_in[1];
    const float* vin = (const float*)d_in[2];
    const float* WQ  = (const float*)d_in[3];
    const float* WK  = (const float*)d_in[4];
    const float* WV  = (const float*)d_in[5];
    const float* WO  = (const float*)d_in[6];
    const float* bQ  = (const float*)d_in[7];
    const float* bK  = (const float*)d_in[8];
    const float* bV  = (const float*)d_in[9];
    const float* bO  = (const float*)d_in[10];
    float* out = (float*)d_out;

    float *pq, *pk;
    __nv_bfloat16 *ah, *al, *wqh, *wql, *wkh, *wkl, *wvh, *wvl, *woh, *wol, *vh, *vl;
    cudaGetSymbolAddress((void**)&pq, g_q);
    cudaGetSymbolAddress((void**)&pk, g_k);
    cudaGetSymbolAddress((void**)&ah, g_ah);
    cudaGetSymbolAddress((void**)&al, g_al);
    cudaGetSymbolAddress((void**)&wqh, g_wqh);
    cudaGetSymbolAddress((void**)&wql, g_wql);
    cudaGetSymbolAddress((void**)&wkh, g_wkh);
    cudaGetSymbolAddress((void**)&wkl, g_wkl);
    cudaGetSymbolAddress((void**)&wvh, g_wvh);
    cudaGetSymbolAddress((void**)&wvl, g_wvl);
    cudaGetSymbolAddress((void**)&woh, g_woh);
    cudaGetSymbolAddress((void**)&wol, g_wol);
    cudaGetSymbolAddress((void**)&vh, g_vh);
    cudaGetSymbolAddress((void**)&vl, g_vl);

    cudaFuncSetAttribute((const void*)gemm_hmma,
                         cudaFuncAttributeMaxDynamicSharedMemorySize, GEMM_SMEM);
    cudaFuncSetAttribute((const void*)flash_hmma,
                         cudaFuncAttributeMaxDynamicSharedMemorySize, FLASH_SMEM);

    rope_table_kernel<<<SEQ, 64>>>();

    dim3 tb(32, 8);
    transpose_split_kernel<<<dim3(4, 64, 16), tb>>>(WQ, wqh, wql, DMODEL, DHEAD);
    transpose_split_kernel<<<dim3(4, 64, 16), tb>>>(WK, wkh, wkl, DMODEL, DHEAD);
    transpose_split_kernel<<<dim3(4, 64, 16), tb>>>(WV, wvh, wvl, DMODEL, DHEAD);
    transpose_split_kernel<<<dim3(64, 64, 1), tb>>>(WO, woh, wol, DMODEL, DMODEL);

    dim3 ggrid(DMODEL / 256, MROWS / 128);   // (8, 32)
    const int nsplit = (MROWS * DMODEL) / (256 * 4);

    split_kernel<<<nsplit, 256>>>(qin, ah, al);
    gemm_hmma<<<ggrid, 256, GEMM_SMEM>>>(ah, al, wqh, wql, bQ, pq, 0, 0, 0);
    split_kernel<<<nsplit, 256>>>(kin, ah, al);
    gemm_hmma<<<ggrid, 256, GEMM_SMEM>>>(ah, al, wkh, wkl, bK, pk, 0, 0, 0);
    split_kernel<<<nsplit, 256>>>(vin, ah, al);
    gemm_hmma<<<ggrid, 256, GEMM_SMEM>>>(ah, al, wvh, wvl, bV, 0, vh, vl, 2);

    rope_split_kernel<<<(BHN * SEQ * 64) / 256, 256>>>();

    flash_hmma<<<dim3(SEQ / 128, BHN), 256, FLASH_SMEM>>>();  // -> g_ah/g_al

    gemm_hmma<<<ggrid, 256, GEMM_SMEM>>>(ah, al, woh, wol, bO, out, 0, 0, 1);
}

// round 8
// speedup vs baseline: 1.3178x; 1.3178x over previous
#include <cuda_runtime.h>
#include <cuda_bf16.h>
#include <math.h>
#include <stdint.h>

#define DMODEL 2048
#define NHEADS 16
#define DHEAD  128
#define SEQ    2048
#define BATCH  2
#define BHN    (BATCH*NHEADS)   // 32
#define MROWS  (BATCH*SEQ)      // 4096

// log2(e) / sqrt(128)
#define QSCALE (1.4426950408889634f * 0.08838834764831845f)

// ---- HMMA GEMM: CTA 128x128, KBLK 64, 4 warps (64x64 each), 128 threads ----
#define PADK 72                       // bf16 per smem row (144 B)
#define TILE_BYTES (128 * PADK * 2)   // 18432
#define OFF_AH 0
#define OFF_AL (TILE_BYTES)
#define OFF_BH (2*TILE_BYTES)
#define OFF_BL (3*TILE_BYTES)
#define GEMM_SMEM (4*TILE_BYTES)      // 73728 B

// ---- HMMA flash config: 128 q x 128 kv, stride 272 B ----
#define FS   272
#define FT   (128 * FS)
#define FQH  0
#define FQL  (FT)
#define FKH  (2*FT)
#define FKL  (3*FT)
#define FVH  (4*FT)
#define FVL  (5*FT)
#define FLASH_SMEM (6*FT)          // 208896 B

// ---------------- scratch (device globals; allocation-free) ----------------
__device__ float  g_q[(size_t)BHN * SEQ * DHEAD];
__device__ float  g_k[(size_t)BHN * SEQ * DHEAD];
__device__ float2 g_rope[SEQ * 64];

__device__ __nv_bfloat16 g_ah[(size_t)MROWS * DMODEL];
__device__ __nv_bfloat16 g_al[(size_t)MROWS * DMODEL];
__device__ __nv_bfloat16 g_wqh[(size_t)DMODEL * DMODEL];
__device__ __nv_bfloat16 g_wql[(size_t)DMODEL * DMODEL];
__device__ __nv_bfloat16 g_wkh[(size_t)DMODEL * DMODEL];
__device__ __nv_bfloat16 g_wkl[(size_t)DMODEL * DMODEL];
__device__ __nv_bfloat16 g_wvh[(size_t)DMODEL * DMODEL];
__device__ __nv_bfloat16 g_wvl[(size_t)DMODEL * DMODEL];
__device__ __nv_bfloat16 g_woh[(size_t)DMODEL * DMODEL];
__device__ __nv_bfloat16 g_wol[(size_t)DMODEL * DMODEL];

__device__ __nv_bfloat16 g_qh[(size_t)BHN * SEQ * DHEAD];
__device__ __nv_bfloat16 g_ql[(size_t)BHN * SEQ * DHEAD];
__device__ __nv_bfloat16 g_kh[(size_t)BHN * SEQ * DHEAD];
__device__ __nv_bfloat16 g_kl[(size_t)BHN * SEQ * DHEAD];
__device__ __nv_bfloat16 g_vh[(size_t)BHN * SEQ * DHEAD];
__device__ __nv_bfloat16 g_vl[(size_t)BHN * SEQ * DHEAD];

// ---------------- helpers ----------------
__device__ __forceinline__ void ldsm4(uint32_t* r, uint32_t addr) {
    asm volatile("ldmatrix.sync.aligned.m8n8.x4.shared.b16 {%0,%1,%2,%3}, [%4];"
                 : "=r"(r[0]), "=r"(r[1]), "=r"(r[2]), "=r"(r[3]) : "r"(addr));
}
__device__ __forceinline__ void ldsm4t(uint32_t* r, uint32_t addr) {
    asm volatile("ldmatrix.sync.aligned.m8n8.x4.trans.shared.b16 {%0,%1,%2,%3}, [%4];"
                 : "=r"(r[0]), "=r"(r[1]), "=r"(r[2]), "=r"(r[3]) : "r"(addr));
}
__device__ __forceinline__ void mma16816(float* d, const uint32_t* a,
                                         uint32_t b0, uint32_t b1) {
    asm volatile(
        "mma.sync.aligned.m16n8k16.row.col.f32.bf16.bf16.f32 "
        "{%0,%1,%2,%3}, {%4,%5,%6,%7}, {%8,%9}, {%0,%1,%2,%3};"
        : "+f"(d[0]), "+f"(d[1]), "+f"(d[2]), "+f"(d[3])
        : "r"(a[0]), "r"(a[1]), "r"(a[2]), "r"(a[3]), "r"(b0), "r"(b1));
}
__device__ __forceinline__ float ex2(float x) {
    float y; asm("ex2.approx.f32 %0, %1;" : "=f"(y) : "f"(x)); return y;
}
__device__ __forceinline__ uint32_t packbf(float lo, float hi) {
    uint32_t r; asm("cvt.rn.bf16x2.f32 %0, %1, %2;" : "=r"(r) : "f"(hi), "f"(lo));
    return r;
}
__device__ __forceinline__ void cpasync16(uint32_t s, const void* g) {
    asm volatile("cp.async.cg.shared.global [%0], [%1], 16;" :: "r"(s), "l"(g));
}

// ---------------------------------------------------------------------------
// RoPE table (fp32 angle, fp64 sin/cos)
// ---------------------------------------------------------------------------
__global__ void rope_table_kernel() {
    int p = blockIdx.x;
    int i = threadIdx.x;  // 0..63
    float freq = (float)pow(10000.0, (double)i / 64.0);
    float ang  = (float)p / freq;
    double s, c;
    sincos((double)ang, &s, &c);
    g_rope[p * 64 + i] = make_float2((float)s, (float)c);
}

// ---------------------------------------------------------------------------
// Rope + bf16 hi/lo split for q (QSCALE folded) and k.
// ---------------------------------------------------------------------------
__global__ void rope_split_kernel() {
    int gid = blockIdx.x * 256 + threadIdx.x;
    int i    = gid & 63;
    int rest = gid >> 6;
    int p    = rest & 2047;
    int bh   = rest >> 11;
    float2 sc = g_rope[p * 64 + i];
    size_t base = ((size_t)bh * SEQ + p) * DHEAD;

    float x0 = g_q[base + i], x1 = g_q[base + 64 + i];
    float q0 = (x0 * sc.y - x1 * sc.x) * QSCALE;
    float q1 = (x1 * sc.y + x0 * sc.x) * QSCALE;
    float y0 = g_k[base + i], y1 = g_k[base + 64 + i];
    float k0 = y0 * sc.y - y1 * sc.x;
    float k1 = y1 * sc.y + y0 * sc.x;

    __nv_bfloat16 h;
    h = __float2bfloat16(q0); g_qh[base + i]      = h; g_ql[base + i]      = __float2bfloat16(q0 - __bfloat162float(h));
    h = __float2bfloat16(q1); g_qh[base + 64 + i] = h; g_ql[base + 64 + i] = __float2bfloat16(q1 - __bfloat162float(h));
    h = __float2bfloat16(k0); g_kh[base + i]      = h; g_kl[base + i]      = __float2bfloat16(k0 - __bfloat162float(h));
    h = __float2bfloat16(k1); g_kh[base + 64 + i] = h; g_kl[base + 64 + i] = __float2bfloat16(k1 - __bfloat162float(h));
}

// ---------------------------------------------------------------------------
// fp32 -> (bf16 hi, bf16 lo) split, elementwise.
// ---------------------------------------------------------------------------
__global__ void split_kernel(const float* __restrict__ x,
                             __nv_bfloat16* __restrict__ hi,
                             __nv_bfloat16* __restrict__ lo) {
    size_t i = ((size_t)blockIdx.x * 256 + threadIdx.x) * 4;
    float4 v = *(const float4*)(x + i);
    float a[4] = {v.x, v.y, v.z, v.w};
    uint32_t ph[2], pl[2];
#pragma unroll
    for (int j = 0; j < 2; ++j) {
        __nv_bfloat16 h0 = __float2bfloat16(a[2*j]);
        __nv_bfloat16 h1 = __float2bfloat16(a[2*j+1]);
        __nv_bfloat16 l0 = __float2bfloat16(a[2*j]   - __bfloat162float(h0));
        __nv_bfloat16 l1 = __float2bfloat16(a[2*j+1] - __bfloat162float(h1));
        ph[j] = (uint32_t)__bfloat16_as_ushort(h0) | ((uint32_t)__bfloat16_as_ushort(h1) << 16);
        pl[j] = (uint32_t)__bfloat16_as_ushort(l0) | ((uint32_t)__bfloat16_as_ushort(l1) << 16);
    }
    *(uint2*)((char*)hi + i * 2) = make_uint2(ph[0], ph[1]);
    *(uint2*)((char*)lo + i * 2) = make_uint2(pl[0], pl[1]);
}

// ---------------------------------------------------------------------------
// Transpose + split: src [H][R][C] fp32 -> dst[h*C + c][r] bf16 (hi, lo).
// ---------------------------------------------------------------------------
__global__ void transpose_split_kernel(const float* __restrict__ src,
                                       __nv_bfloat16* __restrict__ hi,
                                       __nv_bfloat16* __restrict__ lo,
                                       int R, int C) {
    __shared__ float t[32][33];
    int h  = blockIdx.z;
    int r0 = blockIdx.y << 5, c0 = blockIdx.x << 5;
    int tx = threadIdx.x, ty = threadIdx.y;  // 32 x 8
    const float* s = src + (size_t)h * R * C;
#pragma unroll
    for (int j = 0; j < 4; ++j)
        t[ty + 8 * j][tx] = s[(size_t)(r0 + ty + 8 * j) * C + c0 + tx];
    __syncthreads();
#pragma unroll
    for (int j = 0; j < 4; ++j) {
        int c = c0 + ty + 8 * j;
        float v = t[tx][ty + 8 * j];
        __nv_bfloat16 vh = __float2bfloat16(v);
        __nv_bfloat16 vl = __float2bfloat16(v - __bfloat162float(vh));
        size_t o = (size_t)(h * C + c) * R + r0 + tx;
        hi[o] = vh;
        lo[o] = vl;
    }
}

// ---------------------------------------------------------------------------
// HMMA split GEMM (R6 winner): out = A * B^T + bias. Single-buffer KBLK=64,
// 4 warps (2m x 2n), warp tile 64x64, 128 threads, 2 CTAs/SM.
// mode 0: fp32 out -> [b][h][p][e]; mode 1: fp32 row-major;
// mode 2: bf16 hi/lo split out -> outh/outl at [b][h][p][e]  (V path).
// ---------------------------------------------------------------------------
__global__ __launch_bounds__(128, 2) void gemm_hmma(
    const __nv_bfloat16* __restrict__ Ah,
    const __nv_bfloat16* __restrict__ Al,
    const __nv_bfloat16* __restrict__ Bh,
    const __nv_bfloat16* __restrict__ Bl,
    const float* __restrict__ bias,
    float* __restrict__ out,
    __nv_bfloat16* __restrict__ outh,
    __nv_bfloat16* __restrict__ outl,
    int mode)
{
    extern __shared__ char sm[];
    const uint32_t sb = (uint32_t)__cvta_generic_to_shared(sm);

    const int tid  = threadIdx.x;
    const int wid  = tid >> 5;
    const int lane = tid & 31;
    const int row0 = blockIdx.y * 128;
    const int n0   = blockIdx.x * 128;
    const int m_w  = (wid & 1) * 64;
    const int n_w  = (wid >> 1) * 64;

    const uint32_t aOff = (uint32_t)(m_w + (lane & 15)) * 144 + ((lane >> 4) << 4);
    const uint32_t bOff = (uint32_t)(n_w + ((lane >> 4) << 3) + (lane & 7)) * 144 +
                          (uint32_t)((lane & 8) << 1);
    const uint32_t aHi = sb + OFF_AH + aOff;
    const uint32_t aLo = sb + OFF_AL + aOff;
    const uint32_t bHi = sb + OFF_BH + bOff;
    const uint32_t bLo = sb + OFF_BL + bOff;

    float acc[4][8][4];
#pragma unroll
    for (int i = 0; i < 4; ++i)
#pragma unroll
        for (int j = 0; j < 8; ++j)
#pragma unroll
            for (int r = 0; r < 4; ++r) acc[i][j][r] = 0.0f;

    const int lr  = tid >> 3;          // 0..15 (+16 per i)
    const int lc8 = (tid & 7) * 8;     // 0..56

    for (int it = 0; it < DMODEL / 64; ++it) {
        const int k0 = it * 64;
        __syncthreads();
#pragma unroll
        for (int i = 0; i < 8; ++i) {
            int r = lr + i * 16;
            size_t ga = (size_t)(row0 + r) * DMODEL + k0 + lc8;
            size_t gb = (size_t)(n0 + r) * DMODEL + k0 + lc8;
            uint32_t so = (uint32_t)(r * 144 + lc8 * 2);
            *(float4*)(sm + OFF_AH + so) = *(const float4*)(Ah + ga);
            *(float4*)(sm + OFF_AL + so) = *(const float4*)(Al + ga);
            *(float4*)(sm + OFF_BH + so) = *(const float4*)(Bh + gb);
            *(float4*)(sm + OFF_BL + so) = *(const float4*)(Bl + gb);
        }
        __syncthreads();

#pragma unroll
        for (int kk = 0; kk < 4; ++kk) {
            uint32_t Af[4][4], Bf[4][4];
            // pass 1: Ah * Bh
#pragma unroll
            for (int mi = 0; mi < 4; ++mi)
                ldsm4(Af[mi], aHi + mi * (16 * 144) + kk * 32);
#pragma unroll
            for (int ni = 0; ni < 4; ++ni)
                ldsm4(Bf[ni], bHi + ni * (16 * 144) + kk * 32);
#pragma unroll
            for (int mi = 0; mi < 4; ++mi)
#pragma unroll
                for (int j = 0; j < 8; ++j)
                    mma16816(acc[mi][j], Af[mi], Bf[j >> 1][(j & 1) * 2],
                             Bf[j >> 1][(j & 1) * 2 + 1]);
            // pass 2: Al * Bh (reuse Bf)
            {
                uint32_t Al4[4];
#pragma unroll
                for (int mi = 0; mi < 4; ++mi) {
                    ldsm4(Al4, aLo + mi * (16 * 144) + kk * 32);
#pragma unroll
                    for (int j = 0; j < 8; ++j)
                        mma16816(acc[mi][j], Al4, Bf[j >> 1][(j & 1) * 2],
                                 Bf[j >> 1][(j & 1) * 2 + 1]);
                }
            }
            // pass 3: Ah * Bl (reuse Af)
#pragma unroll
            for (int ni = 0; ni < 4; ++ni)
                ldsm4(Bf[ni], bLo + ni * (16 * 144) + kk * 32);
#pragma unroll
            for (int mi = 0; mi < 4; ++mi)
#pragma unroll
                for (int j = 0; j < 8; ++j)
                    mma16816(acc[mi][j], Af[mi], Bf[j >> 1][(j & 1) * 2],
                             Bf[j >> 1][(j & 1) * 2 + 1]);
        }
    }

    // Epilogue
    const int g = lane >> 2, t4 = lane & 3;
#pragma unroll
    for (int mi = 0; mi < 4; ++mi) {
        int m = row0 + m_w + mi * 16 + g;
#pragma unroll
        for (int j = 0; j < 8; ++j) {
            int col = n0 + n_w + j * 8 + t4 * 2;
            float b0 = bias[col], b1 = bias[col + 1];
            float2 v0 = make_float2(acc[mi][j][0] + b0, acc[mi][j][1] + b1);
            float2 v1 = make_float2(acc[mi][j][2] + b0, acc[mi][j][3] + b1);
            if (mode == 1) {
                *(float2*)(out + (size_t)m * DMODEL + col)       = v0;
                *(float2*)(out + (size_t)(m + 8) * DMODEL + col) = v1;
            } else {
                int h = col >> 7, e = col & 127;
                int b  = m >> 11, p = m & 2047;
                size_t base = (((size_t)(b * NHEADS + h) * SEQ) << 7) + e;
                size_t i0 = base + ((size_t)p << 7);
                size_t i1 = base + ((size_t)(p + 8) << 7);
                if (mode == 0) {
                    *(float2*)(out + i0) = v0;
                    *(float2*)(out + i1) = v1;
                } else {  // mode 2: bf16 hi/lo split (V path)
                    uint32_t h0 = packbf(v0.x, v0.y);
                    uint32_t l0 = packbf(v0.x - __uint_as_float(h0 << 16),
                                         v0.y - __uint_as_float(h0 & 0xffff0000u));
                    uint32_t h1 = packbf(v1.x, v1.y);
                    uint32_t l1 = packbf(v1.x - __uint_as_float(h1 << 16),
                                         v1.y - __uint_as_float(h1 & 0xffff0000u));
                    *(uint32_t*)(outh + i0) = h0;
                    *(uint32_t*)(outl + i0) = l0;
                    *(uint32_t*)(outh + i1) = h1;
                    *(uint32_t*)(outl + i1) = l1;
                }
            }
        }
    }
}

// ---------------------------------------------------------------------------
// HMMA causal flash attention. CTA = 128 q x 128 kv, 8 warps x 16 rows.
// V tiles loaded via cp.async, overlapped with the S-phase MMAs.
// Epilogue writes z directly as bf16 hi/lo into g_ah/g_al (O-proj input).
// ---------------------------------------------------------------------------
__global__ __launch_bounds__(256, 1) void flash_hmma() {
    extern __shared__ char sm[];
    const uint32_t sb = (uint32_t)__cvta_generic_to_shared(sm);

    const int tid  = threadIdx.x;
    const int wid  = tid >> 5;
    const int lane = tid & 31;
    const int bh   = blockIdx.y;
    const int qt   = gridDim.x - 1 - blockIdx.x;   // heavy tiles first
    const int q0   = qt * 128;

    const __nv_bfloat16* qh = g_qh + (size_t)bh * SEQ * DHEAD;
    const __nv_bfloat16* ql = g_ql + (size_t)bh * SEQ * DHEAD;
    const __nv_bfloat16* kh = g_kh + (size_t)bh * SEQ * DHEAD;
    const __nv_bfloat16* kl = g_kl + (size_t)bh * SEQ * DHEAD;
    const __nv_bfloat16* vh = g_vh + (size_t)bh * SEQ * DHEAD;
    const __nv_bfloat16* vl = g_vl + (size_t)bh * SEQ * DHEAD;

#pragma unroll
    for (int i = 0; i < 8; ++i) {
        int f = tid + i * 256;
        int r = f >> 4, c8 = (f & 15) * 8;
        uint32_t off = (uint32_t)(r * FS + c8 * 2);
        size_t g = (size_t)(q0 + r) * DHEAD + c8;
        *(uint4*)(sm + FQH + off) = *(const uint4*)(qh + g);
        *(uint4*)(sm + FQL + off) = *(const uint4*)(ql + g);
    }

    const uint32_t aOff = (uint32_t)(wid * 16 + (lane & 15)) * FS + ((lane >> 4) << 4);
    const uint32_t aQh = sb + FQH + aOff;
    const uint32_t aQl = sb + FQL + aOff;
    const uint32_t bOff = (uint32_t)(((lane >> 4) << 3) + (lane & 7)) * FS +
                          (uint32_t)((lane & 8) << 1);
    const uint32_t bKh = sb + FKH + bOff;
    const uint32_t bKl = sb + FKL + bOff;
    const uint32_t vOff = (uint32_t)(lane & 15) * FS + ((lane >> 4) << 4);
    const uint32_t bVh = sb + FVH + vOff;
    const uint32_t bVl = sb + FVL + vOff;

    float o[16][4];
#pragma unroll
    for (int j = 0; j < 16; ++j)
#pragma unroll
        for (int r = 0; r < 4; ++r) o[j][r] = 0.0f;
    float m1 = -1e30f, m2 = -1e30f, l1 = 0.0f, l2 = 0.0f;

    for (int t = 0; t <= qt; ++t) {
        const int k0 = t * 128;
        __syncthreads();   // all warps done with previous K/V smem
        // K tiles: direct ld/st (needed immediately). V tiles: cp.async,
        // waited only before the PV phase -> overlapped with S MMAs.
#pragma unroll
        for (int i = 0; i < 8; ++i) {
            int f = tid + i * 256;
            int r = f >> 4, c8 = (f & 15) * 8;
            uint32_t off = (uint32_t)(r * FS + c8 * 2);
            size_t g = (size_t)(k0 + r) * DHEAD + c8;
            *(uint4*)(sm + FKH + off) = *(const uint4*)(kh + g);
            *(uint4*)(sm + FKL + off) = *(const uint4*)(kl + g);
            cpasync16(sb + FVH + off, vh + g);
            cpasync16(sb + FVL + off, vl + g);
        }
        asm volatile("cp.async.commit_group;" ::: "memory");
        __syncthreads();   // K visible

        float s[16][4];
#pragma unroll
        for (int j = 0; j < 16; ++j)
#pragma unroll
            for (int r = 0; r < 4; ++r) s[j][r] = 0.0f;

#pragma unroll
        for (int kk = 0; kk < 8; ++kk) {
            uint32_t qa[4], qb[4], kb[4];
            ldsm4(qa, aQh + kk * 32);
            ldsm4(qb, aQl + kk * 32);
#pragma unroll
            for (int nn = 0; nn < 8; ++nn) {
                ldsm4(kb, bKh + nn * (16 * FS) + kk * 32);
                mma16816(s[2*nn],   qa, kb[0], kb[1]);
                mma16816(s[2*nn+1], qa, kb[2], kb[3]);
                mma16816(s[2*nn],   qb, kb[0], kb[1]);
                mma16816(s[2*nn+1], qb, kb[2], kb[3]);
                ldsm4(kb, bKl + nn * (16 * FS) + kk * 32);
                mma16816(s[2*nn],   qa, kb[0], kb[1]);
                mma16816(s[2*nn+1], qa, kb[2], kb[3]);
            }
        }

        const int r1 = q0 + wid * 16 + (lane >> 2);
        const int r2 = r1 + 8;
        if (t == qt) {
            const int c0 = k0 + (lane & 3) * 2;
#pragma unroll
            for (int j = 0; j < 16; ++j) {
                int col = c0 + j * 8;
                if (col     > r1) s[j][0] = -1e30f;
                if (col + 1 > r1) s[j][1] = -1e30f;
                if (col     > r2) s[j][2] = -1e30f;
                if (col + 1 > r2) s[j][3] = -1e30f;
            }
        }

        float mx1 = -1e30f, mx2 = -1e30f;
#pragma unroll
        for (int j = 0; j < 16; ++j) {
            mx1 = fmaxf(mx1, fmaxf(s[j][0], s[j][1]));
            mx2 = fmaxf(mx2, fmaxf(s[j][2], s[j][3]));
        }
        mx1 = fmaxf(mx1, __shfl_xor_sync(0xffffffffu, mx1, 1));
        mx1 = fmaxf(mx1, __shfl_xor_sync(0xffffffffu, mx1, 2));
        mx2 = fmaxf(mx2, __shfl_xor_sync(0xffffffffu, mx2, 1));
        mx2 = fmaxf(mx2, __shfl_xor_sync(0xffffffffu, mx2, 2));
        float mn1 = fmaxf(m1, mx1), mn2 = fmaxf(m2, mx2);
        float sc1 = ex2(m1 - mn1), sc2 = ex2(m2 - mn2);
        float rs1 = 0.0f, rs2 = 0.0f;
#pragma unroll
        for (int j = 0; j < 16; ++j) {
            s[j][0] = ex2(s[j][0] - mn1);
            s[j][1] = ex2(s[j][1] - mn1);
            s[j][2] = ex2(s[j][2] - mn2);
            s[j][3] = ex2(s[j][3] - mn2);
            rs1 += s[j][0] + s[j][1];
            rs2 += s[j][2] + s[j][3];
        }
        rs1 += __shfl_xor_sync(0xffffffffu, rs1, 1);
        rs1 += __shfl_xor_sync(0xffffffffu, rs1, 2);
        rs2 += __shfl_xor_sync(0xffffffffu, rs2, 1);
        rs2 += __shfl_xor_sync(0xffffffffu, rs2, 2);
        l1 = l1 * sc1 + rs1;  m1 = mn1;
        l2 = l2 * sc2 + rs2;  m2 = mn2;
#pragma unroll
        for (int j = 0; j < 16; ++j) {
            o[j][0] *= sc1; o[j][1] *= sc1;
            o[j][2] *= sc2; o[j][3] *= sc2;
        }

        // V must be complete and visible to all warps before PV
        asm volatile("cp.async.wait_group 0;" ::: "memory");
        __syncthreads();

#pragma unroll
        for (int kk = 0; kk < 8; ++kk) {
            uint32_t ph[4], pl[4], vb[4];
#pragma unroll
            for (int hv = 0; hv < 2; ++hv) {
                const float* sp = s[2*kk + hv];
                uint32_t p0 = packbf(sp[0], sp[1]);
                uint32_t p1 = packbf(sp[2], sp[3]);
                ph[hv*2]   = p0;
                ph[hv*2+1] = p1;
                pl[hv*2]   = packbf(sp[0] - __uint_as_float(p0 << 16),
                                    sp[1] - __uint_as_float(p0 & 0xffff0000u));
                pl[hv*2+1] = packbf(sp[2] - __uint_as_float(p1 << 16),
                                    sp[3] - __uint_as_float(p1 & 0xffff0000u));
            }
            uint32_t pha[4] = {ph[0], ph[1], ph[2], ph[3]};
            uint32_t pla[4] = {pl[0], pl[1], pl[2], pl[3]};
#pragma unroll
            for (int nn = 0; nn < 8; ++nn) {
                ldsm4t(vb, bVh + kk * (16 * FS) + nn * 32);
                mma16816(o[2*nn],   pha, vb[0], vb[1]);
                mma16816(o[2*nn+1], pha, vb[2], vb[3]);
                mma16816(o[2*nn],   pla, vb[0], vb[1]);
                mma16816(o[2*nn+1], pla, vb[2], vb[3]);
                ldsm4t(vb, bVl + kk * (16 * FS) + nn * 32);
                mma16816(o[2*nn],   pha, vb[0], vb[1]);
                mma16816(o[2*nn+1], pha, vb[2], vb[3]);
            }
        }
    }

    // Epilogue: normalize + bf16 hi/lo split straight into g_ah/g_al.
    const int b = bh >> 4, h = bh & 15;
    const int r1 = q0 + wid * 16 + (lane >> 2);
    const float inv1 = 1.0f / l1, inv2 = 1.0f / l2;
    size_t base1 = (size_t)(b * SEQ + r1) * DMODEL + h * DHEAD + (lane & 3) * 2;
    size_t base2 = base1 + (size_t)8 * DMODEL;
#pragma unroll
    for (int j = 0; j < 16; ++j) {
        float a0 = o[j][0] * inv1, a1 = o[j][1] * inv1;
        uint32_t hh = packbf(a0, a1);
        uint32_t ll = packbf(a0 - __uint_as_float(hh << 16),
                             a1 - __uint_as_float(hh & 0xffff0000u));
        *(uint32_t*)&g_ah[base1 + j * 8] = hh;
        *(uint32_t*)&g_al[base1 + j * 8] = ll;
        float a2 = o[j][2] * inv2, a3 = o[j][3] * inv2;
        uint32_t hh2 = packbf(a2, a3);
        uint32_t ll2 = packbf(a2 - __uint_as_float(hh2 << 16),
                              a3 - __uint_as_float(hh2 & 0xffff0000u));
        *(uint32_t*)&g_ah[base2 + j * 8] = hh2;
        *(uint32_t*)&g_al[base2 + j * 8] = ll2;
    }
}

// ---------------------------------------------------------------------------
extern "C" void kernel_launch(void* const* d_in, const int* in_sizes, int n_in,
                              void* d_out, int out_size) {
    (void)in_sizes; (void)n_in; (void)out_size;
    const float* qin = (const float*)d_in[0];
    const float* kin = (const float*)d_in[1];
    const float* vin = (const float*)d_in[2];
    const float* WQ  = (const float*)d_in[3];
    const float* WK  = (const float*)d_in[4];
    const float* WV  = (const float*)d_in[5];
    const float* WO  = (const float*)d_in[6];
    const float* bQ  = (const float*)d_in[7];
    const float* bK  = (const float*)d_in[8];
    const float* bV  = (const float*)d_in[9];
    const float* bO  = (const float*)d_in[10];
    float* out = (float*)d_out;

    float *pq, *pk;
    __nv_bfloat16 *ah, *al, *wqh, *wql, *wkh, *wkl, *wvh, *wvl, *woh, *wol, *vh, *vl;
    cudaGetSymbolAddress((void**)&pq, g_q);
    cudaGetSymbolAddress((void**)&pk, g_k);
    cudaGetSymbolAddress((void**)&ah, g_ah);
    cudaGetSymbolAddress((void**)&al, g_al);
    cudaGetSymbolAddress((void**)&wqh, g_wqh);
    cudaGetSymbolAddress((void**)&wql, g_wql);
    cudaGetSymbolAddress((void**)&wkh, g_wkh);
    cudaGetSymbolAddress((void**)&wkl, g_wkl);
    cudaGetSymbolAddress((void**)&wvh, g_wvh);
    cudaGetSymbolAddress((void**)&wvl, g_wvl);
    cudaGetSymbolAddress((void**)&woh, g_woh);
    cudaGetSymbolAddress((void**)&wol, g_wol);
    cudaGetSymbolAddress((void**)&vh, g_vh);
    cudaGetSymbolAddress((void**)&vl, g_vl);

    cudaFuncSetAttribute((const void*)gemm_hmma,
                         cudaFuncAttributeMaxDynamicSharedMemorySize, GEMM_SMEM);
    cudaFuncSetAttribute((const void*)flash_hmma,
                         cudaFuncAttributeMaxDynamicSharedMemorySize, FLASH_SMEM);

    dim3 tb(32, 8);
    dim3 ggrid(DMODEL / 128, MROWS / 128);   // (16, 32)
    const int nsplit = (MROWS * DMODEL) / (256 * 4);

    // Launch order arranged so launch #5 (ncu capture window) = gemm_hmma.
    transpose_split_kernel<<<dim3(4, 64, 16), tb>>>(WQ, wqh, wql, DMODEL, DHEAD);  // 1
    transpose_split_kernel<<<dim3(4, 64, 16), tb>>>(WK, wkh, wkl, DMODEL, DHEAD);  // 2
    transpose_split_kernel<<<dim3(4, 64, 16), tb>>>(WV, wvh, wvl, DMODEL, DHEAD);  // 3
    split_kernel<<<nsplit, 256>>>(qin, ah, al);                                    // 4
    gemm_hmma<<<ggrid, 128, GEMM_SMEM>>>(ah, al, wqh, wql, bQ, pq, 0, 0, 0);       // 5
    split_kernel<<<nsplit, 256>>>(kin, ah, al);                                    // 6
    gemm_hmma<<<ggrid, 128, GEMM_SMEM>>>(ah, al, wkh, wkl, bK, pk, 0, 0, 0);       // 7
    split_kernel<<<nsplit, 256>>>(vin, ah, al);                                    // 8
    gemm_hmma<<<ggrid, 128, GEMM_SMEM>>>(ah, al, wvh, wvl, bV, 0, vh, vl, 2);      // 9
    transpose_split_kernel<<<dim3(64, 64, 1), tb>>>(WO, woh, wol, DMODEL, DMODEL); // 10
    rope_table_kernel<<<SEQ, 64>>>();                                              // 11
    rope_split_kernel<<<(BHN * SEQ * 64) / 256, 256>>>();                          // 12
    flash_hmma<<<dim3(SEQ / 128, BHN), 256, FLASH_SMEM>>>();                       // 13
    gemm_hmma<<<ggrid, 128, GEMM_SMEM>>>(ah, al, woh, wol, bO, out, 0, 0, 1);      // 14
}

// round 9
// speedup vs baseline: 1.6492x; 1.2514x over previous
#include <cuda_runtime.h>
#include <cuda_bf16.h>
#include <cuda_fp16.h>
#include <math.h>
#include <stdint.h>

#define DMODEL 2048
#define NHEADS 16
#define DHEAD  128
#define SEQ    2048
#define BATCH  2
#define BHN    (BATCH*NHEADS)   // 32
#define MROWS  (BATCH*SEQ)      // 4096

// log2(e) / sqrt(128)
#define QSCALE (1.4426950408889634f * 0.08838834764831845f)

// ---- fp16 2-pass GEMM: CTA 128x128, KBLK 64, 4 warps (64x64), 128 thr ----
#define PADK 72                       // fp16 per smem row (144 B)
#define TILE_BYTES (128 * PADK * 2)   // 18432
#define OFF_AH 0
#define OFF_AL (TILE_BYTES)
#define OFF_BH (2*TILE_BYTES)
#define GEMM_SMEM (3*TILE_BYTES)      // 55296 B (2 CTAs/SM)

// ---- HMMA flash config (bf16 3-pass, unchanged): 128 q x 128 kv ----
#define FS   272
#define FT   (128 * FS)
#define FQH  0
#define FQL  (FT)
#define FKH  (2*FT)
#define FKL  (3*FT)
#define FVH  (4*FT)
#define FVL  (5*FT)
#define FLASH_SMEM (6*FT)          // 208896 B

// ---------------- scratch (device globals; allocation-free) ----------------
__device__ float  g_q[(size_t)BHN * SEQ * DHEAD];
__device__ float  g_k[(size_t)BHN * SEQ * DHEAD];
__device__ float2 g_rope[SEQ * 64];

__device__ __half g_ah[(size_t)MROWS * DMODEL];
__device__ __half g_al[(size_t)MROWS * DMODEL];
__device__ __half g_wq[(size_t)DMODEL * DMODEL];
__device__ __half g_wk[(size_t)DMODEL * DMODEL];
__device__ __half g_wv[(size_t)DMODEL * DMODEL];
__device__ __half g_wo[(size_t)DMODEL * DMODEL];

__device__ __nv_bfloat16 g_qh[(size_t)BHN * SEQ * DHEAD];
__device__ __nv_bfloat16 g_ql[(size_t)BHN * SEQ * DHEAD];
__device__ __nv_bfloat16 g_kh[(size_t)BHN * SEQ * DHEAD];
__device__ __nv_bfloat16 g_kl[(size_t)BHN * SEQ * DHEAD];
__device__ __nv_bfloat16 g_vh[(size_t)BHN * SEQ * DHEAD];
__device__ __nv_bfloat16 g_vl[(size_t)BHN * SEQ * DHEAD];

// ---------------- helpers ----------------
__device__ __forceinline__ void ldsm4(uint32_t* r, uint32_t addr) {
    asm volatile("ldmatrix.sync.aligned.m8n8.x4.shared.b16 {%0,%1,%2,%3}, [%4];"
                 : "=r"(r[0]), "=r"(r[1]), "=r"(r[2]), "=r"(r[3]) : "r"(addr));
}
__device__ __forceinline__ void ldsm4t(uint32_t* r, uint32_t addr) {
    asm volatile("ldmatrix.sync.aligned.m8n8.x4.trans.shared.b16 {%0,%1,%2,%3}, [%4];"
                 : "=r"(r[0]), "=r"(r[1]), "=r"(r[2]), "=r"(r[3]) : "r"(addr));
}
// bf16 mma (flash)
__device__ __forceinline__ void mma16816(float* d, const uint32_t* a,
                                         uint32_t b0, uint32_t b1) {
    asm volatile(
        "mma.sync.aligned.m16n8k16.row.col.f32.bf16.bf16.f32 "
        "{%0,%1,%2,%3}, {%4,%5,%6,%7}, {%8,%9}, {%0,%1,%2,%3};"
        : "+f"(d[0]), "+f"(d[1]), "+f"(d[2]), "+f"(d[3])
        : "r"(a[0]), "r"(a[1]), "r"(a[2]), "r"(a[3]), "r"(b0), "r"(b1));
}
// fp16 mma (projections)
__device__ __forceinline__ void mma16816h(float* d, const uint32_t* a,
                                          uint32_t b0, uint32_t b1) {
    asm volatile(
        "mma.sync.aligned.m16n8k16.row.col.f32.f16.f16.f32 "
        "{%0,%1,%2,%3}, {%4,%5,%6,%7}, {%8,%9}, {%0,%1,%2,%3};"
        : "+f"(d[0]), "+f"(d[1]), "+f"(d[2]), "+f"(d[3])
        : "r"(a[0]), "r"(a[1]), "r"(a[2]), "r"(a[3]), "r"(b0), "r"(b1));
}
__device__ __forceinline__ float ex2(float x) {
    float y; asm("ex2.approx.f32 %0, %1;" : "=f"(y) : "f"(x)); return y;
}
__device__ __forceinline__ uint32_t packbf(float lo, float hi) {
    uint32_t r; asm("cvt.rn.bf16x2.f32 %0, %1, %2;" : "=r"(r) : "f"(hi), "f"(lo));
    return r;
}
__device__ __forceinline__ void cpasync16(uint32_t s, const void* g) {
    asm volatile("cp.async.cg.shared.global [%0], [%1], 16;" :: "r"(s), "l"(g));
}

// ---------------------------------------------------------------------------
// RoPE table (fp32 angle, fp64 sin/cos)
// ---------------------------------------------------------------------------
__global__ void rope_table_kernel() {
    int p = blockIdx.x;
    int i = threadIdx.x;  // 0..63
    float freq = (float)pow(10000.0, (double)i / 64.0);
    float ang  = (float)p / freq;
    double s, c;
    sincos((double)ang, &s, &c);
    g_rope[p * 64 + i] = make_float2((float)s, (float)c);
}

// ---------------------------------------------------------------------------
// Rope + bf16 hi/lo split for q (QSCALE folded) and k (flash inputs).
// ---------------------------------------------------------------------------
__global__ void rope_split_kernel() {
    int gid = blockIdx.x * 256 + threadIdx.x;
    int i    = gid & 63;
    int rest = gid >> 6;
    int p    = rest & 2047;
    int bh   = rest >> 11;
    float2 sc = g_rope[p * 64 + i];
    size_t base = ((size_t)bh * SEQ + p) * DHEAD;

    float x0 = g_q[base + i], x1 = g_q[base + 64 + i];
    float q0 = (x0 * sc.y - x1 * sc.x) * QSCALE;
    float q1 = (x1 * sc.y + x0 * sc.x) * QSCALE;
    float y0 = g_k[base + i], y1 = g_k[base + 64 + i];
    float k0 = y0 * sc.y - y1 * sc.x;
    float k1 = y1 * sc.y + y0 * sc.x;

    __nv_bfloat16 h;
    h = __float2bfloat16(q0); g_qh[base + i]      = h; g_ql[base + i]      = __float2bfloat16(q0 - __bfloat162float(h));
    h = __float2bfloat16(q1); g_qh[base + 64 + i] = h; g_ql[base + 64 + i] = __float2bfloat16(q1 - __bfloat162float(h));
    h = __float2bfloat16(k0); g_kh[base + i]      = h; g_kl[base + i]      = __float2bfloat16(k0 - __bfloat162float(h));
    h = __float2bfloat16(k1); g_kh[base + 64 + i] = h; g_kl[base + 64 + i] = __float2bfloat16(k1 - __bfloat162float(h));
}

// ---------------------------------------------------------------------------
// fp32 -> (fp16 hi, fp16 lo) split, elementwise (activations).
// ---------------------------------------------------------------------------
__global__ void split_kernel(const float* __restrict__ x,
                             __half* __restrict__ hi,
                             __half* __restrict__ lo) {
    size_t i = ((size_t)blockIdx.x * 256 + threadIdx.x) * 4;
    float4 v = *(const float4*)(x + i);
    float a[4] = {v.x, v.y, v.z, v.w};
    uint32_t ph[2], pl[2];
#pragma unroll
    for (int j = 0; j < 2; ++j) {
        __half2 h2 = __float22half2_rn(make_float2(a[2*j], a[2*j+1]));
        float2 bk = __half22float2(h2);
        __half2 l2 = __float22half2_rn(make_float2(a[2*j] - bk.x, a[2*j+1] - bk.y));
        ph[j] = *(uint32_t*)&h2;
        pl[j] = *(uint32_t*)&l2;
    }
    *(uint2*)((char*)hi + i * 2) = make_uint2(ph[0], ph[1]);
    *(uint2*)((char*)lo + i * 2) = make_uint2(pl[0], pl[1]);
}

// ---------------------------------------------------------------------------
// Transpose + fp16 round: src [H][R][C] fp32 -> dst[h*C + c][r] fp16 (hi only).
// ---------------------------------------------------------------------------
__global__ void transpose_half_kernel(const float* __restrict__ src,
                                      __half* __restrict__ dst,
                                      int R, int C) {
    __shared__ float t[32][33];
    int h  = blockIdx.z;
    int r0 = blockIdx.y << 5, c0 = blockIdx.x << 5;
    int tx = threadIdx.x, ty = threadIdx.y;  // 32 x 8
    const float* s = src + (size_t)h * R * C;
#pragma unroll
    for (int j = 0; j < 4; ++j)
        t[ty + 8 * j][tx] = s[(size_t)(r0 + ty + 8 * j) * C + c0 + tx];
    __syncthreads();
#pragma unroll
    for (int j = 0; j < 4; ++j) {
        int c = c0 + ty + 8 * j;
        dst[(size_t)(h * C + c) * R + r0 + tx] = __float2half_rn(t[tx][ty + 8 * j]);
    }
}

// ---------------------------------------------------------------------------
// fp16 2-pass GEMM: out = A * B^T + bias;  D = Ah*Bh + Al*Bh.
// CTA 128x128, KBLK 64, 4 warps (64x64), 128 threads, 2 CTAs/SM.
// mode 0: fp32 out -> [b][h][p][e]; mode 1: fp32 row-major;
// mode 2: bf16 hi/lo split -> outh/outl at [b][h][p][e]  (V path, for flash).
// ---------------------------------------------------------------------------
__global__ __launch_bounds__(128, 2) void gemm_hmma(
    const __half* __restrict__ Ah,
    const __half* __restrict__ Al,
    const __half* __restrict__ Bh,
    const float* __restrict__ bias,
    float* __restrict__ out,
    __nv_bfloat16* __restrict__ outh,
    __nv_bfloat16* __restrict__ outl,
    int mode)
{
    extern __shared__ char sm[];
    const uint32_t sb = (uint32_t)__cvta_generic_to_shared(sm);

    const int tid  = threadIdx.x;
    const int wid  = tid >> 5;
    const int lane = tid & 31;
    const int row0 = blockIdx.y * 128;
    const int n0   = blockIdx.x * 128;
    const int m_w  = (wid & 1) * 64;
    const int n_w  = (wid >> 1) * 64;

    const uint32_t aOff = (uint32_t)(m_w + (lane & 15)) * 144 + ((lane >> 4) << 4);
    const uint32_t bOff = (uint32_t)(n_w + ((lane >> 4) << 3) + (lane & 7)) * 144 +
                          (uint32_t)((lane & 8) << 1);
    const uint32_t aHi = sb + OFF_AH + aOff;
    const uint32_t aLo = sb + OFF_AL + aOff;
    const uint32_t bHi = sb + OFF_BH + bOff;

    float acc[4][8][4];
#pragma unroll
    for (int i = 0; i < 4; ++i)
#pragma unroll
        for (int j = 0; j < 8; ++j)
#pragma unroll
            for (int r = 0; r < 4; ++r) acc[i][j][r] = 0.0f;

    const int lr  = tid >> 3;          // 0..15 (+16 per i)
    const int lc8 = (tid & 7) * 8;     // 0..56

    for (int it = 0; it < DMODEL / 64; ++it) {
        const int k0 = it * 64;
        __syncthreads();
#pragma unroll
        for (int i = 0; i < 8; ++i) {
            int r = lr + i * 16;
            size_t ga = (size_t)(row0 + r) * DMODEL + k0 + lc8;
            size_t gb = (size_t)(n0 + r) * DMODEL + k0 + lc8;
            uint32_t so = (uint32_t)(r * 144 + lc8 * 2);
            *(float4*)(sm + OFF_AH + so) = *(const float4*)(Ah + ga);
            *(float4*)(sm + OFF_AL + so) = *(const float4*)(Al + ga);
            *(float4*)(sm + OFF_BH + so) = *(const float4*)(Bh + gb);
        }
        __syncthreads();

#pragma unroll
        for (int kk = 0; kk < 4; ++kk) {
            uint32_t Af[4][4], Bf[4][4];
            // pass 1: Ah * Bh
#pragma unroll
            for (int mi = 0; mi < 4; ++mi)
                ldsm4(Af[mi], aHi + mi * (16 * 144) + kk * 32);
#pragma unroll
            for (int ni = 0; ni < 4; ++ni)
                ldsm4(Bf[ni], bHi + ni * (16 * 144) + kk * 32);
#pragma unroll
            for (int mi = 0; mi < 4; ++mi)
#pragma unroll
                for (int j = 0; j < 8; ++j)
                    mma16816h(acc[mi][j], Af[mi], Bf[j >> 1][(j & 1) * 2],
                              Bf[j >> 1][(j & 1) * 2 + 1]);
            // pass 2: Al * Bh (reuse Bf)
#pragma unroll
            for (int mi = 0; mi < 4; ++mi) {
                uint32_t Al4[4];
                ldsm4(Al4, aLo + mi * (16 * 144) + kk * 32);
#pragma unroll
                for (int j = 0; j < 8; ++j)
                    mma16816h(acc[mi][j], Al4, Bf[j >> 1][(j & 1) * 2],
                              Bf[j >> 1][(j & 1) * 2 + 1]);
            }
        }
    }

    // Epilogue
    const int g = lane >> 2, t4 = lane & 3;
#pragma unroll
    for (int mi = 0; mi < 4; ++mi) {
        int m = row0 + m_w + mi * 16 + g;
#pragma unroll
        for (int j = 0; j < 8; ++j) {
            int col = n0 + n_w + j * 8 + t4 * 2;
            float b0 = bias[col], b1 = bias[col + 1];
            float2 v0 = make_float2(acc[mi][j][0] + b0, acc[mi][j][1] + b1);
            float2 v1 = make_float2(acc[mi][j][2] + b0, acc[mi][j][3] + b1);
            if (mode == 1) {
                *(float2*)(out + (size_t)m * DMODEL + col)       = v0;
                *(float2*)(out + (size_t)(m + 8) * DMODEL + col) = v1;
            } else {
                int h = col >> 7, e = col & 127;
                int b  = m >> 11, p = m & 2047;
                size_t base = (((size_t)(b * NHEADS + h) * SEQ) << 7) + e;
                size_t i0 = base + ((size_t)p << 7);
                size_t i1 = base + ((size_t)(p + 8) << 7);
                if (mode == 0) {
                    *(float2*)(out + i0) = v0;
                    *(float2*)(out + i1) = v1;
                } else {  // mode 2: bf16 hi/lo split (V path)
                    uint32_t h0 = packbf(v0.x, v0.y);
                    uint32_t l0 = packbf(v0.x - __uint_as_float(h0 << 16),
                                         v0.y - __uint_as_float(h0 & 0xffff0000u));
                    uint32_t h1 = packbf(v1.x, v1.y);
                    uint32_t l1 = packbf(v1.x - __uint_as_float(h1 << 16),
                                         v1.y - __uint_as_float(h1 & 0xffff0000u));
                    *(uint32_t*)(outh + i0) = h0;
                    *(uint32_t*)(outl + i0) = l0;
                    *(uint32_t*)(outh + i1) = h1;
                    *(uint32_t*)(outl + i1) = l1;
                }
            }
        }
    }
}

// ---------------------------------------------------------------------------
// HMMA causal flash attention (bf16 3-pass, V via cp.async overlap).
// Epilogue writes z as fp16 hi/lo into g_ah/g_al (O-proj input).
// ---------------------------------------------------------------------------
__global__ __launch_bounds__(256, 1) void flash_hmma() {
    extern __shared__ char sm[];
    const uint32_t sb = (uint32_t)__cvta_generic_to_shared(sm);

    const int tid  = threadIdx.x;
    const int wid  = tid >> 5;
    const int lane = tid & 31;
    const int bh   = blockIdx.y;
    const int qt   = gridDim.x - 1 - blockIdx.x;   // heavy tiles first
    const int q0   = qt * 128;

    const __nv_bfloat16* qh = g_qh + (size_t)bh * SEQ * DHEAD;
    const __nv_bfloat16* ql = g_ql + (size_t)bh * SEQ * DHEAD;
    const __nv_bfloat16* kh = g_kh + (size_t)bh * SEQ * DHEAD;
    const __nv_bfloat16* kl = g_kl + (size_t)bh * SEQ * DHEAD;
    const __nv_bfloat16* vh = g_vh + (size_t)bh * SEQ * DHEAD;
    const __nv_bfloat16* vl = g_vl + (size_t)bh * SEQ * DHEAD;

#pragma unroll
    for (int i = 0; i < 8; ++i) {
        int f = tid + i * 256;
        int r = f >> 4, c8 = (f & 15) * 8;
        uint32_t off = (uint32_t)(r * FS + c8 * 2);
        size_t g = (size_t)(q0 + r) * DHEAD + c8;
        *(uint4*)(sm + FQH + off) = *(const uint4*)(qh + g);
        *(uint4*)(sm + FQL + off) = *(const uint4*)(ql + g);
    }

    const uint32_t aOff = (uint32_t)(wid * 16 + (lane & 15)) * FS + ((lane >> 4) << 4);
    const uint32_t aQh = sb + FQH + aOff;
    const uint32_t aQl = sb + FQL + aOff;
    const uint32_t bOff = (uint32_t)(((lane >> 4) << 3) + (lane & 7)) * FS +
                          (uint32_t)((lane & 8) << 1);
    const uint32_t bKh = sb + FKH + bOff;
    const uint32_t bKl = sb + FKL + bOff;
    const uint32_t vOff = (uint32_t)(lane & 15) * FS + ((lane >> 4) << 4);
    const uint32_t bVh = sb + FVH + vOff;
    const uint32_t bVl = sb + FVL + vOff;

    float o[16][4];
#pragma unroll
    for (int j = 0; j < 16; ++j)
#pragma unroll
        for (int r = 0; r < 4; ++r) o[j][r] = 0.0f;
    float m1 = -1e30f, m2 = -1e30f, l1 = 0.0f, l2 = 0.0f;

    for (int t = 0; t <= qt; ++t) {
        const int k0 = t * 128;
        __syncthreads();
#pragma unroll
        for (int i = 0; i < 8; ++i) {
            int f = tid + i * 256;
            int r = f >> 4, c8 = (f & 15) * 8;
            uint32_t off = (uint32_t)(r * FS + c8 * 2);
            size_t g = (size_t)(k0 + r) * DHEAD + c8;
            *(uint4*)(sm + FKH + off) = *(const uint4*)(kh + g);
            *(uint4*)(sm + FKL + off) = *(const uint4*)(kl + g);
            cpasync16(sb + FVH + off, vh + g);
            cpasync16(sb + FVL + off, vl + g);
        }
        asm volatile("cp.async.commit_group;" ::: "memory");
        __syncthreads();   // K visible

        float s[16][4];
#pragma unroll
        for (int j = 0; j < 16; ++j)
#pragma unroll
            for (int r = 0; r < 4; ++r) s[j][r] = 0.0f;

#pragma unroll
        for (int kk = 0; kk < 8; ++kk) {
            uint32_t qa[4], qb[4], kb[4];
            ldsm4(qa, aQh + kk * 32);
            ldsm4(qb, aQl + kk * 32);
#pragma unroll
            for (int nn = 0; nn < 8; ++nn) {
                ldsm4(kb, bKh + nn * (16 * FS) + kk * 32);
                mma16816(s[2*nn],   qa, kb[0], kb[1]);
                mma16816(s[2*nn+1], qa, kb[2], kb[3]);
                mma16816(s[2*nn],   qb, kb[0], kb[1]);
                mma16816(s[2*nn+1], qb, kb[2], kb[3]);
                ldsm4(kb, bKl + nn * (16 * FS) + kk * 32);
                mma16816(s[2*nn],   qa, kb[0], kb[1]);
                mma16816(s[2*nn+1], qa, kb[2], kb[3]);
            }
        }

        const int r1 = q0 + wid * 16 + (lane >> 2);
        const int r2 = r1 + 8;
        if (t == qt) {
            const int c0 = k0 + (lane & 3) * 2;
#pragma unroll
            for (int j = 0; j < 16; ++j) {
                int col = c0 + j * 8;
                if (col     > r1) s[j][0] = -1e30f;
                if (col + 1 > r1) s[j][1] = -1e30f;
                if (col     > r2) s[j][2] = -1e30f;
                if (col + 1 > r2) s[j][3] = -1e30f;
            }
        }

        float mx1 = -1e30f, mx2 = -1e30f;
#pragma unroll
        for (int j = 0; j < 16; ++j) {
            mx1 = fmaxf(mx1, fmaxf(s[j][0], s[j][1]));
            mx2 = fmaxf(mx2, fmaxf(s[j][2], s[j][3]));
        }
        mx1 = fmaxf(mx1, __shfl_xor_sync(0xffffffffu, mx1, 1));
        mx1 = fmaxf(mx1, __shfl_xor_sync(0xffffffffu, mx1, 2));
        mx2 = fmaxf(mx2, __shfl_xor_sync(0xffffffffu, mx2, 1));
        mx2 = fmaxf(mx2, __shfl_xor_sync(0xffffffffu, mx2, 2));
        float mn1 = fmaxf(m1, mx1), mn2 = fmaxf(m2, mx2);
        float sc1 = ex2(m1 - mn1), sc2 = ex2(m2 - mn2);
        float rs1 = 0.0f, rs2 = 0.0f;
#pragma unroll
        for (int j = 0; j < 16; ++j) {
            s[j][0] = ex2(s[j][0] - mn1);
            s[j][1] = ex2(s[j][1] - mn1);
            s[j][2] = ex2(s[j][2] - mn2);
            s[j][3] = ex2(s[j][3] - mn2);
            rs1 += s[j][0] + s[j][1];
            rs2 += s[j][2] + s[j][3];
        }
        rs1 += __shfl_xor_sync(0xffffffffu, rs1, 1);
        rs1 += __shfl_xor_sync(0xffffffffu, rs1, 2);
        rs2 += __shfl_xor_sync(0xffffffffu, rs2, 1);
        rs2 += __shfl_xor_sync(0xffffffffu, rs2, 2);
        l1 = l1 * sc1 + rs1;  m1 = mn1;
        l2 = l2 * sc2 + rs2;  m2 = mn2;
#pragma unroll
        for (int j = 0; j < 16; ++j) {
            o[j][0] *= sc1; o[j][1] *= sc1;
            o[j][2] *= sc2; o[j][3] *= sc2;
        }

        asm volatile("cp.async.wait_group 0;" ::: "memory");
        __syncthreads();   // V visible

#pragma unroll
        for (int kk = 0; kk < 8; ++kk) {
            uint32_t ph[4], pl[4], vb[4];
#pragma unroll
            for (int hv = 0; hv < 2; ++hv) {
                const float* sp = s[2*kk + hv];
                uint32_t p0 = packbf(sp[0], sp[1]);
                uint32_t p1 = packbf(sp[2], sp[3]);
                ph[hv*2]   = p0;
                ph[hv*2+1] = p1;
                pl[hv*2]   = packbf(sp[0] - __uint_as_float(p0 << 16),
                                    sp[1] - __uint_as_float(p0 & 0xffff0000u));
                pl[hv*2+1] = packbf(sp[2] - __uint_as_float(p1 << 16),
                                    sp[3] - __uint_as_float(p1 & 0xffff0000u));
            }
            uint32_t pha[4] = {ph[0], ph[1], ph[2], ph[3]};
            uint32_t pla[4] = {pl[0], pl[1], pl[2], pl[3]};
#pragma unroll
            for (int nn = 0; nn < 8; ++nn) {
                ldsm4t(vb, bVh + kk * (16 * FS) + nn * 32);
                mma16816(o[2*nn],   pha, vb[0], vb[1]);
                mma16816(o[2*nn+1], pha, vb[2], vb[3]);
                mma16816(o[2*nn],   pla, vb[0], vb[1]);
                mma16816(o[2*nn+1], pla, vb[2], vb[3]);
                ldsm4t(vb, bVl + kk * (16 * FS) + nn * 32);
                mma16816(o[2*nn],   pha, vb[0], vb[1]);
                mma16816(o[2*nn+1], pha, vb[2], vb[3]);
            }
        }
    }

    // Epilogue: normalize + fp16 hi/lo split straight into g_ah/g_al.
    const int b = bh >> 4, h = bh & 15;
    const int r1 = q0 + wid * 16 + (lane >> 2);
    const float inv1 = 1.0f / l1, inv2 = 1.0f / l2;
    size_t base1 = (size_t)(b * SEQ + r1) * DMODEL + h * DHEAD + (lane & 3) * 2;
    size_t base2 = base1 + (size_t)8 * DMODEL;
#pragma unroll
    for (int j = 0; j < 16; ++j) {
        float a0 = o[j][0] * inv1, a1 = o[j][1] * inv1;
        __half2 hh = __float22half2_rn(make_float2(a0, a1));
        float2 bk = __half22float2(hh);
        __half2 ll = __float22half2_rn(make_float2(a0 - bk.x, a1 - bk.y));
        *(uint32_t*)&g_ah[base1 + j * 8] = *(uint32_t*)&hh;
        *(uint32_t*)&g_al[base1 + j * 8] = *(uint32_t*)&ll;
        float a2 = o[j][2] * inv2, a3 = o[j][3] * inv2;
        __half2 hh2 = __float22half2_rn(make_float2(a2, a3));
        float2 bk2 = __half22float2(hh2);
        __half2 ll2 = __float22half2_rn(make_float2(a2 - bk2.x, a3 - bk2.y));
        *(uint32_t*)&g_ah[base2 + j * 8] = *(uint32_t*)&hh2;
        *(uint32_t*)&g_al[base2 + j * 8] = *(uint32_t*)&ll2;
    }
}

// ---------------------------------------------------------------------------
extern "C" void kernel_launch(void* const* d_in, const int* in_sizes, int n_in,
                              void* d_out, int out_size) {
    (void)in_sizes; (void)n_in; (void)out_size;
    const float* qin = (const float*)d_in[0];
    const float* kin = (const float*)d_in[1];
    const float* vin = (const float*)d_in[2];
    const float* WQ  = (const float*)d_in[3];
    const float* WK  = (const float*)d_in[4];
    const float* WV  = (const float*)d_in[5];
    const float* WO  = (const float*)d_in[6];
    const float* bQ  = (const float*)d_in[7];
    const float* bK  = (const float*)d_in[8];
    const float* bV  = (const float*)d_in[9];
    const float* bO  = (const float*)d_in[10];
    float* out = (float*)d_out;

    float *pq, *pk;
    __half *ah, *al, *wq, *wk, *wv, *wo;
    __nv_bfloat16 *vh, *vl;
    cudaGetSymbolAddress((void**)&pq, g_q);
    cudaGetSymbolAddress((void**)&pk, g_k);
    cudaGetSymbolAddress((void**)&ah, g_ah);
    cudaGetSymbolAddress((void**)&al, g_al);
    cudaGetSymbolAddress((void**)&wq, g_wq);
    cudaGetSymbolAddress((void**)&wk, g_wk);
    cudaGetSymbolAddress((void**)&wv, g_wv);
    cudaGetSymbolAddress((void**)&wo, g_wo);
    cudaGetSymbolAddress((void**)&vh, g_vh);
    cudaGetSymbolAddress((void**)&vl, g_vl);

    cudaFuncSetAttribute((const void*)gemm_hmma,
                         cudaFuncAttributeMaxDynamicSharedMemorySize, GEMM_SMEM);
    cudaFuncSetAttribute((const void*)flash_hmma,
                         cudaFuncAttributeMaxDynamicSharedMemorySize, FLASH_SMEM);

    dim3 tb(32, 8);
    dim3 ggrid(DMODEL / 128, MROWS / 128);   // (16, 32)
    const int nsplit = (MROWS * DMODEL) / (256 * 4);

    // ncu (-s 5) captures launch #6 -> the Q-projection GEMM.
    transpose_half_kernel<<<dim3(4, 64, 16), tb>>>(WQ, wq, DMODEL, DHEAD);   // 1
    transpose_half_kernel<<<dim3(4, 64, 16), tb>>>(WK, wk, DMODEL, DHEAD);   // 2
    transpose_half_kernel<<<dim3(4, 64, 16), tb>>>(WV, wv, DMODEL, DHEAD);   // 3
    transpose_half_kernel<<<dim3(64, 64, 1), tb>>>(WO, wo, DMODEL, DMODEL);  // 4
    split_kernel<<<nsplit, 256>>>(qin, ah, al);                              // 5
    gemm_hmma<<<ggrid, 128, GEMM_SMEM>>>(ah, al, wq, bQ, pq, 0, 0, 0);       // 6 <- ncu
    split_kernel<<<nsplit, 256>>>(kin, ah, al);                              // 7
    gemm_hmma<<<ggrid, 128, GEMM_SMEM>>>(ah, al, wk, bK, pk, 0, 0, 0);       // 8
    split_kernel<<<nsplit, 256>>>(vin, ah, al);                              // 9
    gemm_hmma<<<ggrid, 128, GEMM_SMEM>>>(ah, al, wv, bV, 0, vh, vl, 2);      // 10
    rope_table_kernel<<<SEQ, 64>>>();                                        // 11
    rope_split_kernel<<<(BHN * SEQ * 64) / 256, 256>>>();                    // 12
    flash_hmma<<<dim3(SEQ / 128, BHN), 256, FLASH_SMEM>>>();                 // 13
    gemm_hmma<<<ggrid, 128, GEMM_SMEM>>>(ah, al, wo, bO, out, 0, 0, 1);      // 14
}

// round 10
// speedup vs baseline: 1.8082x; 1.0964x over previous
#include <cuda_runtime.h>
#include <cuda_bf16.h>
#include <cuda_fp16.h>
#include <math.h>
#include <stdint.h>

#define DMODEL 2048
#define NHEADS 16
#define DHEAD  128
#define SEQ    2048
#define BATCH  2
#define BHN    (BATCH*NHEADS)   // 32
#define MROWS  (BATCH*SEQ)      // 4096

// log2(e) / sqrt(128)
#define QSCALE (1.4426950408889634f * 0.08838834764831845f)

// ---- fp16 2-pass GEMM: CTA 128x128, KBLK 64, 4 warps (64x64), 128 thr ----
#define PADK 72                       // fp16 per smem row (144 B)
#define TILE_BYTES (128 * PADK * 2)   // 18432
#define OFF_AH 0
#define OFF_AL (TILE_BYTES)
#define OFF_BH (2*TILE_BYTES)
#define GEMM_SMEM (3*TILE_BYTES)      // 55296 B (2 CTAs/SM)

// ---- fp16 2-pass flash: 128 q x 128 kv, 5 tiles, stride 272 B ----
#define FS   272
#define FT   (128 * FS)
#define FQH  0
#define FQL  (FT)
#define FKH  (2*FT)
#define FVH  (3*FT)
#define FVL  (4*FT)
#define FLASH_SMEM (5*FT)          // 174080 B

// ---------------- scratch (device globals; allocation-free) ----------------
__device__ float  g_q[(size_t)BHN * SEQ * DHEAD];
__device__ float  g_k[(size_t)BHN * SEQ * DHEAD];
__device__ float2 g_rope[SEQ * 64];

__device__ __half g_ah[(size_t)MROWS * DMODEL];
__device__ __half g_al[(size_t)MROWS * DMODEL];
__device__ __half g_wq[(size_t)DMODEL * DMODEL];
__device__ __half g_wk[(size_t)DMODEL * DMODEL];
__device__ __half g_wv[(size_t)DMODEL * DMODEL];
__device__ __half g_wo[(size_t)DMODEL * DMODEL];

__device__ __half g_qh[(size_t)BHN * SEQ * DHEAD];
__device__ __half g_ql[(size_t)BHN * SEQ * DHEAD];
__device__ __half g_kh[(size_t)BHN * SEQ * DHEAD];
__device__ __half g_vh[(size_t)BHN * SEQ * DHEAD];
__device__ __half g_vl[(size_t)BHN * SEQ * DHEAD];

// ---------------- helpers ----------------
__device__ __forceinline__ void ldsm4(uint32_t* r, uint32_t addr) {
    asm volatile("ldmatrix.sync.aligned.m8n8.x4.shared.b16 {%0,%1,%2,%3}, [%4];"
                 : "=r"(r[0]), "=r"(r[1]), "=r"(r[2]), "=r"(r[3]) : "r"(addr));
}
__device__ __forceinline__ void ldsm4t(uint32_t* r, uint32_t addr) {
    asm volatile("ldmatrix.sync.aligned.m8n8.x4.trans.shared.b16 {%0,%1,%2,%3}, [%4];"
                 : "=r"(r[0]), "=r"(r[1]), "=r"(r[2]), "=r"(r[3]) : "r"(addr));
}
// fp16 mma
__device__ __forceinline__ void mma16816h(float* d, const uint32_t* a,
                                          uint32_t b0, uint32_t b1) {
    asm volatile(
        "mma.sync.aligned.m16n8k16.row.col.f32.f16.f16.f32 "
        "{%0,%1,%2,%3}, {%4,%5,%6,%7}, {%8,%9}, {%0,%1,%2,%3};"
        : "+f"(d[0]), "+f"(d[1]), "+f"(d[2]), "+f"(d[3])
        : "r"(a[0]), "r"(a[1]), "r"(a[2]), "r"(a[3]), "r"(b0), "r"(b1));
}
__device__ __forceinline__ float ex2(float x) {
    float y; asm("ex2.approx.f32 %0, %1;" : "=f"(y) : "f"(x)); return y;
}
__device__ __forceinline__ uint32_t packhf(float lo, float hi) {
    uint32_t r; asm("cvt.rn.f16x2.f32 %0, %1, %2;" : "=r"(r) : "f"(hi), "f"(lo));
    return r;
}
__device__ __forceinline__ void cpasync16(uint32_t s, const void* g) {
    asm volatile("cp.async.cg.shared.global [%0], [%1], 16;" :: "r"(s), "l"(g));
}

// ---------------------------------------------------------------------------
// RoPE table (fp32 angle, fp64 sin/cos)
// ---------------------------------------------------------------------------
__global__ void rope_table_kernel() {
    int p = blockIdx.x;
    int i = threadIdx.x;  // 0..63
    float freq = (float)pow(10000.0, (double)i / 64.0);
    float ang  = (float)p / freq;
    double s, c;
    sincos((double)ang, &s, &c);
    g_rope[p * 64 + i] = make_float2((float)s, (float)c);
}

// ---------------------------------------------------------------------------
// Rope + fp16 split: q -> hi/lo (QSCALE folded); k -> hi only.
// ---------------------------------------------------------------------------
__global__ void rope_split_kernel() {
    int gid = blockIdx.x * 256 + threadIdx.x;
    int i    = gid & 63;
    int rest = gid >> 6;
    int p    = rest & 2047;
    int bh   = rest >> 11;
    float2 sc = g_rope[p * 64 + i];
    size_t base = ((size_t)bh * SEQ + p) * DHEAD;

    float x0 = g_q[base + i], x1 = g_q[base + 64 + i];
    float q0 = (x0 * sc.y - x1 * sc.x) * QSCALE;
    float q1 = (x1 * sc.y + x0 * sc.x) * QSCALE;
    float y0 = g_k[base + i], y1 = g_k[base + 64 + i];
    float k0 = y0 * sc.y - y1 * sc.x;
    float k1 = y1 * sc.y + y0 * sc.x;

    __half h;
    h = __float2half_rn(q0); g_qh[base + i]      = h; g_ql[base + i]      = __float2half_rn(q0 - __half2float(h));
    h = __float2half_rn(q1); g_qh[base + 64 + i] = h; g_ql[base + 64 + i] = __float2half_rn(q1 - __half2float(h));
    g_kh[base + i]      = __float2half_rn(k0);
    g_kh[base + 64 + i] = __float2half_rn(k1);
}

// ---------------------------------------------------------------------------
// fp32 -> (fp16 hi, fp16 lo) split, elementwise (activations).
// ---------------------------------------------------------------------------
__global__ void split_kernel(const float* __restrict__ x,
                             __half* __restrict__ hi,
                             __half* __restrict__ lo) {
    size_t i = ((size_t)blockIdx.x * 256 + threadIdx.x) * 4;
    float4 v = *(const float4*)(x + i);
    float a[4] = {v.x, v.y, v.z, v.w};
    uint32_t ph[2], pl[2];
#pragma unroll
    for (int j = 0; j < 2; ++j) {
        __half2 h2 = __float22half2_rn(make_float2(a[2*j], a[2*j+1]));
        float2 bk = __half22float2(h2);
        __half2 l2 = __float22half2_rn(make_float2(a[2*j] - bk.x, a[2*j+1] - bk.y));
        ph[j] = *(uint32_t*)&h2;
        pl[j] = *(uint32_t*)&l2;
    }
    *(uint2*)((char*)hi + i * 2) = make_uint2(ph[0], ph[1]);
    *(uint2*)((char*)lo + i * 2) = make_uint2(pl[0], pl[1]);
}

// ---------------------------------------------------------------------------
// Transpose + fp16 round: src [H][R][C] fp32 -> dst[h*C + c][r] fp16.
// ---------------------------------------------------------------------------
__global__ void transpose_half_kernel(const float* __restrict__ src,
                                      __half* __restrict__ dst,
                                      int R, int C) {
    __shared__ float t[32][33];
    int h  = blockIdx.z;
    int r0 = blockIdx.y << 5, c0 = blockIdx.x << 5;
    int tx = threadIdx.x, ty = threadIdx.y;  // 32 x 8
    const float* s = src + (size_t)h * R * C;
#pragma unroll
    for (int j = 0; j < 4; ++j)
        t[ty + 8 * j][tx] = s[(size_t)(r0 + ty + 8 * j) * C + c0 + tx];
    __syncthreads();
#pragma unroll
    for (int j = 0; j < 4; ++j) {
        int c = c0 + ty + 8 * j;
        dst[(size_t)(h * C + c) * R + r0 + tx] = __float2half_rn(t[tx][ty + 8 * j]);
    }
}

// ---------------------------------------------------------------------------
// fp16 2-pass GEMM: out = A * B^T + bias;  D = Ah*Bh + Al*Bh.
// CTA 128x128, KBLK 64, 4 warps (64x64), 128 threads, 2 CTAs/SM.
// mode 0: fp32 out -> [b][h][p][e]; mode 1: fp32 row-major;
// mode 2: fp16 hi/lo split -> outh/outl at [b][h][p][e]  (V path, for flash).
// ---------------------------------------------------------------------------
__global__ __launch_bounds__(128, 2) void gemm_hmma(
    const __half* __restrict__ Ah,
    const __half* __restrict__ Al,
    const __half* __restrict__ Bh,
    const float* __restrict__ bias,
    float* __restrict__ out,
    __half* __restrict__ outh,
    __half* __restrict__ outl,
    int mode)
{
    extern __shared__ char sm[];
    const uint32_t sb = (uint32_t)__cvta_generic_to_shared(sm);

    const int tid  = threadIdx.x;
    const int wid  = tid >> 5;
    const int lane = tid & 31;
    const int row0 = blockIdx.y * 128;
    const int n0   = blockIdx.x * 128;
    const int m_w  = (wid & 1) * 64;
    const int n_w  = (wid >> 1) * 64;

    const uint32_t aOff = (uint32_t)(m_w + (lane & 15)) * 144 + ((lane >> 4) << 4);
    const uint32_t bOff = (uint32_t)(n_w + ((lane >> 4) << 3) + (lane & 7)) * 144 +
                          (uint32_t)((lane & 8) << 1);
    const uint32_t aHi = sb + OFF_AH + aOff;
    const uint32_t aLo = sb + OFF_AL + aOff;
    const uint32_t bHi = sb + OFF_BH + bOff;

    float acc[4][8][4];
#pragma unroll
    for (int i = 0; i < 4; ++i)
#pragma unroll
        for (int j = 0; j < 8; ++j)
#pragma unroll
            for (int r = 0; r < 4; ++r) acc[i][j][r] = 0.0f;

    const int lr  = tid >> 3;          // 0..15 (+16 per i)
    const int lc8 = (tid & 7) * 8;     // 0..56

    for (int it = 0; it < DMODEL / 64; ++it) {
        const int k0 = it * 64;
        __syncthreads();
#pragma unroll
        for (int i = 0; i < 8; ++i) {
            int r = lr + i * 16;
            size_t ga = (size_t)(row0 + r) * DMODEL + k0 + lc8;
            size_t gb = (size_t)(n0 + r) * DMODEL + k0 + lc8;
            uint32_t so = (uint32_t)(r * 144 + lc8 * 2);
            *(float4*)(sm + OFF_AH + so) = *(const float4*)(Ah + ga);
            *(float4*)(sm + OFF_AL + so) = *(const float4*)(Al + ga);
            *(float4*)(sm + OFF_BH + so) = *(const float4*)(Bh + gb);
        }
        __syncthreads();

#pragma unroll
        for (int kk = 0; kk < 4; ++kk) {
            uint32_t Af[4][4], Bf[4][4];
            // pass 1: Ah * Bh
#pragma unroll
            for (int mi = 0; mi < 4; ++mi)
                ldsm4(Af[mi], aHi + mi * (16 * 144) + kk * 32);
#pragma unroll
            for (int ni = 0; ni < 4; ++ni)
                ldsm4(Bf[ni], bHi + ni * (16 * 144) + kk * 32);
#pragma unroll
            for (int mi = 0; mi < 4; ++mi)
#pragma unroll
                for (int j = 0; j < 8; ++j)
                    mma16816h(acc[mi][j], Af[mi], Bf[j >> 1][(j & 1) * 2],
                              Bf[j >> 1][(j & 1) * 2 + 1]);
            // pass 2: Al * Bh (reuse Bf)
#pragma unroll
            for (int mi = 0; mi < 4; ++mi) {
                uint32_t Al4[4];
                ldsm4(Al4, aLo + mi * (16 * 144) + kk * 32);
#pragma unroll
                for (int j = 0; j < 8; ++j)
                    mma16816h(acc[mi][j], Al4, Bf[j >> 1][(j & 1) * 2],
                              Bf[j >> 1][(j & 1) * 2 + 1]);
            }
        }
    }

    // Epilogue
    const int g = lane >> 2, t4 = lane & 3;
#pragma unroll
    for (int mi = 0; mi < 4; ++mi) {
        int m = row0 + m_w + mi * 16 + g;
#pragma unroll
        for (int j = 0; j < 8; ++j) {
            int col = n0 + n_w + j * 8 + t4 * 2;
            float b0 = bias[col], b1 = bias[col + 1];
            float2 v0 = make_float2(acc[mi][j][0] + b0, acc[mi][j][1] + b1);
            float2 v1 = make_float2(acc[mi][j][2] + b0, acc[mi][j][3] + b1);
            if (mode == 1) {
                *(float2*)(out + (size_t)m * DMODEL + col)       = v0;
                *(float2*)(out + (size_t)(m + 8) * DMODEL + col) = v1;
            } else {
                int h = col >> 7, e = col & 127;
                int b  = m >> 11, p = m & 2047;
                size_t base = (((size_t)(b * NHEADS + h) * SEQ) << 7) + e;
                size_t i0 = base + ((size_t)p << 7);
                size_t i1 = base + ((size_t)(p + 8) << 7);
                if (mode == 0) {
                    *(float2*)(out + i0) = v0;
                    *(float2*)(out + i1) = v1;
                } else {  // mode 2: fp16 hi/lo split (V path)
                    uint32_t h0 = packhf(v0.x, v0.y);
                    __half2 h0h = *(__half2*)&h0;
                    float2 bk0 = __half22float2(h0h);
                    uint32_t l0 = packhf(v0.x - bk0.x, v0.y - bk0.y);
                    uint32_t h1 = packhf(v1.x, v1.y);
                    __half2 h1h = *(__half2*)&h1;
                    float2 bk1 = __half22float2(h1h);
                    uint32_t l1 = packhf(v1.x - bk1.x, v1.y - bk1.y);
                    *(uint32_t*)(outh + i0) = h0;
                    *(uint32_t*)(outl + i0) = l0;
                    *(uint32_t*)(outh + i1) = h1;
                    *(uint32_t*)(outl + i1) = l1;
                }
            }
        }
    }
}

// ---------------------------------------------------------------------------
// fp16 2-pass causal flash attention. CTA = 128 q x 128 kv, 8 warps x 16 rows.
// S = Qh*Kh + Ql*Kh (K rounded);  O += Ph*Vh + Ph*Vl (P rounded, V exact).
// V tiles via cp.async overlapped with the S-phase MMAs.
// Epilogue writes z as fp16 hi/lo into g_ah/g_al (O-proj input).
// ---------------------------------------------------------------------------
__global__ __launch_bounds__(256, 1) void flash_hmma() {
    extern __shared__ char sm[];
    const uint32_t sb = (uint32_t)__cvta_generic_to_shared(sm);

    const int tid  = threadIdx.x;
    const int wid  = tid >> 5;
    const int lane = tid & 31;
    const int bh   = blockIdx.y;
    const int qt   = gridDim.x - 1 - blockIdx.x;   // heavy tiles first
    const int q0   = qt * 128;

    const __half* qh = g_qh + (size_t)bh * SEQ * DHEAD;
    const __half* ql = g_ql + (size_t)bh * SEQ * DHEAD;
    const __half* kh = g_kh + (size_t)bh * SEQ * DHEAD;
    const __half* vh = g_vh + (size_t)bh * SEQ * DHEAD;
    const __half* vl = g_vl + (size_t)bh * SEQ * DHEAD;

#pragma unroll
    for (int i = 0; i < 8; ++i) {
        int f = tid + i * 256;
        int r = f >> 4, c8 = (f & 15) * 8;
        uint32_t off = (uint32_t)(r * FS + c8 * 2);
        size_t g = (size_t)(q0 + r) * DHEAD + c8;
        *(uint4*)(sm + FQH + off) = *(const uint4*)(qh + g);
        *(uint4*)(sm + FQL + off) = *(const uint4*)(ql + g);
    }

    const uint32_t aOff = (uint32_t)(wid * 16 + (lane & 15)) * FS + ((lane >> 4) << 4);
    const uint32_t aQh = sb + FQH + aOff;
    const uint32_t aQl = sb + FQL + aOff;
    const uint32_t bOff = (uint32_t)(((lane >> 4) << 3) + (lane & 7)) * FS +
                          (uint32_t)((lane & 8) << 1);
    const uint32_t bKh = sb + FKH + bOff;
    const uint32_t vOff = (uint32_t)(lane & 15) * FS + ((lane >> 4) << 4);
    const uint32_t bVh = sb + FVH + vOff;
    const uint32_t bVl = sb + FVL + vOff;

    float o[16][4];
#pragma unroll
    for (int j = 0; j < 16; ++j)
#pragma unroll
        for (int r = 0; r < 4; ++r) o[j][r] = 0.0f;
    float m1 = -1e30f, m2 = -1e30f, l1 = 0.0f, l2 = 0.0f;

    for (int t = 0; t <= qt; ++t) {
        const int k0 = t * 128;
        __syncthreads();
        // K: direct ld/st (needed now). V hi/lo: cp.async, overlapped with S.
#pragma unroll
        for (int i = 0; i < 8; ++i) {
            int f = tid + i * 256;
            int r = f >> 4, c8 = (f & 15) * 8;
            uint32_t off = (uint32_t)(r * FS + c8 * 2);
            size_t g = (size_t)(k0 + r) * DHEAD + c8;
            *(uint4*)(sm + FKH + off) = *(const uint4*)(kh + g);
            cpasync16(sb + FVH + off, vh + g);
            cpasync16(sb + FVL + off, vl + g);
        }
        asm volatile("cp.async.commit_group;" ::: "memory");
        __syncthreads();   // K visible

        float s[16][4];
#pragma unroll
        for (int j = 0; j < 16; ++j)
#pragma unroll
            for (int r = 0; r < 4; ++r) s[j][r] = 0.0f;

#pragma unroll
        for (int kk = 0; kk < 8; ++kk) {
            uint32_t qa[4], qb[4], kb[4];
            ldsm4(qa, aQh + kk * 32);
            ldsm4(qb, aQl + kk * 32);
#pragma unroll
            for (int nn = 0; nn < 8; ++nn) {
                ldsm4(kb, bKh + nn * (16 * FS) + kk * 32);
                mma16816h(s[2*nn],   qa, kb[0], kb[1]);
                mma16816h(s[2*nn+1], qa, kb[2], kb[3]);
                mma16816h(s[2*nn],   qb, kb[0], kb[1]);
                mma16816h(s[2*nn+1], qb, kb[2], kb[3]);
            }
        }

        const int r1 = q0 + wid * 16 + (lane >> 2);
        const int r2 = r1 + 8;
        if (t == qt) {
            const int c0 = k0 + (lane & 3) * 2;
#pragma unroll
            for (int j = 0; j < 16; ++j) {
                int col = c0 + j * 8;
                if (col     > r1) s[j][0] = -1e30f;
                if (col + 1 > r1) s[j][1] = -1e30f;
                if (col     > r2) s[j][2] = -1e30f;
                if (col + 1 > r2) s[j][3] = -1e30f;
            }
        }

        float mx1 = -1e30f, mx2 = -1e30f;
#pragma unroll
        for (int j = 0; j < 16; ++j) {
            mx1 = fmaxf(mx1, fmaxf(s[j][0], s[j][1]));
            mx2 = fmaxf(mx2, fmaxf(s[j][2], s[j][3]));
        }
        mx1 = fmaxf(mx1, __shfl_xor_sync(0xffffffffu, mx1, 1));
        mx1 = fmaxf(mx1, __shfl_xor_sync(0xffffffffu, mx1, 2));
        mx2 = fmaxf(mx2, __shfl_xor_sync(0xffffffffu, mx2, 1));
        mx2 = fmaxf(mx2, __shfl_xor_sync(0xffffffffu, mx2, 2));
        float mn1 = fmaxf(m1, mx1), mn2 = fmaxf(m2, mx2);
        float sc1 = ex2(m1 - mn1), sc2 = ex2(m2 - mn2);
        float rs1 = 0.0f, rs2 = 0.0f;
#pragma unroll
        for (int j = 0; j < 16; ++j) {
            s[j][0] = ex2(s[j][0] - mn1);
            s[j][1] = ex2(s[j][1] - mn1);
            s[j][2] = ex2(s[j][2] - mn2);
            s[j][3] = ex2(s[j][3] - mn2);
            rs1 += s[j][0] + s[j][1];
            rs2 += s[j][2] + s[j][3];
        }
        rs1 += __shfl_xor_sync(0xffffffffu, rs1, 1);
        rs1 += __shfl_xor_sync(0xffffffffu, rs1, 2);
        rs2 += __shfl_xor_sync(0xffffffffu, rs2, 1);
        rs2 += __shfl_xor_sync(0xffffffffu, rs2, 2);
        l1 = l1 * sc1 + rs1;  m1 = mn1;
        l2 = l2 * sc2 + rs2;  m2 = mn2;
#pragma unroll
        for (int j = 0; j < 16; ++j) {
            o[j][0] *= sc1; o[j][1] *= sc1;
            o[j][2] *= sc2; o[j][3] *= sc2;
        }

        asm volatile("cp.async.wait_group 0;" ::: "memory");
        __syncthreads();   // V visible

        // O += P V : P rounded to fp16 (single), V exact (hi+lo)
#pragma unroll
        for (int kk = 0; kk < 8; ++kk) {
            uint32_t pha[4], vb[4];
            pha[0] = packhf(s[2*kk][0],   s[2*kk][1]);
            pha[1] = packhf(s[2*kk][2],   s[2*kk][3]);
            pha[2] = packhf(s[2*kk+1][0], s[2*kk+1][1]);
            pha[3] = packhf(s[2*kk+1][2], s[2*kk+1][3]);
#pragma unroll
            for (int nn = 0; nn < 8; ++nn) {
                ldsm4t(vb, bVh + kk * (16 * FS) + nn * 32);
                mma16816h(o[2*nn],   pha, vb[0], vb[1]);
                mma16816h(o[2*nn+1], pha, vb[2], vb[3]);
                ldsm4t(vb, bVl + kk * (16 * FS) + nn * 32);
                mma16816h(o[2*nn],   pha, vb[0], vb[1]);
                mma16816h(o[2*nn+1], pha, vb[2], vb[3]);
            }
        }
    }

    // Epilogue: normalize + fp16 hi/lo split straight into g_ah/g_al.
    const int b = bh >> 4, h = bh & 15;
    const int r1 = q0 + wid * 16 + (lane >> 2);
    const float inv1 = 1.0f / l1, inv2 = 1.0f / l2;
    size_t base1 = (size_t)(b * SEQ + r1) * DMODEL + h * DHEAD + (lane & 3) * 2;
    size_t base2 = base1 + (size_t)8 * DMODEL;
#pragma unroll
    for (int j = 0; j < 16; ++j) {
        float a0 = o[j][0] * inv1, a1 = o[j][1] * inv1;
        __half2 hh = __float22half2_rn(make_float2(a0, a1));
        float2 bk = __half22float2(hh);
        __half2 ll = __float22half2_rn(make_float2(a0 - bk.x, a1 - bk.y));
        *(uint32_t*)&g_ah[base1 + j * 8] = *(uint32_t*)&hh;
        *(uint32_t*)&g_al[base1 + j * 8] = *(uint32_t*)&ll;
        float a2 = o[j][2] * inv2, a3 = o[j][3] * inv2;
        __half2 hh2 = __float22half2_rn(make_float2(a2, a3));
        float2 bk2 = __half22float2(hh2);
        __half2 ll2 = __float22half2_rn(make_float2(a2 - bk2.x, a3 - bk2.y));
        *(uint32_t*)&g_ah[base2 + j * 8] = *(uint32_t*)&hh2;
        *(uint32_t*)&g_al[base2 + j * 8] = *(uint32_t*)&ll2;
    }
}

// ---------------------------------------------------------------------------
extern "C" void kernel_launch(void* const* d_in, const int* in_sizes, int n_in,
                              void* d_out, int out_size) {
    (void)in_sizes; (void)n_in; (void)out_size;
    const float* qin = (const float*)d_in[0];
    const float* kin = (const float*)d_in[1];
    const float* vin = (const float*)d_in[2];
    const float* WQ  = (const float*)d_in[3];
    const float* WK  = (const float*)d_in[4];
    const float* WV  = (const float*)d_in[5];
    const float* WO  = (const float*)d_in[6];
    const float* bQ  = (const float*)d_in[7];
    const float* bK  = (const float*)d_in[8];
    const float* bV  = (const float*)d_in[9];
    const float* bO  = (const float*)d_in[10];
    float* out = (float*)d_out;

    float *pq, *pk;
    __half *ah, *al, *wq, *wk, *wv, *wo, *vh, *vl;
    cudaGetSymbolAddress((void**)&pq, g_q);
    cudaGetSymbolAddress((void**)&pk, g_k);
    cudaGetSymbolAddress((void**)&ah, g_ah);
    cudaGetSymbolAddress((void**)&al, g_al);
    cudaGetSymbolAddress((void**)&wq, g_wq);
    cudaGetSymbolAddress((void**)&wk, g_wk);
    cudaGetSymbolAddress((void**)&wv, g_wv);
    cudaGetSymbolAddress((void**)&wo, g_wo);
    cudaGetSymbolAddress((void**)&vh, g_vh);
    cudaGetSymbolAddress((void**)&vl, g_vl);

    cudaFuncSetAttribute((const void*)gemm_hmma,
                         cudaFuncAttributeMaxDynamicSharedMemorySize, GEMM_SMEM);
    cudaFuncSetAttribute((const void*)flash_hmma,
                         cudaFuncAttributeMaxDynamicSharedMemorySize, FLASH_SMEM);

    dim3 tb(32, 8);
    dim3 ggrid(DMODEL / 128, MROWS / 128);   // (16, 32)
    const int nsplit = (MROWS * DMODEL) / (256 * 4);

    // ncu (-s 5) captures launch #6 -> the Q-projection GEMM.
    transpose_half_kernel<<<dim3(4, 64, 16), tb>>>(WQ, wq, DMODEL, DHEAD);   // 1
    transpose_half_kernel<<<dim3(4, 64, 16), tb>>>(WK, wk, DMODEL, DHEAD);   // 2
    transpose_half_kernel<<<dim3(4, 64, 16), tb>>>(WV, wv, DMODEL, DHEAD);   // 3
    transpose_half_kernel<<<dim3(64, 64, 1), tb>>>(WO, wo, DMODEL, DMODEL);  // 4
    split_kernel<<<nsplit, 256>>>(qin, ah, al);                              // 5
    gemm_hmma<<<ggrid, 128, GEMM_SMEM>>>(ah, al, wq, bQ, pq, 0, 0, 0);       // 6 <- ncu
    split_kernel<<<nsplit, 256>>>(kin, ah, al);                              // 7
    gemm_hmma<<<ggrid, 128, GEMM_SMEM>>>(ah, al, wk, bK, pk, 0, 0, 0);       // 8
    split_kernel<<<nsplit, 256>>>(vin, ah, al);                              // 9
    gemm_hmma<<<ggrid, 128, GEMM_SMEM>>>(ah, al, wv, bV, 0, vh, vl, 2);      // 10
    rope_table_kernel<<<SEQ, 64>>>();                                        // 11
    rope_split_kernel<<<(BHN * SEQ * 64) / 256, 256>>>();                    // 12
    flash_hmma<<<dim3(SEQ / 128, BHN), 256, FLASH_SMEM>>>();                 // 13
    gemm_hmma<<<ggrid, 128, GEMM_SMEM>>>(ah, al, wo, bO, out, 0, 0, 1);      // 14
}

// round 11
// speedup vs baseline: 1.9755x; 1.0925x over previous
#include <cuda_runtime.h>
#include <cuda_fp16.h>
#include <math.h>
#include <stdint.h>

#define DMODEL 2048
#define NHEADS 16
#define DHEAD  128
#define SEQ    2048
#define BATCH  2
#define BHN    (BATCH*NHEADS)   // 32
#define MROWS  (BATCH*SEQ)      // 4096

// log2(e) / sqrt(128)
#define QSCALE (1.4426950408889634f * 0.08838834764831845f)

// ---- fp16 2-pass GEMM: CTA 128x128, KBLK 64, 4 warps (64x64), 128 thr ----
#define PADK 72                       // fp16 per smem row (144 B)
#define TILE_BYTES (128 * PADK * 2)   // 18432
#define OFF_AH 0
#define OFF_AL (TILE_BYTES)
#define OFF_BH (2*TILE_BYTES)
#define GEMM_SMEM (3*TILE_BYTES)      // 55296 B (2 CTAs/SM)

// ---- fp16 flash: 128 q x 128 kv, 4 tiles (Qh,Ql,Kh,Vh), stride 272 B ----
#define FS   272
#define FT   (128 * FS)
#define FQH  0
#define FQL  (FT)
#define FKH  (2*FT)
#define FVH  (3*FT)
#define FLASH_SMEM (4*FT)          // 139264 B

// ---------------- scratch (device globals; allocation-free) ----------------
__device__ float  g_q[(size_t)BHN * SEQ * DHEAD];   // Q proj out, later reused as z
__device__ float  g_k[(size_t)BHN * SEQ * DHEAD];
__device__ float2 g_rope[SEQ * 64];

__device__ __half g_wq[(size_t)DMODEL * DMODEL];
__device__ __half g_wk[(size_t)DMODEL * DMODEL];
__device__ __half g_wv[(size_t)DMODEL * DMODEL];
__device__ __half g_wo[(size_t)DMODEL * DMODEL];

__device__ __half g_qh[(size_t)BHN * SEQ * DHEAD];
__device__ __half g_ql[(size_t)BHN * SEQ * DHEAD];
__device__ __half g_kh[(size_t)BHN * SEQ * DHEAD];
__device__ __half g_vh[(size_t)BHN * SEQ * DHEAD];

// ---------------- helpers ----------------
__device__ __forceinline__ void ldsm4(uint32_t* r, uint32_t addr) {
    asm volatile("ldmatrix.sync.aligned.m8n8.x4.shared.b16 {%0,%1,%2,%3}, [%4];"
                 : "=r"(r[0]), "=r"(r[1]), "=r"(r[2]), "=r"(r[3]) : "r"(addr));
}
__device__ __forceinline__ void ldsm4t(uint32_t* r, uint32_t addr) {
    asm volatile("ldmatrix.sync.aligned.m8n8.x4.trans.shared.b16 {%0,%1,%2,%3}, [%4];"
                 : "=r"(r[0]), "=r"(r[1]), "=r"(r[2]), "=r"(r[3]) : "r"(addr));
}
__device__ __forceinline__ void mma16816h(float* d, const uint32_t* a,
                                          uint32_t b0, uint32_t b1) {
    asm volatile(
        "mma.sync.aligned.m16n8k16.row.col.f32.f16.f16.f32 "
        "{%0,%1,%2,%3}, {%4,%5,%6,%7}, {%8,%9}, {%0,%1,%2,%3};"
        : "+f"(d[0]), "+f"(d[1]), "+f"(d[2]), "+f"(d[3])
        : "r"(a[0]), "r"(a[1]), "r"(a[2]), "r"(a[3]), "r"(b0), "r"(b1));
}
__device__ __forceinline__ float ex2(float x) {
    float y; asm("ex2.approx.f32 %0, %1;" : "=f"(y) : "f"(x)); return y;
}
__device__ __forceinline__ uint32_t packhf(float lo, float hi) {
    uint32_t r; asm("cvt.rn.f16x2.f32 %0, %1, %2;" : "=r"(r) : "f"(hi), "f"(lo));
    return r;
}
__device__ __forceinline__ void cpasync16(uint32_t s, const void* g) {
    asm volatile("cp.async.cg.shared.global [%0], [%1], 16;" :: "r"(s), "l"(g));
}

// ---------------------------------------------------------------------------
// RoPE table (fp32 angle, fp64 sin/cos)
// ---------------------------------------------------------------------------
__global__ void rope_table_kernel() {
    int p = blockIdx.x;
    int i = threadIdx.x;  // 0..63
    float freq = (float)pow(10000.0, (double)i / 64.0);
    float ang  = (float)p / freq;
    double s, c;
    sincos((double)ang, &s, &c);
    g_rope[p * 64 + i] = make_float2((float)s, (float)c);
}

// ---------------------------------------------------------------------------
// Rope + fp16 split: q -> hi/lo (QSCALE folded); k -> hi only.
// ---------------------------------------------------------------------------
__global__ void rope_split_kernel() {
    int gid = blockIdx.x * 256 + threadIdx.x;
    int i    = gid & 63;
    int rest = gid >> 6;
    int p    = rest & 2047;
    int bh   = rest >> 11;
    float2 sc = g_rope[p * 64 + i];
    size_t base = ((size_t)bh * SEQ + p) * DHEAD;

    float x0 = g_q[base + i], x1 = g_q[base + 64 + i];
    float q0 = (x0 * sc.y - x1 * sc.x) * QSCALE;
    float q1 = (x1 * sc.y + x0 * sc.x) * QSCALE;
    float y0 = g_k[base + i], y1 = g_k[base + 64 + i];
    float k0 = y0 * sc.y - y1 * sc.x;
    float k1 = y1 * sc.y + y0 * sc.x;

    __half h;
    h = __float2half_rn(q0); g_qh[base + i]      = h; g_ql[base + i]      = __float2half_rn(q0 - __half2float(h));
    h = __float2half_rn(q1); g_qh[base + 64 + i] = h; g_ql[base + 64 + i] = __float2half_rn(q1 - __half2float(h));
    g_kh[base + i]      = __float2half_rn(k0);
    g_kh[base + 64 + i] = __float2half_rn(k1);
}

// ---------------------------------------------------------------------------
// Transpose + fp16 round: src [H][R][C] fp32 -> dst[h*C + c][r] fp16.
// ---------------------------------------------------------------------------
__global__ void transpose_half_kernel(const float* __restrict__ src,
                                      __half* __restrict__ dst,
                                      int R, int C) {
    __shared__ float t[32][33];
    int h  = blockIdx.z;
    int r0 = blockIdx.y << 5, c0 = blockIdx.x << 5;
    int tx = threadIdx.x, ty = threadIdx.y;  // 32 x 8
    const float* s = src + (size_t)h * R * C;
#pragma unroll
    for (int j = 0; j < 4; ++j)
        t[ty + 8 * j][tx] = s[(size_t)(r0 + ty + 8 * j) * C + c0 + tx];
    __syncthreads();
#pragma unroll
    for (int j = 0; j < 4; ++j) {
        int c = c0 + ty + 8 * j;
        dst[(size_t)(h * C + c) * R + r0 + tx] = __float2half_rn(t[tx][ty + 8 * j]);
    }
}

// ---------------------------------------------------------------------------
// fp16 2-pass GEMM with in-register A split: A is fp32; D = Ah*Bh + Al*Bh.
// CTA 128x128, KBLK 64, 4 warps (64x64), 128 threads, 2 CTAs/SM.
// mode 0: fp32 out -> [b][h][p][e]; mode 1: fp32 row-major;
// mode 2: fp16 (single) -> outh at [b][h][p][e]  (V path, for flash).
// ---------------------------------------------------------------------------
__global__ __launch_bounds__(128, 2) void gemm_hmma(
    const float* __restrict__ A,
    const __half* __restrict__ Bh,
    const float* __restrict__ bias,
    float* __restrict__ out,
    __half* __restrict__ outh,
    int mode)
{
    extern __shared__ char sm[];
    const uint32_t sb = (uint32_t)__cvta_generic_to_shared(sm);

    const int tid  = threadIdx.x;
    const int wid  = tid >> 5;
    const int lane = tid & 31;
    const int row0 = blockIdx.y * 128;
    const int n0   = blockIdx.x * 128;
    const int m_w  = (wid & 1) * 64;
    const int n_w  = (wid >> 1) * 64;

    const uint32_t aOff = (uint32_t)(m_w + (lane & 15)) * 144 + ((lane >> 4) << 4);
    const uint32_t bOff = (uint32_t)(n_w + ((lane >> 4) << 3) + (lane & 7)) * 144 +
                          (uint32_t)((lane & 8) << 1);
    const uint32_t aHi = sb + OFF_AH + aOff;
    const uint32_t aLo = sb + OFF_AL + aOff;
    const uint32_t bHi = sb + OFF_BH + bOff;

    float acc[4][8][4];
#pragma unroll
    for (int i = 0; i < 4; ++i)
#pragma unroll
        for (int j = 0; j < 8; ++j)
#pragma unroll
            for (int r = 0; r < 4; ++r) acc[i][j][r] = 0.0f;

    const int lr  = tid >> 3;          // 0..15 (+16 per i)
    const int lc8 = (tid & 7) * 8;     // 0..56

    for (int it = 0; it < DMODEL / 64; ++it) {
        const int k0 = it * 64;
        __syncthreads();
#pragma unroll
        for (int i = 0; i < 8; ++i) {
            int r = lr + i * 16;
            size_t ga = (size_t)(row0 + r) * DMODEL + k0 + lc8;
            float4 f0 = *(const float4*)(A + ga);
            float4 f1 = *(const float4*)(A + ga + 4);
            float e[8] = {f0.x, f0.y, f0.z, f0.w, f1.x, f1.y, f1.z, f1.w};
            uint32_t hw[4], lw[4];
#pragma unroll
            for (int p = 0; p < 4; ++p) {
                hw[p] = packhf(e[2*p], e[2*p+1]);
                float2 bk = __half22float2(*(__half2*)&hw[p]);
                lw[p] = packhf(e[2*p] - bk.x, e[2*p+1] - bk.y);
            }
            uint32_t so = (uint32_t)(r * 144 + lc8 * 2);
            *(uint4*)(sm + OFF_AH + so) = make_uint4(hw[0], hw[1], hw[2], hw[3]);
            *(uint4*)(sm + OFF_AL + so) = make_uint4(lw[0], lw[1], lw[2], lw[3]);
            size_t gb = (size_t)(n0 + r) * DMODEL + k0 + lc8;
            *(float4*)(sm + OFF_BH + so) = *(const float4*)(Bh + gb);
        }
        __syncthreads();

#pragma unroll
        for (int kk = 0; kk < 4; ++kk) {
            uint32_t Af[4][4], Bf[4][4];
            // pass 1: Ah * Bh
#pragma unroll
            for (int mi = 0; mi < 4; ++mi)
                ldsm4(Af[mi], aHi + mi * (16 * 144) + kk * 32);
#pragma unroll
            for (int ni = 0; ni < 4; ++ni)
                ldsm4(Bf[ni], bHi + ni * (16 * 144) + kk * 32);
#pragma unroll
            for (int mi = 0; mi < 4; ++mi)
#pragma unroll
                for (int j = 0; j < 8; ++j)
                    mma16816h(acc[mi][j], Af[mi], Bf[j >> 1][(j & 1) * 2],
                              Bf[j >> 1][(j & 1) * 2 + 1]);
            // pass 2: Al * Bh (reuse Bf)
#pragma unroll
            for (int mi = 0; mi < 4; ++mi) {
                uint32_t Al4[4];
                ldsm4(Al4, aLo + mi * (16 * 144) + kk * 32);
#pragma unroll
                for (int j = 0; j < 8; ++j)
                    mma16816h(acc[mi][j], Al4, Bf[j >> 1][(j & 1) * 2],
                              Bf[j >> 1][(j & 1) * 2 + 1]);
            }
        }
    }

    // Epilogue
    const int g = lane >> 2, t4 = lane & 3;
#pragma unroll
    for (int mi = 0; mi < 4; ++mi) {
        int m = row0 + m_w + mi * 16 + g;
#pragma unroll
        for (int j = 0; j < 8; ++j) {
            int col = n0 + n_w + j * 8 + t4 * 2;
            float b0 = bias[col], b1 = bias[col + 1];
            float2 v0 = make_float2(acc[mi][j][0] + b0, acc[mi][j][1] + b1);
            float2 v1 = make_float2(acc[mi][j][2] + b0, acc[mi][j][3] + b1);
            if (mode == 1) {
                *(float2*)(out + (size_t)m * DMODEL + col)       = v0;
                *(float2*)(out + (size_t)(m + 8) * DMODEL + col) = v1;
            } else {
                int h = col >> 7, e = col & 127;
                int b  = m >> 11, p = m & 2047;
                size_t base = (((size_t)(b * NHEADS + h) * SEQ) << 7) + e;
                size_t i0 = base + ((size_t)p << 7);
                size_t i1 = base + ((size_t)(p + 8) << 7);
                if (mode == 0) {
                    *(float2*)(out + i0) = v0;
                    *(float2*)(out + i1) = v1;
                } else {  // mode 2: fp16 single (V path)
                    *(uint32_t*)(outh + i0) = packhf(v0.x, v0.y);
                    *(uint32_t*)(outh + i1) = packhf(v1.x, v1.y);
                }
            }
        }
    }
}

// ---------------------------------------------------------------------------
// fp16 causal flash attention. CTA = 128 q x 128 kv, 8 warps x 16 rows.
// S = Qh*Kh + Ql*Kh (K rounded);  O += Ph*Vh (P rounded, V rounded).
// V tile via cp.async overlapped with the S-phase MMAs.
// Epilogue writes z fp32 into g_q as [b*p][h*e] (O-proj A input).
// ---------------------------------------------------------------------------
__global__ __launch_bounds__(256, 1) void flash_hmma() {
    extern __shared__ char sm[];
    const uint32_t sb = (uint32_t)__cvta_generic_to_shared(sm);

    const int tid  = threadIdx.x;
    const int wid  = tid >> 5;
    const int lane = tid & 31;
    const int bh   = blockIdx.y;
    const int qt   = gridDim.x - 1 - blockIdx.x;   // heavy tiles first
    const int q0   = qt * 128;

    const __half* qh = g_qh + (size_t)bh * SEQ * DHEAD;
    const __half* ql = g_ql + (size_t)bh * SEQ * DHEAD;
    const __half* kh = g_kh + (size_t)bh * SEQ * DHEAD;
    const __half* vh = g_vh + (size_t)bh * SEQ * DHEAD;

#pragma unroll
    for (int i = 0; i < 8; ++i) {
        int f = tid + i * 256;
        int r = f >> 4, c8 = (f & 15) * 8;
        uint32_t off = (uint32_t)(r * FS + c8 * 2);
        size_t g = (size_t)(q0 + r) * DHEAD + c8;
        *(uint4*)(sm + FQH + off) = *(const uint4*)(qh + g);
        *(uint4*)(sm + FQL + off) = *(const uint4*)(ql + g);
    }

    const uint32_t aOff = (uint32_t)(wid * 16 + (lane & 15)) * FS + ((lane >> 4) << 4);
    const uint32_t aQh = sb + FQH + aOff;
    const uint32_t aQl = sb + FQL + aOff;
    const uint32_t bOff = (uint32_t)(((lane >> 4) << 3) + (lane & 7)) * FS +
                          (uint32_t)((lane & 8) << 1);
    const uint32_t bKh = sb + FKH + bOff;
    const uint32_t vOff = (uint32_t)(lane & 15) * FS + ((lane >> 4) << 4);
    const uint32_t bVh = sb + FVH + vOff;

    float o[16][4];
#pragma unroll
    for (int j = 0; j < 16; ++j)
#pragma unroll
        for (int r = 0; r < 4; ++r) o[j][r] = 0.0f;
    float m1 = -1e30f, m2 = -1e30f, l1 = 0.0f, l2 = 0.0f;

    for (int t = 0; t <= qt; ++t) {
        const int k0 = t * 128;
        __syncthreads();
        // K: direct ld/st (needed now). V: cp.async, overlapped with S-phase.
#pragma unroll
        for (int i = 0; i < 8; ++i) {
            int f = tid + i * 256;
            int r = f >> 4, c8 = (f & 15) * 8;
            uint32_t off = (uint32_t)(r * FS + c8 * 2);
            size_t g = (size_t)(k0 + r) * DHEAD + c8;
            *(uint4*)(sm + FKH + off) = *(const uint4*)(kh + g);
            cpasync16(sb + FVH + off, vh + g);
        }
        asm volatile("cp.async.commit_group;" ::: "memory");
        __syncthreads();   // K visible

        float s[16][4];
#pragma unroll
        for (int j = 0; j < 16; ++j)
#pragma unroll
            for (int r = 0; r < 4; ++r) s[j][r] = 0.0f;

#pragma unroll
        for (int kk = 0; kk < 8; ++kk) {
            uint32_t qa[4], qb[4], kb[4];
            ldsm4(qa, aQh + kk * 32);
            ldsm4(qb, aQl + kk * 32);
#pragma unroll
            for (int nn = 0; nn < 8; ++nn) {
                ldsm4(kb, bKh + nn * (16 * FS) + kk * 32);
                mma16816h(s[2*nn],   qa, kb[0], kb[1]);
                mma16816h(s[2*nn+1], qa, kb[2], kb[3]);
                mma16816h(s[2*nn],   qb, kb[0], kb[1]);
                mma16816h(s[2*nn+1], qb, kb[2], kb[3]);
            }
        }

        const int r1 = q0 + wid * 16 + (lane >> 2);
        const int r2 = r1 + 8;
        if (t == qt) {
            const int c0 = k0 + (lane & 3) * 2;
#pragma unroll
            for (int j = 0; j < 16; ++j) {
                int col = c0 + j * 8;
                if (col     > r1) s[j][0] = -1e30f;
                if (col + 1 > r1) s[j][1] = -1e30f;
                if (col     > r2) s[j][2] = -1e30f;
                if (col + 1 > r2) s[j][3] = -1e30f;
            }
        }

        float mx1 = -1e30f, mx2 = -1e30f;
#pragma unroll
        for (int j = 0; j < 16; ++j) {
            mx1 = fmaxf(mx1, fmaxf(s[j][0], s[j][1]));
            mx2 = fmaxf(mx2, fmaxf(s[j][2], s[j][3]));
        }
        mx1 = fmaxf(mx1, __shfl_xor_sync(0xffffffffu, mx1, 1));
        mx1 = fmaxf(mx1, __shfl_xor_sync(0xffffffffu, mx1, 2));
        mx2 = fmaxf(mx2, __shfl_xor_sync(0xffffffffu, mx2, 1));
        mx2 = fmaxf(mx2, __shfl_xor_sync(0xffffffffu, mx2, 2));
        float mn1 = fmaxf(m1, mx1), mn2 = fmaxf(m2, mx2);
        float sc1 = ex2(m1 - mn1), sc2 = ex2(m2 - mn2);
        float rs1 = 0.0f, rs2 = 0.0f;
#pragma unroll
        for (int j = 0; j < 16; ++j) {
            s[j][0] = ex2(s[j][0] - mn1);
            s[j][1] = ex2(s[j][1] - mn1);
            s[j][2] = ex2(s[j][2] - mn2);
            s[j][3] = ex2(s[j][3] - mn2);
            rs1 += s[j][0] + s[j][1];
            rs2 += s[j][2] + s[j][3];
        }
        rs1 += __shfl_xor_sync(0xffffffffu, rs1, 1);
        rs1 += __shfl_xor_sync(0xffffffffu, rs1, 2);
        rs2 += __shfl_xor_sync(0xffffffffu, rs2, 1);
        rs2 += __shfl_xor_sync(0xffffffffu, rs2, 2);
        l1 = l1 * sc1 + rs1;  m1 = mn1;
        l2 = l2 * sc2 + rs2;  m2 = mn2;
#pragma unroll
        for (int j = 0; j < 16; ++j) {
            o[j][0] *= sc1; o[j][1] *= sc1;
            o[j][2] *= sc2; o[j][3] *= sc2;
        }

        asm volatile("cp.async.wait_group 0;" ::: "memory");
        __syncthreads();   // V visible

        // O += P V : P rounded to fp16, V single fp16
#pragma unroll
        for (int kk = 0; kk < 8; ++kk) {
            uint32_t pha[4], vb[4];
            pha[0] = packhf(s[2*kk][0],   s[2*kk][1]);
            pha[1] = packhf(s[2*kk][2],   s[2*kk][3]);
            pha[2] = packhf(s[2*kk+1][0], s[2*kk+1][1]);
            pha[3] = packhf(s[2*kk+1][2], s[2*kk+1][3]);
#pragma unroll
            for (int nn = 0; nn < 8; ++nn) {
                ldsm4t(vb, bVh + kk * (16 * FS) + nn * 32);
                mma16816h(o[2*nn],   pha, vb[0], vb[1]);
                mma16816h(o[2*nn+1], pha, vb[2], vb[3]);
            }
        }
    }

    // Epilogue: normalize, write z fp32 into g_q as [b*p][h*e].
    const int b = bh >> 4, h = bh & 15;
    const int r1 = q0 + wid * 16 + (lane >> 2);
    const float inv1 = 1.0f / l1, inv2 = 1.0f / l2;
    float* z1 = g_q + (size_t)(b * SEQ + r1) * DMODEL + h * DHEAD + (lane & 3) * 2;
    float* z2 = z1 + (size_t)8 * DMODEL;
#pragma unroll
    for (int j = 0; j < 16; ++j) {
        *(float2*)(z1 + j * 8) = make_float2(o[j][0] * inv1, o[j][1] * inv1);
        *(float2*)(z2 + j * 8) = make_float2(o[j][2] * inv2, o[j][3] * inv2);
    }
}

// ---------------------------------------------------------------------------
extern "C" void kernel_launch(void* const* d_in, const int* in_sizes, int n_in,
                              void* d_out, int out_size) {
    (void)in_sizes; (void)n_in; (void)out_size;
    const float* qin = (const float*)d_in[0];
    const float* kin = (const float*)d_in[1];
    const float* vin = (const float*)d_in[2];
    const float* WQ  = (const float*)d_in[3];
    const float* WK  = (const float*)d_in[4];
    const float* WV  = (const float*)d_in[5];
    const float* WO  = (const float*)d_in[6];
    const float* bQ  = (const float*)d_in[7];
    const float* bK  = (const float*)d_in[8];
    const float* bV  = (const float*)d_in[9];
    const float* bO  = (const float*)d_in[10];
    float* out = (float*)d_out;

    float *pq, *pk;
    __half *wq, *wk, *wv, *wo, *vh;
    cudaGetSymbolAddress((void**)&pq, g_q);
    cudaGetSymbolAddress((void**)&pk, g_k);
    cudaGetSymbolAddress((void**)&wq, g_wq);
    cudaGetSymbolAddress((void**)&wk, g_wk);
    cudaGetSymbolAddress((void**)&wv, g_wv);
    cudaGetSymbolAddress((void**)&wo, g_wo);
    cudaGetSymbolAddress((void**)&vh, g_vh);

    cudaFuncSetAttribute((const void*)gemm_hmma,
                         cudaFuncAttributeMaxDynamicSharedMemorySize, GEMM_SMEM);
    cudaFuncSetAttribute((const void*)flash_hmma,
                         cudaFuncAttributeMaxDynamicSharedMemorySize, FLASH_SMEM);

    dim3 tb(32, 8);
    dim3 ggrid(DMODEL / 128, MROWS / 128);   // (16, 32)

    transpose_half_kernel<<<dim3(4, 64, 16), tb>>>(WQ, wq, DMODEL, DHEAD);   // 1
    transpose_half_kernel<<<dim3(4, 64, 16), tb>>>(WK, wk, DMODEL, DHEAD);   // 2
    transpose_half_kernel<<<dim3(4, 64, 16), tb>>>(WV, wv, DMODEL, DHEAD);   // 3
    transpose_half_kernel<<<dim3(64, 64, 1), tb>>>(WO, wo, DMODEL, DMODEL);  // 4
    rope_table_kernel<<<SEQ, 64>>>();                                        // 5
    gemm_hmma<<<ggrid, 128, GEMM_SMEM>>>(qin, wq, bQ, pq, 0, 0);             // 6 <- ncu
    gemm_hmma<<<ggrid, 128, GEMM_SMEM>>>(kin, wk, bK, pk, 0, 0);             // 7
    gemm_hmma<<<ggrid, 128, GEMM_SMEM>>>(vin, wv, bV, 0, vh, 2);             // 8
    rope_split_kernel<<<(BHN * SEQ * 64) / 256, 256>>>();                    // 9
    flash_hmma<<<dim3(SEQ / 128, BHN), 256, FLASH_SMEM>>>();                 // 10 -> g_q
    gemm_hmma<<<ggrid, 128, GEMM_SMEM>>>(pq, wo, bO, out, 0, 1);             // 11
}

// round 12
// speedup vs baseline: 2.0671x; 1.0464x over previous
#include <cuda_runtime.h>
#include <cuda_fp16.h>
#include <math.h>
#include <stdint.h>

#define DMODEL 2048
#define NHEADS 16
#define DHEAD  128
#define SEQ    2048
#define BATCH  2
#define BHN    (BATCH*NHEADS)   // 32
#define MROWS  (BATCH*SEQ)      // 4096

// log2(e) / sqrt(128)
#define QSCALE (1.4426950408889634f * 0.08838834764831845f)

// ---- fp16 GEMM: CTA 128x128, KBLK 64, 4 warps (64x64), 128 thr ----
#define PADK 72                       // fp16 per smem row (144 B)
#define TILE_BYTES (128 * PADK * 2)   // 18432
#define OFF_AH 0
#define OFF_AL (TILE_BYTES)
#define OFF_BH (2*TILE_BYTES)
#define GEMM_SMEM (3*TILE_BYTES)      // 55296 B (2 CTAs/SM)

// ---- fp16 flash: 128 q x 128 kv, 4 tiles (Qh,Ql,Kh,Vh), stride 272 B ----
#define FS   272
#define FT   (128 * FS)
#define FQH  0
#define FQL  (FT)
#define FKH  (2*FT)
#define FVH  (3*FT)
#define FLASH_SMEM (4*FT)          // 139264 B

// ---------------- scratch (device globals; allocation-free) ----------------
__device__ float  g_q[(size_t)BHN * SEQ * DHEAD];   // Q proj out, later reused as z
__device__ float  g_k[(size_t)BHN * SEQ * DHEAD];
__device__ float2 g_rope[SEQ * 64];

__device__ __half g_wq[(size_t)DMODEL * DMODEL];
__device__ __half g_wk[(size_t)DMODEL * DMODEL];
__device__ __half g_wv[(size_t)DMODEL * DMODEL];
__device__ __half g_wo[(size_t)DMODEL * DMODEL];

__device__ __half g_qh[(size_t)BHN * SEQ * DHEAD];
__device__ __half g_ql[(size_t)BHN * SEQ * DHEAD];
__device__ __half g_kh[(size_t)BHN * SEQ * DHEAD];
__device__ __half g_vh[(size_t)BHN * SEQ * DHEAD];

// ---------------- helpers ----------------
__device__ __forceinline__ void ldsm4(uint32_t* r, uint32_t addr) {
    asm volatile("ldmatrix.sync.aligned.m8n8.x4.shared.b16 {%0,%1,%2,%3}, [%4];"
                 : "=r"(r[0]), "=r"(r[1]), "=r"(r[2]), "=r"(r[3]) : "r"(addr));
}
__device__ __forceinline__ void ldsm4t(uint32_t* r, uint32_t addr) {
    asm volatile("ldmatrix.sync.aligned.m8n8.x4.trans.shared.b16 {%0,%1,%2,%3}, [%4];"
                 : "=r"(r[0]), "=r"(r[1]), "=r"(r[2]), "=r"(r[3]) : "r"(addr));
}
__device__ __forceinline__ void mma16816h(float* d, const uint32_t* a,
                                          uint32_t b0, uint32_t b1) {
    asm volatile(
        "mma.sync.aligned.m16n8k16.row.col.f32.f16.f16.f32 "
        "{%0,%1,%2,%3}, {%4,%5,%6,%7}, {%8,%9}, {%0,%1,%2,%3};"
        : "+f"(d[0]), "+f"(d[1]), "+f"(d[2]), "+f"(d[3])
        : "r"(a[0]), "r"(a[1]), "r"(a[2]), "r"(a[3]), "r"(b0), "r"(b1));
}
__device__ __forceinline__ float ex2(float x) {
    float y; asm("ex2.approx.f32 %0, %1;" : "=f"(y) : "f"(x)); return y;
}
__device__ __forceinline__ uint32_t packhf(float lo, float hi) {
    uint32_t r; asm("cvt.rn.f16x2.f32 %0, %1, %2;" : "=r"(r) : "f"(hi), "f"(lo));
    return r;
}
__device__ __forceinline__ void cpasync16(uint32_t s, const void* g) {
    asm volatile("cp.async.cg.shared.global [%0], [%1], 16;" :: "r"(s), "l"(g));
}

// ---------------------------------------------------------------------------
// RoPE table (fp32 angle, fp64 sin/cos)
// ---------------------------------------------------------------------------
__global__ void rope_table_kernel() {
    int p = blockIdx.x;
    int i = threadIdx.x;  // 0..63
    float freq = (float)pow(10000.0, (double)i / 64.0);
    float ang  = (float)p / freq;
    double s, c;
    sincos((double)ang, &s, &c);
    g_rope[p * 64 + i] = make_float2((float)s, (float)c);
}

// ---------------------------------------------------------------------------
// Rope + fp16 split: q -> hi/lo (QSCALE folded); k -> hi only.
// ---------------------------------------------------------------------------
__global__ void rope_split_kernel() {
    int gid = blockIdx.x * 256 + threadIdx.x;
    int i    = gid & 63;
    int rest = gid >> 6;
    int p    = rest & 2047;
    int bh   = rest >> 11;
    float2 sc = g_rope[p * 64 + i];
    size_t base = ((size_t)bh * SEQ + p) * DHEAD;

    float x0 = g_q[base + i], x1 = g_q[base + 64 + i];
    float q0 = (x0 * sc.y - x1 * sc.x) * QSCALE;
    float q1 = (x1 * sc.y + x0 * sc.x) * QSCALE;
    float y0 = g_k[base + i], y1 = g_k[base + 64 + i];
    float k0 = y0 * sc.y - y1 * sc.x;
    float k1 = y1 * sc.y + y0 * sc.x;

    __half h;
    h = __float2half_rn(q0); g_qh[base + i]      = h; g_ql[base + i]      = __float2half_rn(q0 - __half2float(h));
    h = __float2half_rn(q1); g_qh[base + 64 + i] = h; g_ql[base + 64 + i] = __float2half_rn(q1 - __half2float(h));
    g_kh[base + i]      = __float2half_rn(k0);
    g_kh[base + 64 + i] = __float2half_rn(k1);
}

// ---------------------------------------------------------------------------
// Transpose + fp16 round: src [H][R][C] fp32 -> dst[h*C + c][r] fp16.
// ---------------------------------------------------------------------------
__global__ void transpose_half_kernel(const float* __restrict__ src,
                                      __half* __restrict__ dst,
                                      int R, int C) {
    __shared__ float t[32][33];
    int h  = blockIdx.z;
    int r0 = blockIdx.y << 5, c0 = blockIdx.x << 5;
    int tx = threadIdx.x, ty = threadIdx.y;  // 32 x 8
    const float* s = src + (size_t)h * R * C;
#pragma unroll
    for (int j = 0; j < 4; ++j)
        t[ty + 8 * j][tx] = s[(size_t)(r0 + ty + 8 * j) * C + c0 + tx];
    __syncthreads();
#pragma unroll
    for (int j = 0; j < 4; ++j) {
        int c = c0 + ty + 8 * j;
        dst[(size_t)(h * C + c) * R + r0 + tx] = __float2half_rn(t[tx][ty + 8 * j]);
    }
}

// ===========================================================================
// Shared GEMM inner machinery (macro to keep the two kernels in sync)
// ===========================================================================
#define GEMM_PROLOGUE()                                                        \
    extern __shared__ char sm[];                                               \
    const uint32_t sb = (uint32_t)__cvta_generic_to_shared(sm);                \
    const int tid  = threadIdx.x;                                              \
    const int wid  = tid >> 5;                                                 \
    const int lane = tid & 31;                                                 \
    const int row0 = blockIdx.y * 128;                                         \
    const int n0   = blockIdx.x * 128;                                         \
    const int m_w  = (wid & 1) * 64;                                           \
    const int n_w  = (wid >> 1) * 64;                                          \
    const uint32_t aOff = (uint32_t)(m_w + (lane & 15)) * 144 + ((lane >> 4) << 4); \
    const uint32_t bOff = (uint32_t)(n_w + ((lane >> 4) << 3) + (lane & 7)) * 144 + \
                          (uint32_t)((lane & 8) << 1);                         \
    const uint32_t aHi = sb + OFF_AH + aOff;                                   \
    const uint32_t aLo = sb + OFF_AL + aOff;                                   \
    const uint32_t bHi = sb + OFF_BH + bOff;                                   \
    float acc[4][8][4];                                                        \
    _Pragma("unroll")                                                          \
    for (int i = 0; i < 4; ++i)                                                \
        _Pragma("unroll")                                                      \
        for (int j = 0; j < 8; ++j)                                            \
            _Pragma("unroll")                                                  \
            for (int r = 0; r < 4; ++r) acc[i][j][r] = 0.0f;                   \
    const int lr  = tid >> 3;                                                  \
    const int lc8 = (tid & 7) * 8;

#define GEMM_MAINLOOP(A, Bh, twopass)                                          \
    for (int it = 0; it < DMODEL / 64; ++it) {                                 \
        const int k0 = it * 64;                                                \
        __syncthreads();                                                       \
        _Pragma("unroll")                                                      \
        for (int i = 0; i < 8; ++i) {                                          \
            int r = lr + i * 16;                                               \
            size_t ga = (size_t)(row0 + r) * DMODEL + k0 + lc8;                \
            float4 f0 = *(const float4*)((A) + ga);                            \
            float4 f1 = *(const float4*)((A) + ga + 4);                        \
            float e[8] = {f0.x, f0.y, f0.z, f0.w, f1.x, f1.y, f1.z, f1.w};     \
            uint32_t hw[4], lw[4];                                             \
            _Pragma("unroll")                                                  \
            for (int p = 0; p < 4; ++p) {                                      \
                hw[p] = packhf(e[2*p], e[2*p+1]);                              \
                float2 bk = __half22float2(*(__half2*)&hw[p]);                 \
                lw[p] = packhf(e[2*p] - bk.x, e[2*p+1] - bk.y);                \
            }                                                                  \
            uint32_t so = (uint32_t)(r * 144 + lc8 * 2);                       \
            *(uint4*)(sm + OFF_AH + so) = make_uint4(hw[0], hw[1], hw[2], hw[3]); \
            if (twopass)                                                       \
                *(uint4*)(sm + OFF_AL + so) = make_uint4(lw[0], lw[1], lw[2], lw[3]); \
            size_t gb = (size_t)(n0 + r) * DMODEL + k0 + lc8;                  \
            *(float4*)(sm + OFF_BH + so) = *(const float4*)((Bh) + gb);        \
        }                                                                      \
        __syncthreads();                                                       \
        _Pragma("unroll")                                                      \
        for (int kk = 0; kk < 4; ++kk) {                                       \
            uint32_t Af[4][4], Bf[4][4];                                       \
            _Pragma("unroll")                                                  \
            for (int mi = 0; mi < 4; ++mi)                                     \
                ldsm4(Af[mi], aHi + mi * (16 * 144) + kk * 32);                \
            _Pragma("unroll")                                                  \
            for (int ni = 0; ni < 4; ++ni)                                     \
                ldsm4(Bf[ni], bHi + ni * (16 * 144) + kk * 32);                \
            _Pragma("unroll")                                                  \
            for (int mi = 0; mi < 4; ++mi)                                     \
                _Pragma("unroll")                                              \
                for (int j = 0; j < 8; ++j)                                    \
                    mma16816h(acc[mi][j], Af[mi], Bf[j >> 1][(j & 1) * 2],     \
                              Bf[j >> 1][(j & 1) * 2 + 1]);                    \
            if (twopass) {                                                     \
                _Pragma("unroll")                                              \
                for (int mi = 0; mi < 4; ++mi) {                               \
                    uint32_t Al4[4];                                           \
                    ldsm4(Al4, aLo + mi * (16 * 144) + kk * 32);               \
                    _Pragma("unroll")                                          \
                    for (int j = 0; j < 8; ++j)                                \
                        mma16816h(acc[mi][j], Al4, Bf[j >> 1][(j & 1) * 2],    \
                                  Bf[j >> 1][(j & 1) * 2 + 1]);                \
                }                                                              \
            }                                                                  \
        }                                                                      \
    }

// ---------------------------------------------------------------------------
// Fused QKV projection: grid.z selects {Q, K, V}. Q/K 2-pass fp32 out;
// V single-pass, fp16 out to g_vh. All outputs in [b][h][p][e].
// ---------------------------------------------------------------------------
__global__ __launch_bounds__(128, 2) void gemm_qkv(
    const float* __restrict__ A0, const float* __restrict__ A1,
    const float* __restrict__ A2,
    const float* __restrict__ bQ, const float* __restrict__ bK,
    const float* __restrict__ bV)
{
    const int z = blockIdx.z;
    const float* A    = (z == 0) ? A0 : (z == 1) ? A1 : A2;
    const __half* Bh  = (z == 0) ? g_wq : (z == 1) ? g_wk : g_wv;
    const float* bias = (z == 0) ? bQ : (z == 1) ? bK : bV;
    const bool twopass = (z != 2);

    GEMM_PROLOGUE();
    GEMM_MAINLOOP(A, Bh, twopass);

    float* out = (z == 0) ? g_q : g_k;
    const int g = lane >> 2, t4 = lane & 3;
#pragma unroll
    for (int mi = 0; mi < 4; ++mi) {
        int m = row0 + m_w + mi * 16 + g;
#pragma unroll
        for (int j = 0; j < 8; ++j) {
            int col = n0 + n_w + j * 8 + t4 * 2;
            float b0 = bias[col], b1 = bias[col + 1];
            float2 v0 = make_float2(acc[mi][j][0] + b0, acc[mi][j][1] + b1);
            float2 v1 = make_float2(acc[mi][j][2] + b0, acc[mi][j][3] + b1);
            int h = col >> 7, e = col & 127;
            int b  = m >> 11, p = m & 2047;
            size_t base = (((size_t)(b * NHEADS + h) * SEQ) << 7) + e;
            size_t i0 = base + ((size_t)p << 7);
            size_t i1 = base + ((size_t)(p + 8) << 7);
            if (z != 2) {
                *(float2*)(out + i0) = v0;
                *(float2*)(out + i1) = v1;
            } else {
                *(uint32_t*)(g_vh + i0) = packhf(v0.x, v0.y);
                *(uint32_t*)(g_vh + i1) = packhf(v1.x, v1.y);
            }
        }
    }
}

// ---------------------------------------------------------------------------
// O projection: 2-pass, fp32 row-major out.
// ---------------------------------------------------------------------------
__global__ __launch_bounds__(128, 2) void gemm_o(
    const float* __restrict__ A,
    const float* __restrict__ bias,
    float* __restrict__ out)
{
    GEMM_PROLOGUE();
    GEMM_MAINLOOP(A, g_wo, true);

    const int g = lane >> 2, t4 = lane & 3;
#pragma unroll
    for (int mi = 0; mi < 4; ++mi) {
        int m = row0 + m_w + mi * 16 + g;
#pragma unroll
        for (int j = 0; j < 8; ++j) {
            int col = n0 + n_w + j * 8 + t4 * 2;
            float b0 = bias[col], b1 = bias[col + 1];
            *(float2*)(out + (size_t)m * DMODEL + col) =
                make_float2(acc[mi][j][0] + b0, acc[mi][j][1] + b1);
            *(float2*)(out + (size_t)(m + 8) * DMODEL + col) =
                make_float2(acc[mi][j][2] + b0, acc[mi][j][3] + b1);
        }
    }
}

// ---------------------------------------------------------------------------
// fp16 causal flash attention. CTA = 128 q x 128 kv, 8 warps x 16 rows.
// S = Qh*Kh + Ql*Kh;  O += Ph*Vh. V via cp.async overlapped with S MMAs.
// Epilogue writes z fp32 into g_q as [b*p][h*e] (O-proj A input).
// ---------------------------------------------------------------------------
__global__ __launch_bounds__(256, 1) void flash_hmma() {
    extern __shared__ char sm[];
    const uint32_t sb = (uint32_t)__cvta_generic_to_shared(sm);

    const int tid  = threadIdx.x;
    const int wid  = tid >> 5;
    const int lane = tid & 31;
    const int bh   = blockIdx.y;
    const int qt   = gridDim.x - 1 - blockIdx.x;   // heavy tiles first
    const int q0   = qt * 128;

    const __half* qh = g_qh + (size_t)bh * SEQ * DHEAD;
    const __half* ql = g_ql + (size_t)bh * SEQ * DHEAD;
    const __half* kh = g_kh + (size_t)bh * SEQ * DHEAD;
    const __half* vh = g_vh + (size_t)bh * SEQ * DHEAD;

#pragma unroll
    for (int i = 0; i < 8; ++i) {
        int f = tid + i * 256;
        int r = f >> 4, c8 = (f & 15) * 8;
        uint32_t off = (uint32_t)(r * FS + c8 * 2);
        size_t g = (size_t)(q0 + r) * DHEAD + c8;
        *(uint4*)(sm + FQH + off) = *(const uint4*)(qh + g);
        *(uint4*)(sm + FQL + off) = *(const uint4*)(ql + g);
    }

    const uint32_t aOff = (uint32_t)(wid * 16 + (lane & 15)) * FS + ((lane >> 4) << 4);
    const uint32_t aQh = sb + FQH + aOff;
    const uint32_t aQl = sb + FQL + aOff;
    const uint32_t bOff = (uint32_t)(((lane >> 4) << 3) + (lane & 7)) * FS +
                          (uint32_t)((lane & 8) << 1);
    const uint32_t bKh = sb + FKH + bOff;
    const uint32_t vOff = (uint32_t)(lane & 15) * FS + ((lane >> 4) << 4);
    const uint32_t bVh = sb + FVH + vOff;

    float o[16][4];
#pragma unroll
    for (int j = 0; j < 16; ++j)
#pragma unroll
        for (int r = 0; r < 4; ++r) o[j][r] = 0.0f;
    float m1 = -1e30f, m2 = -1e30f, l1 = 0.0f, l2 = 0.0f;

    for (int t = 0; t <= qt; ++t) {
        const int k0 = t * 128;
        __syncthreads();
#pragma unroll
        for (int i = 0; i < 8; ++i) {
            int f = tid + i * 256;
            int r = f >> 4, c8 = (f & 15) * 8;
            uint32_t off = (uint32_t)(r * FS + c8 * 2);
            size_t g = (size_t)(k0 + r) * DHEAD + c8;
            *(uint4*)(sm + FKH + off) = *(const uint4*)(kh + g);
            cpasync16(sb + FVH + off, vh + g);
        }
        asm volatile("cp.async.commit_group;" ::: "memory");
        __syncthreads();   // K visible

        float s[16][4];
#pragma unroll
        for (int j = 0; j < 16; ++j)
#pragma unroll
            for (int r = 0; r < 4; ++r) s[j][r] = 0.0f;

#pragma unroll
        for (int kk = 0; kk < 8; ++kk) {
            uint32_t qa[4], qb[4], kb[4];
            ldsm4(qa, aQh + kk * 32);
            ldsm4(qb, aQl + kk * 32);
#pragma unroll
            for (int nn = 0; nn < 8; ++nn) {
                ldsm4(kb, bKh + nn * (16 * FS) + kk * 32);
                mma16816h(s[2*nn],   qa, kb[0], kb[1]);
                mma16816h(s[2*nn+1], qa, kb[2], kb[3]);
                mma16816h(s[2*nn],   qb, kb[0], kb[1]);
                mma16816h(s[2*nn+1], qb, kb[2], kb[3]);
            }
        }

        const int r1 = q0 + wid * 16 + (lane >> 2);
        const int r2 = r1 + 8;
        if (t == qt) {
            const int c0 = k0 + (lane & 3) * 2;
#pragma unroll
            for (int j = 0; j < 16; ++j) {
                int col = c0 + j * 8;
                if (col     > r1) s[j][0] = -1e30f;
                if (col + 1 > r1) s[j][1] = -1e30f;
                if (col     > r2) s[j][2] = -1e30f;
                if (col + 1 > r2) s[j][3] = -1e30f;
            }
        }

        float mx1 = -1e30f, mx2 = -1e30f;
#pragma unroll
        for (int j = 0; j < 16; ++j) {
            mx1 = fmaxf(mx1, fmaxf(s[j][0], s[j][1]));
            mx2 = fmaxf(mx2, fmaxf(s[j][2], s[j][3]));
        }
        mx1 = fmaxf(mx1, __shfl_xor_sync(0xffffffffu, mx1, 1));
        mx1 = fmaxf(mx1, __shfl_xor_sync(0xffffffffu, mx1, 2));
        mx2 = fmaxf(mx2, __shfl_xor_sync(0xffffffffu, mx2, 1));
        mx2 = fmaxf(mx2, __shfl_xor_sync(0xffffffffu, mx2, 2));
        float mn1 = fmaxf(m1, mx1), mn2 = fmaxf(m2, mx2);
        float sc1 = ex2(m1 - mn1), sc2 = ex2(m2 - mn2);
        float rs1 = 0.0f, rs2 = 0.0f;
#pragma unroll
        for (int j = 0; j < 16; ++j) {
            s[j][0] = ex2(s[j][0] - mn1);
            s[j][1] = ex2(s[j][1] - mn1);
            s[j][2] = ex2(s[j][2] - mn2);
            s[j][3] = ex2(s[j][3] - mn2);
            rs1 += s[j][0] + s[j][1];
            rs2 += s[j][2] + s[j][3];
        }
        rs1 += __shfl_xor_sync(0xffffffffu, rs1, 1);
        rs1 += __shfl_xor_sync(0xffffffffu, rs1, 2);
        rs2 += __shfl_xor_sync(0xffffffffu, rs2, 1);
        rs2 += __shfl_xor_sync(0xffffffffu, rs2, 2);
        l1 = l1 * sc1 + rs1;  m1 = mn1;
        l2 = l2 * sc2 + rs2;  m2 = mn2;
#pragma unroll
        for (int j = 0; j < 16; ++j) {
            o[j][0] *= sc1; o[j][1] *= sc1;
            o[j][2] *= sc2; o[j][3] *= sc2;
        }

        asm volatile("cp.async.wait_group 0;" ::: "memory");
        __syncthreads();   // V visible

#pragma unroll
        for (int kk = 0; kk < 8; ++kk) {
            uint32_t pha[4], vb[4];
            pha[0] = packhf(s[2*kk][0],   s[2*kk][1]);
            pha[1] = packhf(s[2*kk][2],   s[2*kk][3]);
            pha[2] = packhf(s[2*kk+1][0], s[2*kk+1][1]);
            pha[3] = packhf(s[2*kk+1][2], s[2*kk+1][3]);
#pragma unroll
            for (int nn = 0; nn < 8; ++nn) {
                ldsm4t(vb, bVh + kk * (16 * FS) + nn * 32);
                mma16816h(o[2*nn],   pha, vb[0], vb[1]);
                mma16816h(o[2*nn+1], pha, vb[2], vb[3]);
            }
        }
    }

    // Epilogue: normalize, write z fp32 into g_q as [b*p][h*e].
    const int b = bh >> 4, h = bh & 15;
    const int r1 = q0 + wid * 16 + (lane >> 2);
    const float inv1 = 1.0f / l1, inv2 = 1.0f / l2;
    float* z1 = g_q + (size_t)(b * SEQ + r1) * DMODEL + h * DHEAD + (lane & 3) * 2;
    float* z2 = z1 + (size_t)8 * DMODEL;
#pragma unroll
    for (int j = 0; j < 16; ++j) {
        *(float2*)(z1 + j * 8) = make_float2(o[j][0] * inv1, o[j][1] * inv1);
        *(float2*)(z2 + j * 8) = make_float2(o[j][2] * inv2, o[j][3] * inv2);
    }
}

// ---------------------------------------------------------------------------
extern "C" void kernel_launch(void* const* d_in, const int* in_sizes, int n_in,
                              void* d_out, int out_size) {
    (void)in_sizes; (void)n_in; (void)out_size;
    const float* qin = (const float*)d_in[0];
    const float* kin = (const float*)d_in[1];
    const float* vin = (const float*)d_in[2];
    const float* WQ  = (const float*)d_in[3];
    const float* WK  = (const float*)d_in[4];
    const float* WV  = (const float*)d_in[5];
    const float* WO  = (const float*)d_in[6];
    const float* bQ  = (const float*)d_in[7];
    const float* bK  = (const float*)d_in[8];
    const float* bV  = (const float*)d_in[9];
    const float* bO  = (const float*)d_in[10];
    float* out = (float*)d_out;

    float* pq;
    __half *wq, *wk, *wv, *wo;
    cudaGetSymbolAddress((void**)&pq, g_q);
    cudaGetSymbolAddress((void**)&wq, g_wq);
    cudaGetSymbolAddress((void**)&wk, g_wk);
    cudaGetSymbolAddress((void**)&wv, g_wv);
    cudaGetSymbolAddress((void**)&wo, g_wo);

    cudaFuncSetAttribute((const void*)gemm_qkv,
                         cudaFuncAttributeMaxDynamicSharedMemorySize, GEMM_SMEM);
    cudaFuncSetAttribute((const void*)gemm_o,
                         cudaFuncAttributeMaxDynamicSharedMemorySize, GEMM_SMEM);
    cudaFuncSetAttribute((const void*)flash_hmma,
                         cudaFuncAttributeMaxDynamicSharedMemorySize, FLASH_SMEM);

    dim3 tb(32, 8);

    transpose_half_kernel<<<dim3(4, 64, 16), tb>>>(WQ, wq, DMODEL, DHEAD);   // 1
    transpose_half_kernel<<<dim3(4, 64, 16), tb>>>(WK, wk, DMODEL, DHEAD);   // 2
    transpose_half_kernel<<<dim3(4, 64, 16), tb>>>(WV, wv, DMODEL, DHEAD);   // 3
    transpose_half_kernel<<<dim3(64, 64, 1), tb>>>(WO, wo, DMODEL, DMODEL);  // 4
    rope_table_kernel<<<SEQ, 64>>>();                                        // 5
    gemm_qkv<<<dim3(16, 32, 3), 128, GEMM_SMEM>>>(qin, kin, vin, bQ, bK, bV);// 6 <- ncu
    rope_split_kernel<<<(BHN * SEQ * 64) / 256, 256>>>();                    // 7
    flash_hmma<<<dim3(SEQ / 128, BHN), 256, FLASH_SMEM>>>();                 // 8 -> g_q
    gemm_o<<<dim3(16, 32), 128, GEMM_SMEM>>>(pq, bO, out);                   // 9
}

// round 13
// speedup vs baseline: 2.3463x; 1.1351x over previous
#include <cuda_runtime.h>
#include <cuda_fp16.h>
#include <math.h>
#include <stdint.h>

#define DMODEL 2048
#define NHEADS 16
#define DHEAD  128
#define SEQ    2048
#define BATCH  2
#define BHN    (BATCH*NHEADS)   // 32
#define MROWS  (BATCH*SEQ)      // 4096

// log2(e) / sqrt(128)
#define QSCALE (1.4426950408889634f * 0.08838834764831845f)

// ---- fp16 GEMM: CTA 128x128, KBLK 64, 4 warps (64x64), 128 thr ----
#define PADK 72                       // fp16 per smem row (144 B)
#define TILE_BYTES (128 * PADK * 2)   // 18432
#define OFF_AH 0
#define OFF_AL (TILE_BYTES)
#define OFF_BH (2*TILE_BYTES)
#define GEMM_SMEM (3*TILE_BYTES)      // 55296 B (2 CTAs/SM)

// ---- fp16 flash: 128 q x 128 kv, 4 tiles (Qh,Ql,Kh,Vh), stride 272 B ----
#define FS   272
#define FT   (128 * FS)
#define FQH  0
#define FQL  (FT)
#define FKH  (2*FT)
#define FVH  (3*FT)
#define FLASH_SMEM (4*FT)          // 139264 B

// ---------------- scratch (device globals; allocation-free) ----------------
__device__ float  g_q[(size_t)BHN * SEQ * DHEAD];   // Q proj out, later reused as z
__device__ float  g_k[(size_t)BHN * SEQ * DHEAD];
__device__ float2 g_rope[SEQ * 64];

__device__ __half g_wq[(size_t)DMODEL * DMODEL];
__device__ __half g_wk[(size_t)DMODEL * DMODEL];
__device__ __half g_wv[(size_t)DMODEL * DMODEL];
__device__ __half g_wo[(size_t)DMODEL * DMODEL];

__device__ __half g_qh[(size_t)BHN * SEQ * DHEAD];
__device__ __half g_ql[(size_t)BHN * SEQ * DHEAD];
__device__ __half g_kh[(size_t)BHN * SEQ * DHEAD];
__device__ __half g_vh[(size_t)BHN * SEQ * DHEAD];

// ---------------- helpers ----------------
__device__ __forceinline__ void ldsm4(uint32_t* r, uint32_t addr) {
    asm volatile("ldmatrix.sync.aligned.m8n8.x4.shared.b16 {%0,%1,%2,%3}, [%4];"
                 : "=r"(r[0]), "=r"(r[1]), "=r"(r[2]), "=r"(r[3]) : "r"(addr));
}
__device__ __forceinline__ void ldsm4t(uint32_t* r, uint32_t addr) {
    asm volatile("ldmatrix.sync.aligned.m8n8.x4.trans.shared.b16 {%0,%1,%2,%3}, [%4];"
                 : "=r"(r[0]), "=r"(r[1]), "=r"(r[2]), "=r"(r[3]) : "r"(addr));
}
__device__ __forceinline__ void mma16816h(float* d, const uint32_t* a,
                                          uint32_t b0, uint32_t b1) {
    asm volatile(
        "mma.sync.aligned.m16n8k16.row.col.f32.f16.f16.f32 "
        "{%0,%1,%2,%3}, {%4,%5,%6,%7}, {%8,%9}, {%0,%1,%2,%3};"
        : "+f"(d[0]), "+f"(d[1]), "+f"(d[2]), "+f"(d[3])
        : "r"(a[0]), "r"(a[1]), "r"(a[2]), "r"(a[3]), "r"(b0), "r"(b1));
}
__device__ __forceinline__ float ex2(float x) {
    float y; asm("ex2.approx.f32 %0, %1;" : "=f"(y) : "f"(x)); return y;
}
__device__ __forceinline__ uint32_t packhf(float lo, float hi) {
    uint32_t r; asm("cvt.rn.f16x2.f32 %0, %1, %2;" : "=r"(r) : "f"(hi), "f"(lo));
    return r;
}
__device__ __forceinline__ void cpasync16(uint32_t s, const void* g) {
    asm volatile("cp.async.cg.shared.global [%0], [%1], 16;" :: "r"(s), "l"(g));
}

// ---------------------------------------------------------------------------
// RoPE table (fp32 angle, fp64 sin/cos)
// ---------------------------------------------------------------------------
__global__ void rope_table_kernel() {
    int p = blockIdx.x;
    int i = threadIdx.x;  // 0..63
    float freq = (float)pow(10000.0, (double)i / 64.0);
    float ang  = (float)p / freq;
    double s, c;
    sincos((double)ang, &s, &c);
    g_rope[p * 64 + i] = make_float2((float)s, (float)c);
}

// ---------------------------------------------------------------------------
// Rope + fp16 split: q -> hi/lo (QSCALE folded); k -> hi only.
// ---------------------------------------------------------------------------
__global__ void rope_split_kernel() {
    int gid = blockIdx.x * 256 + threadIdx.x;
    int i    = gid & 63;
    int rest = gid >> 6;
    int p    = rest & 2047;
    int bh   = rest >> 11;
    float2 sc = g_rope[p * 64 + i];
    size_t base = ((size_t)bh * SEQ + p) * DHEAD;

    float x0 = g_q[base + i], x1 = g_q[base + 64 + i];
    float q0 = (x0 * sc.y - x1 * sc.x) * QSCALE;
    float q1 = (x1 * sc.y + x0 * sc.x) * QSCALE;
    float y0 = g_k[base + i], y1 = g_k[base + 64 + i];
    float k0 = y0 * sc.y - y1 * sc.x;
    float k1 = y1 * sc.y + y0 * sc.x;

    __half h;
    h = __float2half_rn(q0); g_qh[base + i]      = h; g_ql[base + i]      = __float2half_rn(q0 - __half2float(h));
    h = __float2half_rn(q1); g_qh[base + 64 + i] = h; g_ql[base + 64 + i] = __float2half_rn(q1 - __half2float(h));
    g_kh[base + i]      = __float2half_rn(k0);
    g_kh[base + 64 + i] = __float2half_rn(k1);
}

// ---------------------------------------------------------------------------
// Transpose + fp16 round: src [H][R][C] fp32 -> dst[h*C + c][r] fp16.
// ---------------------------------------------------------------------------
__global__ void transpose_half_kernel(const float* __restrict__ src,
                                      __half* __restrict__ dst,
                                      int R, int C) {
    __shared__ float t[32][33];
    int h  = blockIdx.z;
    int r0 = blockIdx.y << 5, c0 = blockIdx.x << 5;
    int tx = threadIdx.x, ty = threadIdx.y;  // 32 x 8
    const float* s = src + (size_t)h * R * C;
#pragma unroll
    for (int j = 0; j < 4; ++j)
        t[ty + 8 * j][tx] = s[(size_t)(r0 + ty + 8 * j) * C + c0 + tx];
    __syncthreads();
#pragma unroll
    for (int j = 0; j < 4; ++j) {
        int c = c0 + ty + 8 * j;
        dst[(size_t)(h * C + c) * R + r0 + tx] = __float2half_rn(t[tx][ty + 8 * j]);
    }
}

// ===========================================================================
// Shared GEMM inner machinery
// ===========================================================================
#define GEMM_PROLOGUE()                                                        \
    extern __shared__ char sm[];                                               \
    const uint32_t sb = (uint32_t)__cvta_generic_to_shared(sm);                \
    const int tid  = threadIdx.x;                                              \
    const int wid  = tid >> 5;                                                 \
    const int lane = tid & 31;                                                 \
    const int row0 = blockIdx.y * 128;                                         \
    const int n0   = blockIdx.x * 128;                                         \
    const int m_w  = (wid & 1) * 64;                                           \
    const int n_w  = (wid >> 1) * 64;                                          \
    const uint32_t aOff = (uint32_t)(m_w + (lane & 15)) * 144 + ((lane >> 4) << 4); \
    const uint32_t bOff = (uint32_t)(n_w + ((lane >> 4) << 3) + (lane & 7)) * 144 + \
                          (uint32_t)((lane & 8) << 1);                         \
    const uint32_t aHi = sb + OFF_AH + aOff;                                   \
    const uint32_t aLo = sb + OFF_AL + aOff;                                   \
    const uint32_t bHi = sb + OFF_BH + bOff;                                   \
    float acc[4][8][4];                                                        \
    _Pragma("unroll")                                                          \
    for (int i = 0; i < 4; ++i)                                                \
        _Pragma("unroll")                                                      \
        for (int j = 0; j < 8; ++j)                                            \
            _Pragma("unroll")                                                  \
            for (int r = 0; r < 4; ++r) acc[i][j][r] = 0.0f;                   \
    const int lr  = tid >> 3;                                                  \
    const int lc8 = (tid & 7) * 8;

#define GEMM_MAINLOOP(A, Bh, twopass)                                          \
    for (int it = 0; it < DMODEL / 64; ++it) {                                 \
        const int k0 = it * 64;                                                \
        __syncthreads();                                                       \
        _Pragma("unroll")                                                      \
        for (int i = 0; i < 8; ++i) {                                          \
            int r = lr + i * 16;                                               \
            size_t ga = (size_t)(row0 + r) * DMODEL + k0 + lc8;                \
            float4 f0 = *(const float4*)((A) + ga);                            \
            float4 f1 = *(const float4*)((A) + ga + 4);                        \
            float e[8] = {f0.x, f0.y, f0.z, f0.w, f1.x, f1.y, f1.z, f1.w};     \
            uint32_t hw[4], lw[4];                                             \
            _Pragma("unroll")                                                  \
            for (int p = 0; p < 4; ++p) {                                      \
                hw[p] = packhf(e[2*p], e[2*p+1]);                              \
                float2 bk = __half22float2(*(__half2*)&hw[p]);                 \
                lw[p] = packhf(e[2*p] - bk.x, e[2*p+1] - bk.y);                \
            }                                                                  \
            uint32_t so = (uint32_t)(r * 144 + lc8 * 2);                       \
            *(uint4*)(sm + OFF_AH + so) = make_uint4(hw[0], hw[1], hw[2], hw[3]); \
            if (twopass)                                                       \
                *(uint4*)(sm + OFF_AL + so) = make_uint4(lw[0], lw[1], lw[2], lw[3]); \
            size_t gb = (size_t)(n0 + r) * DMODEL + k0 + lc8;                  \
            *(float4*)(sm + OFF_BH + so) = *(const float4*)((Bh) + gb);        \
        }                                                                      \
        __syncthreads();                                                       \
        _Pragma("unroll")                                                      \
        for (int kk = 0; kk < 4; ++kk) {                                       \
            uint32_t Af[4][4], Bf[4][4];                                       \
            _Pragma("unroll")                                                  \
            for (int mi = 0; mi < 4; ++mi)                                     \
                ldsm4(Af[mi], aHi + mi * (16 * 144) + kk * 32);                \
            _Pragma("unroll")                                                  \
            for (int ni = 0; ni < 4; ++ni)                                     \
                ldsm4(Bf[ni], bHi + ni * (16 * 144) + kk * 32);                \
            _Pragma("unroll")                                                  \
            for (int mi = 0; mi < 4; ++mi)                                     \
                _Pragma("unroll")                                              \
                for (int j = 0; j < 8; ++j)                                    \
                    mma16816h(acc[mi][j], Af[mi], Bf[j >> 1][(j & 1) * 2],     \
                              Bf[j >> 1][(j & 1) * 2 + 1]);                    \
            if (twopass) {                                                     \
                _Pragma("unroll")                                              \
                for (int mi = 0; mi < 4; ++mi) {                               \
                    uint32_t Al4[4];                                           \
                    ldsm4(Al4, aLo + mi * (16 * 144) + kk * 32);               \
                    _Pragma("unroll")                                          \
                    for (int j = 0; j < 8; ++j)                                \
                        mma16816h(acc[mi][j], Al4, Bf[j >> 1][(j & 1) * 2],    \
                                  Bf[j >> 1][(j & 1) * 2 + 1]);                \
                }                                                              \
            }                                                                  \
        }                                                                      \
    }

// ---------------------------------------------------------------------------
// Fused QKV projection: grid.z selects {Q, K, V}. Q 2-pass (hi/lo kept exact
// through flash); K single-pass (rounded to fp16 post-rope anyway);
// V single-pass fp16 out. All outputs in [b][h][p][e].
// ---------------------------------------------------------------------------
__global__ __launch_bounds__(128, 2) void gemm_qkv(
    const float* __restrict__ A0, const float* __restrict__ A1,
    const float* __restrict__ A2,
    const float* __restrict__ bQ, const float* __restrict__ bK,
    const float* __restrict__ bV)
{
    const int z = blockIdx.z;
    const float* A    = (z == 0) ? A0 : (z == 1) ? A1 : A2;
    const __half* Bh  = (z == 0) ? g_wq : (z == 1) ? g_wk : g_wv;
    const float* bias = (z == 0) ? bQ : (z == 1) ? bK : bV;
    const bool twopass = (z == 0);

    GEMM_PROLOGUE();
    GEMM_MAINLOOP(A, Bh, twopass);

    float* out = (z == 0) ? g_q : g_k;
    const int g = lane >> 2, t4 = lane & 3;
#pragma unroll
    for (int mi = 0; mi < 4; ++mi) {
        int m = row0 + m_w + mi * 16 + g;
#pragma unroll
        for (int j = 0; j < 8; ++j) {
            int col = n0 + n_w + j * 8 + t4 * 2;
            float b0 = bias[col], b1 = bias[col + 1];
            float2 v0 = make_float2(acc[mi][j][0] + b0, acc[mi][j][1] + b1);
            float2 v1 = make_float2(acc[mi][j][2] + b0, acc[mi][j][3] + b1);
            int h = col >> 7, e = col & 127;
            int b  = m >> 11, p = m & 2047;
            size_t base = (((size_t)(b * NHEADS + h) * SEQ) << 7) + e;
            size_t i0 = base + ((size_t)p << 7);
            size_t i1 = base + ((size_t)(p + 8) << 7);
            if (z != 2) {
                *(float2*)(out + i0) = v0;
                *(float2*)(out + i1) = v1;
            } else {
                *(uint32_t*)(g_vh + i0) = packhf(v0.x, v0.y);
                *(uint32_t*)(g_vh + i1) = packhf(v1.x, v1.y);
            }
        }
    }
}

// ---------------------------------------------------------------------------
// O projection: single-pass, fp32 row-major out.
// ---------------------------------------------------------------------------
__global__ __launch_bounds__(128, 2) void gemm_o(
    const float* __restrict__ A,
    const float* __restrict__ bias,
    float* __restrict__ out)
{
    GEMM_PROLOGUE();
    GEMM_MAINLOOP(A, g_wo, false);

    const int g = lane >> 2, t4 = lane & 3;
#pragma unroll
    for (int mi = 0; mi < 4; ++mi) {
        int m = row0 + m_w + mi * 16 + g;
#pragma unroll
        for (int j = 0; j < 8; ++j) {
            int col = n0 + n_w + j * 8 + t4 * 2;
            float b0 = bias[col], b1 = bias[col + 1];
            *(float2*)(out + (size_t)m * DMODEL + col) =
                make_float2(acc[mi][j][0] + b0, acc[mi][j][1] + b1);
            *(float2*)(out + (size_t)(m + 8) * DMODEL + col) =
                make_float2(acc[mi][j][2] + b0, acc[mi][j][3] + b1);
        }
    }
}

// ---------------------------------------------------------------------------
// fp16 causal flash attention. CTA = 128 q x 128 kv, 8 warps x 16 rows.
// S = Qh*Kh + Ql*Kh;  O += Ph*Vh. V via cp.async overlapped with S MMAs.
// Epilogue writes z fp32 into g_q as [b*p][h*e] (O-proj A input).
// ---------------------------------------------------------------------------
__global__ __launch_bounds__(256, 1) void flash_hmma() {
    extern __shared__ char sm[];
    const uint32_t sb = (uint32_t)__cvta_generic_to_shared(sm);

    const int tid  = threadIdx.x;
    const int wid  = tid >> 5;
    const int lane = tid & 31;
    const int bh   = blockIdx.y;
    const int qt   = gridDim.x - 1 - blockIdx.x;   // heavy tiles first
    const int q0   = qt * 128;

    const __half* qh = g_qh + (size_t)bh * SEQ * DHEAD;
    const __half* ql = g_ql + (size_t)bh * SEQ * DHEAD;
    const __half* kh = g_kh + (size_t)bh * SEQ * DHEAD;
    const __half* vh = g_vh + (size_t)bh * SEQ * DHEAD;

#pragma unroll
    for (int i = 0; i < 8; ++i) {
        int f = tid + i * 256;
        int r = f >> 4, c8 = (f & 15) * 8;
        uint32_t off = (uint32_t)(r * FS + c8 * 2);
        size_t g = (size_t)(q0 + r) * DHEAD + c8;
        *(uint4*)(sm + FQH + off) = *(const uint4*)(qh + g);
        *(uint4*)(sm + FQL + off) = *(const uint4*)(ql + g);
    }

    const uint32_t aOff = (uint32_t)(wid * 16 + (lane & 15)) * FS + ((lane >> 4) << 4);
    const uint32_t aQh = sb + FQH + aOff;
    const uint32_t aQl = sb + FQL + aOff;
    const uint32_t bOff = (uint32_t)(((lane >> 4) << 3) + (lane & 7)) * FS +
                          (uint32_t)((lane & 8) << 1);
    const uint32_t bKh = sb + FKH + bOff;
    const uint32_t vOff = (uint32_t)(lane & 15) * FS + ((lane >> 4) << 4);
    const uint32_t bVh = sb + FVH + vOff;

    float o[16][4];
#pragma unroll
    for (int j = 0; j < 16; ++j)
#pragma unroll
        for (int r = 0; r < 4; ++r) o[j][r] = 0.0f;
    float m1 = -1e30f, m2 = -1e30f, l1 = 0.0f, l2 = 0.0f;

    for (int t = 0; t <= qt; ++t) {
        const int k0 = t * 128;
        __syncthreads();
#pragma unroll
        for (int i = 0; i < 8; ++i) {
            int f = tid + i * 256;
            int r = f >> 4, c8 = (f & 15) * 8;
            uint32_t off = (uint32_t)(r * FS + c8 * 2);
            size_t g = (size_t)(k0 + r) * DHEAD + c8;
            *(uint4*)(sm + FKH + off) = *(const uint4*)(kh + g);
            cpasync16(sb + FVH + off, vh + g);
        }
        asm volatile("cp.async.commit_group;" ::: "memory");
        __syncthreads();   // K visible

        float s[16][4];
#pragma unroll
        for (int j = 0; j < 16; ++j)
#pragma unroll
            for (int r = 0; r < 4; ++r) s[j][r] = 0.0f;

#pragma unroll
        for (int kk = 0; kk < 8; ++kk) {
            uint32_t qa[4], qb[4], kb[4];
            ldsm4(qa, aQh + kk * 32);
            ldsm4(qb, aQl + kk * 32);
#pragma unroll
            for (int nn = 0; nn < 8; ++nn) {
                ldsm4(kb, bKh + nn * (16 * FS) + kk * 32);
                mma16816h(s[2*nn],   qa, kb[0], kb[1]);
                mma16816h(s[2*nn+1], qa, kb[2], kb[3]);
                mma16816h(s[2*nn],   qb, kb[0], kb[1]);
                mma16816h(s[2*nn+1], qb, kb[2], kb[3]);
            }
        }

        const int r1 = q0 + wid * 16 + (lane >> 2);
        const int r2 = r1 + 8;
        if (t == qt) {
            const int c0 = k0 + (lane & 3) * 2;
#pragma unroll
            for (int j = 0; j < 16; ++j) {
                int col = c0 + j * 8;
                if (col     > r1) s[j][0] = -1e30f;
                if (col + 1 > r1) s[j][1] = -1e30f;
                if (col     > r2) s[j][2] = -1e30f;
                if (col + 1 > r2) s[j][3] = -1e30f;
            }
        }

        float mx1 = -1e30f, mx2 = -1e30f;
#pragma unroll
        for (int j = 0; j < 16; ++j) {
            mx1 = fmaxf(mx1, fmaxf(s[j][0], s[j][1]));
            mx2 = fmaxf(mx2, fmaxf(s[j][2], s[j][3]));
        }
        mx1 = fmaxf(mx1, __shfl_xor_sync(0xffffffffu, mx1, 1));
        mx1 = fmaxf(mx1, __shfl_xor_sync(0xffffffffu, mx1, 2));
        mx2 = fmaxf(mx2, __shfl_xor_sync(0xffffffffu, mx2, 1));
        mx2 = fmaxf(mx2, __shfl_xor_sync(0xffffffffu, mx2, 2));
        float mn1 = fmaxf(m1, mx1), mn2 = fmaxf(m2, mx2);
        float sc1 = ex2(m1 - mn1), sc2 = ex2(m2 - mn2);
        float rs1 = 0.0f, rs2 = 0.0f;
#pragma unroll
        for (int j = 0; j < 16; ++j) {
            s[j][0] = ex2(s[j][0] - mn1);
            s[j][1] = ex2(s[j][1] - mn1);
            s[j][2] = ex2(s[j][2] - mn2);
            s[j][3] = ex2(s[j][3] - mn2);
            rs1 += s[j][0] + s[j][1];
            rs2 += s[j][2] + s[j][3];
        }
        rs1 += __shfl_xor_sync(0xffffffffu, rs1, 1);
        rs1 += __shfl_xor_sync(0xffffffffu, rs1, 2);
        rs2 += __shfl_xor_sync(0xffffffffu, rs2, 1);
        rs2 += __shfl_xor_sync(0xffffffffu, rs2, 2);
        l1 = l1 * sc1 + rs1;  m1 = mn1;
        l2 = l2 * sc2 + rs2;  m2 = mn2;
#pragma unroll
        for (int j = 0; j < 16; ++j) {
            o[j][0] *= sc1; o[j][1] *= sc1;
            o[j][2] *= sc2; o[j][3] *= sc2;
        }

        asm volatile("cp.async.wait_group 0;" ::: "memory");
        __syncthreads();   // V visible

#pragma unroll
        for (int kk = 0; kk < 8; ++kk) {
            uint32_t pha[4], vb[4];
            pha[0] = packhf(s[2*kk][0],   s[2*kk][1]);
            pha[1] = packhf(s[2*kk][2],   s[2*kk][3]);
            pha[2] = packhf(s[2*kk+1][0], s[2*kk+1][1]);
            pha[3] = packhf(s[2*kk+1][2], s[2*kk+1][3]);
#pragma unroll
            for (int nn = 0; nn < 8; ++nn) {
                ldsm4t(vb, bVh + kk * (16 * FS) + nn * 32);
                mma16816h(o[2*nn],   pha, vb[0], vb[1]);
                mma16816h(o[2*nn+1], pha, vb[2], vb[3]);
            }
        }
    }

    // Epilogue: normalize, write z fp32 into g_q as [b*p][h*e].
    const int b = bh >> 4, h = bh & 15;
    const int r1 = q0 + wid * 16 + (lane >> 2);
    const float inv1 = 1.0f / l1, inv2 = 1.0f / l2;
    float* z1 = g_q + (size_t)(b * SEQ + r1) * DMODEL + h * DHEAD + (lane & 3) * 2;
    float* z2 = z1 + (size_t)8 * DMODEL;
#pragma unroll
    for (int j = 0; j < 16; ++j) {
        *(float2*)(z1 + j * 8) = make_float2(o[j][0] * inv1, o[j][1] * inv1);
        *(float2*)(z2 + j * 8) = make_float2(o[j][2] * inv2, o[j][3] * inv2);
    }
}

// ---------------------------------------------------------------------------
extern "C" void kernel_launch(void* const* d_in, const int* in_sizes, int n_in,
                              void* d_out, int out_size) {
    (void)in_sizes; (void)n_in; (void)out_size;
    const float* qin = (const float*)d_in[0];
    const float* kin = (const float*)d_in[1];
    const float* vin = (const float*)d_in[2];
    const float* WQ  = (const float*)d_in[3];
    const float* WK  = (const float*)d_in[4];
    const float* WV  = (const float*)d_in[5];
    const float* WO  = (const float*)d_in[6];
    const float* bQ  = (const float*)d_in[7];
    const float* bK  = (const float*)d_in[8];
    const float* bV  = (const float*)d_in[9];
    const float* bO  = (const float*)d_in[10];
    float* out = (float*)d_out;

    float* pq;
    __half *wq, *wk, *wv, *wo;
    cudaGetSymbolAddress((void**)&pq, g_q);
    cudaGetSymbolAddress((void**)&wq, g_wq);
    cudaGetSymbolAddress((void**)&wk, g_wk);
    cudaGetSymbolAddress((void**)&wv, g_wv);
    cudaGetSymbolAddress((void**)&wo, g_wo);

    cudaFuncSetAttribute((const void*)gemm_qkv,
                         cudaFuncAttributeMaxDynamicSharedMemorySize, GEMM_SMEM);
    cudaFuncSetAttribute((const void*)gemm_o,
                         cudaFuncAttributeMaxDynamicSharedMemorySize, GEMM_SMEM);
    cudaFuncSetAttribute((const void*)flash_hmma,
                         cudaFuncAttributeMaxDynamicSharedMemorySize, FLASH_SMEM);

    dim3 tb(32, 8);

    transpose_half_kernel<<<dim3(4, 64, 16), tb>>>(WQ, wq, DMODEL, DHEAD);   // 1
    transpose_half_kernel<<<dim3(4, 64, 16), tb>>>(WK, wk, DMODEL, DHEAD);   // 2
    transpose_half_kernel<<<dim3(4, 64, 16), tb>>>(WV, wv, DMODEL, DHEAD);   // 3
    transpose_half_kernel<<<dim3(64, 64, 1), tb>>>(WO, wo, DMODEL, DMODEL);  // 4
    rope_table_kernel<<<SEQ, 64>>>();                                        // 5
    gemm_qkv<<<dim3(16, 32, 3), 128, GEMM_SMEM>>>(qin, kin, vin, bQ, bK, bV);// 6 <- ncu
    rope_split_kernel<<<(BHN * SEQ * 64) / 256, 256>>>();                    // 7
    flash_hmma<<<dim3(SEQ / 128, BHN), 256, FLASH_SMEM>>>();                 // 8 -> g_q
    gemm_o<<<dim3(16, 32), 128, GEMM_SMEM>>>(pq, bO, out);                   // 9
}

// round 14
// speedup vs baseline: 2.7491x; 1.1717x over previous
#include <cuda_runtime.h>
#include <cuda_fp16.h>
#include <math.h>
#include <stdint.h>

#define DMODEL 2048
#define NHEADS 16
#define DHEAD  128
#define SEQ    2048
#define BATCH  2
#define BHN    (BATCH*NHEADS)   // 32
#define MROWS  (BATCH*SEQ)      // 4096

// log2(e) / sqrt(128)
#define QSCALE (1.4426950408889634f * 0.08838834764831845f)

// ---- fp16 single-pass GEMM: CTA 128x128, KBLK 64, 4 warps (64x64) ----
#define PADK 72                       // fp16 per smem row (144 B)
#define TILE_BYTES (128 * PADK * 2)   // 18432
#define OFF_AH 0
#define OFF_BH (TILE_BYTES)
#define GEMM_SMEM (2*TILE_BYTES)      // 36864 B (2 CTAs/SM)

// ---- fp16 flash: 128 q x 128 kv, 3 tiles (Qh,Kh,Vh), stride 272 B ----
#define FS   272
#define FT   (128 * FS)
#define FQH  0
#define FKH  (FT)
#define FVH  (2*FT)
#define FLASH_SMEM (3*FT)          // 104448 B

// ---------------- scratch (device globals; allocation-free) ----------------
__device__ float  g_q[(size_t)BHN * SEQ * DHEAD];
__device__ float  g_k[(size_t)BHN * SEQ * DHEAD];
__device__ float2 g_rope[SEQ * 64];

__device__ __half g_wq[(size_t)DMODEL * DMODEL];
__device__ __half g_wk[(size_t)DMODEL * DMODEL];
__device__ __half g_wv[(size_t)DMODEL * DMODEL];
__device__ __half g_wo[(size_t)DMODEL * DMODEL];

__device__ __half g_qh[(size_t)BHN * SEQ * DHEAD];
__device__ __half g_kh[(size_t)BHN * SEQ * DHEAD];
__device__ __half g_vh[(size_t)BHN * SEQ * DHEAD];
__device__ __half g_zh[(size_t)MROWS * DMODEL];     // flash out (fp16, row-major)

// ---------------- helpers ----------------
__device__ __forceinline__ void ldsm4(uint32_t* r, uint32_t addr) {
    asm volatile("ldmatrix.sync.aligned.m8n8.x4.shared.b16 {%0,%1,%2,%3}, [%4];"
                 : "=r"(r[0]), "=r"(r[1]), "=r"(r[2]), "=r"(r[3]) : "r"(addr));
}
__device__ __forceinline__ void ldsm4t(uint32_t* r, uint32_t addr) {
    asm volatile("ldmatrix.sync.aligned.m8n8.x4.trans.shared.b16 {%0,%1,%2,%3}, [%4];"
                 : "=r"(r[0]), "=r"(r[1]), "=r"(r[2]), "=r"(r[3]) : "r"(addr));
}
__device__ __forceinline__ void mma16816h(float* d, const uint32_t* a,
                                          uint32_t b0, uint32_t b1) {
    asm volatile(
        "mma.sync.aligned.m16n8k16.row.col.f32.f16.f16.f32 "
        "{%0,%1,%2,%3}, {%4,%5,%6,%7}, {%8,%9}, {%0,%1,%2,%3};"
        : "+f"(d[0]), "+f"(d[1]), "+f"(d[2]), "+f"(d[3])
        : "r"(a[0]), "r"(a[1]), "r"(a[2]), "r"(a[3]), "r"(b0), "r"(b1));
}
__device__ __forceinline__ float ex2(float x) {
    float y; asm("ex2.approx.f32 %0, %1;" : "=f"(y) : "f"(x)); return y;
}
__device__ __forceinline__ uint32_t packhf(float lo, float hi) {
    uint32_t r; asm("cvt.rn.f16x2.f32 %0, %1, %2;" : "=r"(r) : "f"(hi), "f"(lo));
    return r;
}
__device__ __forceinline__ void cpasync16(uint32_t s, const void* g) {
    asm volatile("cp.async.cg.shared.global [%0], [%1], 16;" :: "r"(s), "l"(g));
}

// ---------------------------------------------------------------------------
// RoPE table (fp32 angle, fp64 sin/cos)
// ---------------------------------------------------------------------------
__global__ void rope_table_kernel() {
    int p = blockIdx.x;
    int i = threadIdx.x;  // 0..63
    float freq = (float)pow(10000.0, (double)i / 64.0);
    float ang  = (float)p / freq;
    double s, c;
    sincos((double)ang, &s, &c);
    g_rope[p * 64 + i] = make_float2((float)s, (float)c);
}

// ---------------------------------------------------------------------------
// Rope + fp16 round: q (QSCALE folded) and k, both single fp16.
// ---------------------------------------------------------------------------
__global__ void rope_split_kernel() {
    int gid = blockIdx.x * 256 + threadIdx.x;
    int i    = gid & 63;
    int rest = gid >> 6;
    int p    = rest & 2047;
    int bh   = rest >> 11;
    float2 sc = g_rope[p * 64 + i];
    size_t base = ((size_t)bh * SEQ + p) * DHEAD;

    float x0 = g_q[base + i], x1 = g_q[base + 64 + i];
    float q0 = (x0 * sc.y - x1 * sc.x) * QSCALE;
    float q1 = (x1 * sc.y + x0 * sc.x) * QSCALE;
    float y0 = g_k[base + i], y1 = g_k[base + 64 + i];
    float k0 = y0 * sc.y - y1 * sc.x;
    float k1 = y1 * sc.y + y0 * sc.x;

    g_qh[base + i]      = __float2half_rn(q0);
    g_qh[base + 64 + i] = __float2half_rn(q1);
    g_kh[base + i]      = __float2half_rn(k0);
    g_kh[base + 64 + i] = __float2half_rn(k1);
}

// ---------------------------------------------------------------------------
// Transpose + fp16 round: src [H][R][C] fp32 -> dst[h*C + c][r] fp16.
// ---------------------------------------------------------------------------
__global__ void transpose_half_kernel(const float* __restrict__ src,
                                      __half* __restrict__ dst,
                                      int R, int C) {
    __shared__ float t[32][33];
    int h  = blockIdx.z;
    int r0 = blockIdx.y << 5, c0 = blockIdx.x << 5;
    int tx = threadIdx.x, ty = threadIdx.y;  // 32 x 8
    const float* s = src + (size_t)h * R * C;
#pragma unroll
    for (int j = 0; j < 4; ++j)
        t[ty + 8 * j][tx] = s[(size_t)(r0 + ty + 8 * j) * C + c0 + tx];
    __syncthreads();
#pragma unroll
    for (int j = 0; j < 4; ++j) {
        int c = c0 + ty + 8 * j;
        dst[(size_t)(h * C + c) * R + r0 + tx] = __float2half_rn(t[tx][ty + 8 * j]);
    }
}

// ===========================================================================
// Shared GEMM machinery (single-pass fp16)
// ===========================================================================
#define GEMM_PROLOGUE()                                                        \
    extern __shared__ char sm[];                                               \
    const uint32_t sb = (uint32_t)__cvta_generic_to_shared(sm);                \
    const int tid  = threadIdx.x;                                              \
    const int wid  = tid >> 5;                                                 \
    const int lane = tid & 31;                                                 \
    const int row0 = blockIdx.y * 128;                                         \
    const int n0   = blockIdx.x * 128;                                         \
    const int m_w  = (wid & 1) * 64;                                           \
    const int n_w  = (wid >> 1) * 64;                                          \
    const uint32_t aOff = (uint32_t)(m_w + (lane & 15)) * 144 + ((lane >> 4) << 4); \
    const uint32_t bOff = (uint32_t)(n_w + ((lane >> 4) << 3) + (lane & 7)) * 144 + \
                          (uint32_t)((lane & 8) << 1);                         \
    const uint32_t aHi = sb + OFF_AH + aOff;                                   \
    const uint32_t bHi = sb + OFF_BH + bOff;                                   \
    float acc[4][8][4];                                                        \
    _Pragma("unroll")                                                          \
    for (int i = 0; i < 4; ++i)                                                \
        _Pragma("unroll")                                                      \
        for (int j = 0; j < 8; ++j)                                            \
            _Pragma("unroll")                                                  \
            for (int r = 0; r < 4; ++r) acc[i][j][r] = 0.0f;                   \
    const int lr  = tid >> 3;                                                  \
    const int lc8 = (tid & 7) * 8;

#define GEMM_COMPUTE()                                                         \
    _Pragma("unroll")                                                          \
    for (int kk = 0; kk < 4; ++kk) {                                           \
        uint32_t Af[4][4], Bf[4][4];                                           \
        _Pragma("unroll")                                                      \
        for (int mi = 0; mi < 4; ++mi)                                         \
            ldsm4(Af[mi], aHi + mi * (16 * 144) + kk * 32);                    \
        _Pragma("unroll")                                                      \
        for (int ni = 0; ni < 4; ++ni)                                         \
            ldsm4(Bf[ni], bHi + ni * (16 * 144) + kk * 32);                    \
        _Pragma("unroll")                                                      \
        for (int mi = 0; mi < 4; ++mi)                                         \
            _Pragma("unroll")                                                  \
            for (int j = 0; j < 8; ++j)                                        \
                mma16816h(acc[mi][j], Af[mi], Bf[j >> 1][(j & 1) * 2],         \
                          Bf[j >> 1][(j & 1) * 2 + 1]);                        \
    }

// ---------------------------------------------------------------------------
// Fused QKV projection (single-pass): grid.z selects {Q, K, V}.
// A fp32, rounded to fp16 in the load path. Q/K fp32 out; V fp16 out.
// ---------------------------------------------------------------------------
__global__ __launch_bounds__(128, 2) void gemm_qkv(
    const float* __restrict__ A0, const float* __restrict__ A1,
    const float* __restrict__ A2,
    const float* __restrict__ bQ, const float* __restrict__ bK,
    const float* __restrict__ bV)
{
    const int z = blockIdx.z;
    const float* A    = (z == 0) ? A0 : (z == 1) ? A1 : A2;
    const __half* Bh  = (z == 0) ? g_wq : (z == 1) ? g_wk : g_wv;
    const float* bias = (z == 0) ? bQ : (z == 1) ? bK : bV;

    GEMM_PROLOGUE();

    for (int it = 0; it < DMODEL / 64; ++it) {
        const int k0 = it * 64;
        __syncthreads();
#pragma unroll
        for (int i = 0; i < 8; ++i) {
            int r = lr + i * 16;
            size_t ga = (size_t)(row0 + r) * DMODEL + k0 + lc8;
            float4 f0 = *(const float4*)(A + ga);
            float4 f1 = *(const float4*)(A + ga + 4);
            uint32_t hw[4];
            hw[0] = packhf(f0.x, f0.y);
            hw[1] = packhf(f0.z, f0.w);
            hw[2] = packhf(f1.x, f1.y);
            hw[3] = packhf(f1.z, f1.w);
            uint32_t so = (uint32_t)(r * 144 + lc8 * 2);
            *(uint4*)(sm + OFF_AH + so) = make_uint4(hw[0], hw[1], hw[2], hw[3]);
            size_t gb = (size_t)(n0 + r) * DMODEL + k0 + lc8;
            *(float4*)(sm + OFF_BH + so) = *(const float4*)(Bh + gb);
        }
        __syncthreads();
        GEMM_COMPUTE();
    }

    float* out = (z == 0) ? g_q : g_k;
    const int g = lane >> 2, t4 = lane & 3;
#pragma unroll
    for (int mi = 0; mi < 4; ++mi) {
        int m = row0 + m_w + mi * 16 + g;
#pragma unroll
        for (int j = 0; j < 8; ++j) {
            int col = n0 + n_w + j * 8 + t4 * 2;
            float b0 = bias[col], b1 = bias[col + 1];
            float2 v0 = make_float2(acc[mi][j][0] + b0, acc[mi][j][1] + b1);
            float2 v1 = make_float2(acc[mi][j][2] + b0, acc[mi][j][3] + b1);
            int h = col >> 7, e = col & 127;
            int b  = m >> 11, p = m & 2047;
            size_t base = (((size_t)(b * NHEADS + h) * SEQ) << 7) + e;
            size_t i0 = base + ((size_t)p << 7);
            size_t i1 = base + ((size_t)(p + 8) << 7);
            if (z != 2) {
                *(float2*)(out + i0) = v0;
                *(float2*)(out + i1) = v1;
            } else {
                *(uint32_t*)(g_vh + i0) = packhf(v0.x, v0.y);
                *(uint32_t*)(g_vh + i1) = packhf(v1.x, v1.y);
            }
        }
    }
}

// ---------------------------------------------------------------------------
// O projection: single-pass, A already fp16 (g_zh), fp32 row-major out.
// ---------------------------------------------------------------------------
__global__ __launch_bounds__(128, 2) void gemm_o(
    const float* __restrict__ bias,
    float* __restrict__ out)
{
    GEMM_PROLOGUE();

    for (int it = 0; it < DMODEL / 64; ++it) {
        const int k0 = it * 64;
        __syncthreads();
#pragma unroll
        for (int i = 0; i < 8; ++i) {
            int r = lr + i * 16;
            uint32_t so = (uint32_t)(r * 144 + lc8 * 2);
            size_t ga = (size_t)(row0 + r) * DMODEL + k0 + lc8;
            *(uint4*)(sm + OFF_AH + so) = *(const uint4*)(g_zh + ga);
            size_t gb = (size_t)(n0 + r) * DMODEL + k0 + lc8;
            *(float4*)(sm + OFF_BH + so) = *(const float4*)(g_wo + gb);
        }
        __syncthreads();
        GEMM_COMPUTE();
    }

    const int g = lane >> 2, t4 = lane & 3;
#pragma unroll
    for (int mi = 0; mi < 4; ++mi) {
        int m = row0 + m_w + mi * 16 + g;
#pragma unroll
        for (int j = 0; j < 8; ++j) {
            int col = n0 + n_w + j * 8 + t4 * 2;
            float b0 = bias[col], b1 = bias[col + 1];
            *(float2*)(out + (size_t)m * DMODEL + col) =
                make_float2(acc[mi][j][0] + b0, acc[mi][j][1] + b1);
            *(float2*)(out + (size_t)(m + 8) * DMODEL + col) =
                make_float2(acc[mi][j][2] + b0, acc[mi][j][3] + b1);
        }
    }
}

// ---------------------------------------------------------------------------
// fp16 causal flash attention. CTA = 128 q x 128 kv, 8 warps x 16 rows.
// S = Qh*Kh (both rounded);  O += Ph*Vh. V via cp.async overlapped with S.
// Epilogue writes z fp16 into g_zh [b*p][h*e] (O-proj A input — identical
// rounding to what the single-pass O GEMM would apply anyway).
// ---------------------------------------------------------------------------
__global__ __launch_bounds__(256, 1) void flash_hmma() {
    extern __shared__ char sm[];
    const uint32_t sb = (uint32_t)__cvta_generic_to_shared(sm);

    const int tid  = threadIdx.x;
    const int wid  = tid >> 5;
    const int lane = tid & 31;
    const int bh   = blockIdx.y;
    const int qt   = gridDim.x - 1 - blockIdx.x;   // heavy tiles first
    const int q0   = qt * 128;

    const __half* qh = g_qh + (size_t)bh * SEQ * DHEAD;
    const __half* kh = g_kh + (size_t)bh * SEQ * DHEAD;
    const __half* vh = g_vh + (size_t)bh * SEQ * DHEAD;

#pragma unroll
    for (int i = 0; i < 8; ++i) {
        int f = tid + i * 256;
        int r = f >> 4, c8 = (f & 15) * 8;
        uint32_t off = (uint32_t)(r * FS + c8 * 2);
        *(uint4*)(sm + FQH + off) = *(const uint4*)(qh + (size_t)(q0 + r) * DHEAD + c8);
    }

    const uint32_t aOff = (uint32_t)(wid * 16 + (lane & 15)) * FS + ((lane >> 4) << 4);
    const uint32_t aQh = sb + FQH + aOff;
    const uint32_t bOff = (uint32_t)(((lane >> 4) << 3) + (lane & 7)) * FS +
                          (uint32_t)((lane & 8) << 1);
    const uint32_t bKh = sb + FKH + bOff;
    const uint32_t vOff = (uint32_t)(lane & 15) * FS + ((lane >> 4) << 4);
    const uint32_t bVh = sb + FVH + vOff;

    float o[16][4];
#pragma unroll
    for (int j = 0; j < 16; ++j)
#pragma unroll
        for (int r = 0; r < 4; ++r) o[j][r] = 0.0f;
    float m1 = -1e30f, m2 = -1e30f, l1 = 0.0f, l2 = 0.0f;

    for (int t = 0; t <= qt; ++t) {
        const int k0 = t * 128;
        __syncthreads();
#pragma unroll
        for (int i = 0; i < 8; ++i) {
            int f = tid + i * 256;
            int r = f >> 4, c8 = (f & 15) * 8;
            uint32_t off = (uint32_t)(r * FS + c8 * 2);
            size_t g = (size_t)(k0 + r) * DHEAD + c8;
            *(uint4*)(sm + FKH + off) = *(const uint4*)(kh + g);
            cpasync16(sb + FVH + off, vh + g);
        }
        asm volatile("cp.async.commit_group;" ::: "memory");
        __syncthreads();   // K visible

        float s[16][4];
#pragma unroll
        for (int j = 0; j < 16; ++j)
#pragma unroll
            for (int r = 0; r < 4; ++r) s[j][r] = 0.0f;

#pragma unroll
        for (int kk = 0; kk < 8; ++kk) {
            uint32_t qa[4], kb[4];
            ldsm4(qa, aQh + kk * 32);
#pragma unroll
            for (int nn = 0; nn < 8; ++nn) {
                ldsm4(kb, bKh + nn * (16 * FS) + kk * 32);
                mma16816h(s[2*nn],   qa, kb[0], kb[1]);
                mma16816h(s[2*nn+1], qa, kb[2], kb[3]);
            }
        }

        const int r1 = q0 + wid * 16 + (lane >> 2);
        const int r2 = r1 + 8;
        if (t == qt) {
            const int c0 = k0 + (lane & 3) * 2;
#pragma unroll
            for (int j = 0; j < 16; ++j) {
                int col = c0 + j * 8;
                if (col     > r1) s[j][0] = -1e30f;
                if (col + 1 > r1) s[j][1] = -1e30f;
                if (col     > r2) s[j][2] = -1e30f;
                if (col + 1 > r2) s[j][3] = -1e30f;
            }
        }

        float mx1 = -1e30f, mx2 = -1e30f;
#pragma unroll
        for (int j = 0; j < 16; ++j) {
            mx1 = fmaxf(mx1, fmaxf(s[j][0], s[j][1]));
            mx2 = fmaxf(mx2, fmaxf(s[j][2], s[j][3]));
        }
        mx1 = fmaxf(mx1, __shfl_xor_sync(0xffffffffu, mx1, 1));
        mx1 = fmaxf(mx1, __shfl_xor_sync(0xffffffffu, mx1, 2));
        mx2 = fmaxf(mx2, __shfl_xor_sync(0xffffffffu, mx2, 1));
        mx2 = fmaxf(mx2, __shfl_xor_sync(0xffffffffu, mx2, 2));
        float mn1 = fmaxf(m1, mx1), mn2 = fmaxf(m2, mx2);
        float sc1 = ex2(m1 - mn1), sc2 = ex2(m2 - mn2);
        float rs1 = 0.0f, rs2 = 0.0f;
#pragma unroll
        for (int j = 0; j < 16; ++j) {
            s[j][0] = ex2(s[j][0] - mn1);
            s[j][1] = ex2(s[j][1] - mn1);
            s[j][2] = ex2(s[j][2] - mn2);
            s[j][3] = ex2(s[j][3] - mn2);
            rs1 += s[j][0] + s[j][1];
            rs2 += s[j][2] + s[j][3];
        }
        rs1 += __shfl_xor_sync(0xffffffffu, rs1, 1);
        rs1 += __shfl_xor_sync(0xffffffffu, rs1, 2);
        rs2 += __shfl_xor_sync(0xffffffffu, rs2, 1);
        rs2 += __shfl_xor_sync(0xffffffffu, rs2, 2);
        l1 = l1 * sc1 + rs1;  m1 = mn1;
        l2 = l2 * sc2 + rs2;  m2 = mn2;
#pragma unroll
        for (int j = 0; j < 16; ++j) {
            o[j][0] *= sc1; o[j][1] *= sc1;
            o[j][2] *= sc2; o[j][3] *= sc2;
        }

        asm volatile("cp.async.wait_group 0;" ::: "memory");
        __syncthreads();   // V visible

#pragma unroll
        for (int kk = 0; kk < 8; ++kk) {
            uint32_t pha[4], vb[4];
            pha[0] = packhf(s[2*kk][0],   s[2*kk][1]);
            pha[1] = packhf(s[2*kk][2],   s[2*kk][3]);
            pha[2] = packhf(s[2*kk+1][0], s[2*kk+1][1]);
            pha[3] = packhf(s[2*kk+1][2], s[2*kk+1][3]);
#pragma unroll
            for (int nn = 0; nn < 8; ++nn) {
                ldsm4t(vb, bVh + kk * (16 * FS) + nn * 32);
                mma16816h(o[2*nn],   pha, vb[0], vb[1]);
                mma16816h(o[2*nn+1], pha, vb[2], vb[3]);
            }
        }
    }

    // Epilogue: normalize, round to fp16, write z into g_zh [b*p][h*e].
    const int b = bh >> 4, h = bh & 15;
    const int r1 = q0 + wid * 16 + (lane >> 2);
    const float inv1 = 1.0f / l1, inv2 = 1.0f / l2;
    size_t base1 = (size_t)(b * SEQ + r1) * DMODEL + h * DHEAD + (lane & 3) * 2;
    size_t base2 = base1 + (size_t)8 * DMODEL;
#pragma unroll
    for (int j = 0; j < 16; ++j) {
        *(uint32_t*)(g_zh + base1 + j * 8) = packhf(o[j][0] * inv1, o[j][1] * inv1);
        *(uint32_t*)(g_zh + base2 + j * 8) = packhf(o[j][2] * inv2, o[j][3] * inv2);
    }
}

// ---------------------------------------------------------------------------
extern "C" void kernel_launch(void* const* d_in, const int* in_sizes, int n_in,
                              void* d_out, int out_size) {
    (void)in_sizes; (void)n_in; (void)out_size;
    const float* qin = (const float*)d_in[0];
    const float* kin = (const float*)d_in[1];
    const float* vin = (const float*)d_in[2];
    const float* WQ  = (const float*)d_in[3];
    const float* WK  = (const float*)d_in[4];
    const float* WV  = (const float*)d_in[5];
    const float* WO  = (const float*)d_in[6];
    const float* bQ  = (const float*)d_in[7];
    const float* bK  = (const float*)d_in[8];
    const float* bV  = (const float*)d_in[9];
    const float* bO  = (const float*)d_in[10];
    float* out = (float*)d_out;

    __half *wq, *wk, *wv, *wo;
    cudaGetSymbolAddress((void**)&wq, g_wq);
    cudaGetSymbolAddress((void**)&wk, g_wk);
    cudaGetSymbolAddress((void**)&wv, g_wv);
    cudaGetSymbolAddress((void**)&wo, g_wo);

    cudaFuncSetAttribute((const void*)gemm_qkv,
                         cudaFuncAttributeMaxDynamicSharedMemorySize, GEMM_SMEM);
    cudaFuncSetAttribute((const void*)gemm_o,
                         cudaFuncAttributeMaxDynamicSharedMemorySize, GEMM_SMEM);
    cudaFuncSetAttribute((const void*)flash_hmma,
                         cudaFuncAttributeMaxDynamicSharedMemorySize, FLASH_SMEM);

    dim3 tb(32, 8);

    transpose_half_kernel<<<dim3(4, 64, 16), tb>>>(WQ, wq, DMODEL, DHEAD);   // 1
    transpose_half_kernel<<<dim3(4, 64, 16), tb>>>(WK, wk, DMODEL, DHEAD);   // 2
    transpose_half_kernel<<<dim3(4, 64, 16), tb>>>(WV, wv, DMODEL, DHEAD);   // 3
    transpose_half_kernel<<<dim3(64, 64, 1), tb>>>(WO, wo, DMODEL, DMODEL);  // 4
    rope_table_kernel<<<SEQ, 64>>>();                                        // 5
    gemm_qkv<<<dim3(16, 32, 3), 128, GEMM_SMEM>>>(qin, kin, vin, bQ, bK, bV);// 6 <- ncu
    rope_split_kernel<<<(BHN * SEQ * 64) / 256, 256>>>();                    // 7
    flash_hmma<<<dim3(SEQ / 128, BHN), 256, FLASH_SMEM>>>();                 // 8 -> g_zh
    gemm_o<<<dim3(16, 32), 128, GEMM_SMEM>>>(bO, out);                       // 9
}